// round 10
// baseline (speedup 1.0000x reference)
#include <cuda_runtime.h>
#include <cuda_bf16.h>
#include <math.h>
#include <stdint.h>

#define NN 10000
#define EE 160000
#define HH 256

// ---------------------------------------------------------------------------
// Scratch (no runtime allocation allowed)
// ---------------------------------------------------------------------------
__device__ float g_h[NN * HH];
__device__ float g_p[NN * HH];
__device__ float g_q[NN * HH];
__device__ float g_agg[NN * HH];
__device__ float g_t[NN * HH];
__device__ float g_u[NN * HH];
__device__ float g_wpa[256 * 256];
__device__ float g_wqb[256 * 256];
__device__ float g_wr2[32 * 256];
__device__ float g_cz[256];
// act1 (layer-1 activations) hi/lo bf16, [E, 256]
__device__ __nv_bfloat16 g_a1h[(size_t)EE * HH];
__device__ __nv_bfloat16 g_a1l[(size_t)EE * HH];
// Transposed weights W^T[N=256, Kc=32] tiles (24): 0..7=W2, 8..15=W3, 16..23=W4
__device__ __align__(16) __nv_bfloat16 g_wt[24 * 16384];

__device__ __forceinline__ float gelu_f(float x) {
    float x3 = x * x * x;
    return 0.5f * x * (1.0f + tanhf(0.7978845608028654f * (x + 0.044715f * x3)));
}
__device__ __forceinline__ float lrelu_f(float x) { return x > 0.0f ? x : 0.01f * x; }

// ---------------------------------------------------------------------------
// PTX helpers (sm_80/sm_90 base ISA: valid at .target sm_100)
// ---------------------------------------------------------------------------
__device__ __forceinline__ uint32_t smem_u32(const void* p) {
    uint32_t a;
    asm("{ .reg .u64 t; cvta.to.shared.u64 t, %1; cvt.u32.u64 %0, t; }" : "=r"(a) : "l"(p));
    return a;
}
__device__ __forceinline__ void cp_async16(uint32_t smem_addr, const void* gptr) {
    asm volatile("cp.async.cg.shared.global [%0], [%1], 16;\n" :: "r"(smem_addr), "l"(gptr));
}
#define CP_COMMIT() asm volatile("cp.async.commit_group;\n" ::: "memory")
#define CP_WAIT0()  asm volatile("cp.async.wait_group 0;\n" ::: "memory")
#define CP_WAIT1()  asm volatile("cp.async.wait_group 1;\n" ::: "memory")

__device__ __forceinline__ void bulk_reduce_add_f32(void* gdst, uint32_t ssrc, uint32_t bytes) {
    asm volatile("cp.reduce.async.bulk.global.shared::cta.bulk_group.add.f32 [%0], [%1], %2;\n"
                 :: "l"(gdst), "r"(ssrc), "r"(bytes) : "memory");
}
#define BULK_COMMIT() asm volatile("cp.async.bulk.commit_group;" ::: "memory")
#define BULK_WAIT0()  asm volatile("cp.async.bulk.wait_group 0;" ::: "memory")
#define FENCE_ASYNC() asm volatile("fence.proxy.async.shared::cta;" ::: "memory")

__device__ __forceinline__ void ldsm4(uint32_t* f, uint32_t a) {
    asm volatile("ldmatrix.sync.aligned.m8n8.x4.shared.b16 {%0,%1,%2,%3}, [%4];\n"
                 : "=r"(f[0]), "=r"(f[1]), "=r"(f[2]), "=r"(f[3]) : "r"(a));
}
__device__ __forceinline__ void mma16816(float* d, const uint32_t* a, uint32_t b0, uint32_t b1) {
    asm volatile(
        "mma.sync.aligned.m16n8k16.row.col.f32.bf16.bf16.f32 "
        "{%0,%1,%2,%3}, {%4,%5,%6,%7}, {%8,%9}, {%0,%1,%2,%3};\n"
        : "+f"(d[0]), "+f"(d[1]), "+f"(d[2]), "+f"(d[3])
        : "r"(a[0]), "r"(a[1]), "r"(a[2]), "r"(a[3]), "r"(b0), "r"(b1));
}

// ---------------------------------------------------------------------------
// Mega kernel 0: z=0 -> h = gelu(xcat@w_emb+b)   (xcat gathered on the fly)
//                z=1 -> wpa = w_n2m @ mw1a ; z=2 -> wqb = w_n2m @ mw1b
//                z=3 -> flat prep: wt tiles (W2/3/4), wr2 = w_r2m@mw1c, cz
// ---------------------------------------------------------------------------
__global__ __launch_bounds__(256, 2) void k0_mega(
    const int* __restrict__ atom_types, const float* __restrict__ x_extra,
    const float* __restrict__ emb_table,
    const float* __restrict__ w_emb, const float* __restrict__ b_emb,
    const float* __restrict__ w_n2m, const float* __restrict__ b_n2m,
    const float* __restrict__ w_r2m, const float* __restrict__ b_r2m,
    const float* __restrict__ mw1, const float* __restrict__ mb1,
    const float* __restrict__ mw2, const float* __restrict__ mw3,
    const float* __restrict__ mw4,
    float* __restrict__ h, float* __restrict__ wpa, float* __restrict__ wqb,
    float* __restrict__ wr2, float* __restrict__ cz,
    __nv_bfloat16* __restrict__ wt, int N) {
    int z = blockIdx.z;
    if (z == 3) {
        // flat prep work: [0,196608) wt tiles; [196608,204800) wr2; [204800,205056) cz
        int bid = blockIdx.x * 2 + blockIdx.y;       // gridDim.y == 2
        int flat = bid * 256 + (int)threadIdx.x;     // 0..80383
        for (int item = flat; item < 205056; item += 80384) {
            if (item < 196608) {
                int kg = item >> 8, n = item & 255;
                const float* w; int kl, t;
                if (kg < 256)      { w = mw2; kl = kg;       t = kl >> 5; }
                else if (kg < 512) { w = mw3; kl = kg - 256; t = 8 + (kl >> 5); }
                else               { w = mw4; kl = kg - 512; t = 16 + (kl >> 5); }
                int kk = kl & 31;
                float v = w[(long)kl * 256 + n];
                __nv_bfloat16 hh = __float2bfloat16(v);
                __nv_bfloat16 ll = __float2bfloat16(v - __bfloat162float(hh));
                size_t base = (size_t)t * 16384 + n * 32 + kk;
                wt[base] = hh;
                wt[base + 8192] = ll;
            } else if (item < 204800) {
                int it = item - 196608;
                int kl = it >> 8, n = it & 255;
                float s = 0.0f;
                for (int j = 0; j < 256; j++)
                    s += w_r2m[kl * 256 + j] * mw1[(long)(512 + j) * 256 + n];
                wr2[kl * 256 + n] = s;
            } else {
                int n = item - 204800;
                float s = mb1[n];
                for (int k = 0; k < 256; k++) {
                    s += b_n2m[k] * (mw1[(long)k * 256 + n] + mw1[(long)(256 + k) * 256 + n]);
                    s += b_r2m[k] * mw1[(long)(512 + k) * 256 + n];
                }
                cz[n] = s;
            }
        }
        return;
    }

    // ---- GEMM path ----
    __shared__ float As[64 * 33];
    __shared__ float Bs[32 * 132];
    const float* A = nullptr;
    const float* W;
    const float* bias = nullptr;
    float* C;
    int K, rows, act = 0;
    bool gather = false;
    if (z == 0) { gather = true; K = 48; W = w_emb; bias = b_emb; C = h; rows = N; act = 1; }
    else if (z == 1) { A = w_n2m; K = 256; W = mw1; C = wpa; rows = 256; }
    else { A = w_n2m; K = 256; W = mw1 + 65536; C = wqb; rows = 256; }

    int tid = threadIdx.x, tx = tid & 15, ty = tid >> 4;
    int row0 = blockIdx.x * 64;
    int col0 = blockIdx.y * 128;
    if (row0 >= rows) return;

    float acc[4][8];
#pragma unroll
    for (int i = 0; i < 4; i++)
#pragma unroll
        for (int j = 0; j < 8; j++) acc[i][j] = 0.0f;
    for (int k0 = 0; k0 < K; k0 += 32) {
#pragma unroll
        for (int i = 0; i < 8; i++) {
            int idx = tid + i * 256, r = idx >> 5, c = idx & 31;
            int gr = row0 + r, gk = k0 + c;
            float v = 0.0f;
            if (gr < rows && gk < K) {
                if (gather)
                    v = (gk < 32) ? emb_table[atom_types[gr] * 32 + gk]
                                  : x_extra[gr * 16 + gk - 32];
                else
                    v = A[(long)gr * K + gk];
            }
            As[r * 33 + c] = v;
        }
#pragma unroll
        for (int i = 0; i < 16; i++) {
            int idx = tid + i * 256, r = idx >> 7, c = idx & 127;
            int gk = k0 + r;
            Bs[r * 132 + c] = (gk < K) ? W[(long)gk * 256 + col0 + c] : 0.0f;
        }
        __syncthreads();
#pragma unroll
        for (int kk = 0; kk < 32; kk++) {
            float a[4];
#pragma unroll
            for (int i = 0; i < 4; i++) a[i] = As[(ty * 4 + i) * 33 + kk];
#pragma unroll
            for (int j = 0; j < 8; j++) {
                float b = Bs[kk * 132 + tx + 16 * j];
#pragma unroll
                for (int i = 0; i < 4; i++) acc[i][j] = fmaf(a[i], b, acc[i][j]);
            }
        }
        __syncthreads();
    }
#pragma unroll
    for (int i = 0; i < 4; i++) {
        int r = row0 + ty * 4 + i;
        if (r < rows) {
#pragma unroll
            for (int j = 0; j < 8; j++) {
                int col = col0 + tx + 16 * j;
                float v = acc[i][j];
                if (bias) v += bias[col];
                if (act == 1) v = gelu_f(v);
                C[(long)r * 256 + col] = v;
            }
        }
    }
}

// ---------------------------------------------------------------------------
// Node-side GEMM, BM=64, BN=128 (gridDim.y=2); blockIdx.z==1 selects (W2,C2);
// zbuf (if set, z==0) is zeroed over the same tile footprint.
// ---------------------------------------------------------------------------
__global__ __launch_bounds__(256, 2) void gemm_bn128(
    const float* __restrict__ A, int K, const float* __restrict__ W,
    const float* __restrict__ bias, const float* __restrict__ res,
    float* __restrict__ C, int rows, int act,
    const float* __restrict__ W2, float* __restrict__ C2,
    float* __restrict__ zbuf) {
    __shared__ float As[64 * 33];
    __shared__ float Bs[32 * 132];
    if (blockIdx.z == 1) { W = W2; C = C2; }
    int tid = threadIdx.x, tx = tid & 15, ty = tid >> 4;
    int row0 = blockIdx.x * 64;
    int col0 = blockIdx.y * 128;
    if (row0 >= rows) return;
    float acc[4][8];
#pragma unroll
    for (int i = 0; i < 4; i++)
#pragma unroll
        for (int j = 0; j < 8; j++) acc[i][j] = 0.0f;
    for (int k0 = 0; k0 < K; k0 += 32) {
#pragma unroll
        for (int i = 0; i < 8; i++) {
            int idx = tid + i * 256, r = idx >> 5, c = idx & 31;
            int gr = row0 + r, gk = k0 + c;
            As[r * 33 + c] = (gr < rows && gk < K) ? A[(long)gr * K + gk] : 0.0f;
        }
#pragma unroll
        for (int i = 0; i < 16; i++) {
            int idx = tid + i * 256, r = idx >> 7, c = idx & 127;
            int gk = k0 + r;
            Bs[r * 132 + c] = (gk < K) ? W[(long)gk * 256 + col0 + c] : 0.0f;
        }
        __syncthreads();
#pragma unroll
        for (int kk = 0; kk < 32; kk++) {
            float a[4];
#pragma unroll
            for (int i = 0; i < 4; i++) a[i] = As[(ty * 4 + i) * 33 + kk];
#pragma unroll
            for (int j = 0; j < 8; j++) {
                float b = Bs[kk * 132 + tx + 16 * j];
#pragma unroll
                for (int i = 0; i < 4; i++) acc[i][j] = fmaf(a[i], b, acc[i][j]);
            }
        }
        __syncthreads();
    }
#pragma unroll
    for (int i = 0; i < 4; i++) {
        int r = row0 + ty * 4 + i;
        if (r < rows) {
#pragma unroll
            for (int j = 0; j < 8; j++) {
                int col = col0 + tx + 16 * j;
                float v = acc[i][j];
                if (bias) v += bias[col];
                if (act == 1) v = gelu_f(v);
                if (res) v += res[(long)r * 256 + col];
                C[(long)r * 256 + col] = v;
                if (zbuf && blockIdx.z == 0) zbuf[(long)r * 256 + col] = 0.0f;
            }
        }
    }
}

// ---------------------------------------------------------------------------
// edge combine: act1 = lrelu( rbf@Wr2 + p[src] + q[dst] + cz ) -> bf16 hi/lo
// ---------------------------------------------------------------------------
__global__ __launch_bounds__(256, 2) void edge_combine(
    const float* __restrict__ dists, const float* __restrict__ freq,
    const float* __restrict__ wr2, const float* __restrict__ p,
    const float* __restrict__ q, const float* __restrict__ cz,
    const int* __restrict__ edge_index,
    __nv_bfloat16* __restrict__ a1h, __nv_bfloat16* __restrict__ a1l, int E) {
    __shared__ float Rs[64 * 33];
    __shared__ float Bs[32 * 256];
    __shared__ float s_freq[32];
    __shared__ float s_cz[256];
    __shared__ int s_src[64], s_dst[64];
    int tid = threadIdx.x, tx = tid & 15, ty = tid >> 4;
    int e0 = blockIdx.x * 64;
    if (tid < 32) s_freq[tid] = freq[tid];
    s_cz[tid] = cz[tid];
    if (tid < 64) {
        int e = e0 + tid;
        s_src[tid] = (e < E) ? edge_index[e] : 0;
        s_dst[tid] = (e < E) ? edge_index[E + e] : 0;
    }
#pragma unroll
    for (int i = 0; i < 32; i++) Bs[i * 256 + tid] = wr2[i * 256 + tid];
    __syncthreads();
#pragma unroll
    for (int i = 0; i < 8; i++) {
        int idx = tid + i * 256, el = idx >> 5, r = idx & 31;
        int e = e0 + el;
        float d = (e < E) ? dists[e] * 0.2f : 1.0f;
        float d2 = d * d, d5 = d2 * d2 * d;
        float env = 1.0f / d + d5 * (-28.0f + d * (48.0f + d * (-21.0f)));
        Rs[el * 33 + r] = env * sinf(s_freq[r] * d);
    }
    __syncthreads();
    float acc[4][16];
#pragma unroll
    for (int i = 0; i < 4; i++)
#pragma unroll
        for (int j = 0; j < 16; j++) acc[i][j] = 0.0f;
#pragma unroll
    for (int kk = 0; kk < 32; kk++) {
        float a[4];
#pragma unroll
        for (int i = 0; i < 4; i++) a[i] = Rs[(ty * 4 + i) * 33 + kk];
#pragma unroll
        for (int j = 0; j < 16; j++) {
            float b = Bs[kk * 256 + tx + 16 * j];
#pragma unroll
            for (int i = 0; i < 4; i++) acc[i][j] = fmaf(a[i], b, acc[i][j]);
        }
    }
#pragma unroll
    for (int i = 0; i < 4; i++) {
        int r = ty * 4 + i;
        int e = e0 + r;
        if (e < E) {
            const float* prow = p + (size_t)s_src[r] * 256;
            const float* qrow = q + (size_t)s_dst[r] * 256;
#pragma unroll
            for (int j = 0; j < 16; j++) {
                int col = tx + 16 * j;
                float v = acc[i][j] + prow[col] + qrow[col] + s_cz[col];
                v = lrelu_f(v);
                __nv_bfloat16 h = __float2bfloat16(v);
                a1h[(size_t)e * 256 + col] = h;
                a1l[(size_t)e * 256 + col] = __float2bfloat16(v - __bfloat162float(h));
            }
        }
    }
}

// ---------------------------------------------------------------------------
// HMMA fused edge MLP (layers 2..4). CTA = 128 edges x 256 outputs, 16 warps
// (4x4 warp grid, warp tile 32x64), 2-deep B ring (dist-1 prefetch).
// Final layer: fp32 rows in SMEM -> cp.reduce.async.bulk scatter.
// Dynamic SMEM:
//   ACT_HI [0,      67584) : 128 rows x 264 bf16 (stride 528B)  (also FOUT fp32)
//   ACT_LO [67584, 135168)
//   BBUF   [135168,217088): 2 x (hi 256x40 bf16 stride 80B | lo +20480)
// ---------------------------------------------------------------------------
#define ACT_HI 0
#define ACT_LO 67584
#define BBUF   135168
#define DSMEM  217088

__global__ __launch_bounds__(512, 1) void edge_mlp_hmma(
    const __nv_bfloat16* __restrict__ a1h, const __nv_bfloat16* __restrict__ a1l,
    const int* __restrict__ edge_index, const __nv_bfloat16* __restrict__ wt,
    const float* __restrict__ b2, const float* __restrict__ b3,
    const float* __restrict__ b4, float* __restrict__ agg, int E) {
    extern __shared__ __align__(16) char dsm[];
    __shared__ int s_dst[128];
    __shared__ float s_bias[768];

    const int tid = threadIdx.x;
    const int wid = tid >> 5, lane = tid & 31;
    const int wm = wid >> 2, wn = wid & 3;
    const int r0 = wm * 32;
    const int c0 = wn * 64;
    const int e0 = blockIdx.x * 128;
    const uint32_t sb = smem_u32(dsm);

    for (int i = tid; i < 768; i += 512) {
        const float* b = (i < 256) ? b2 : (i < 512) ? b3 : b4;
        s_bias[i] = b[i & 255];
    }
    if (tid < 128) {
        int e = e0 + tid;
        s_dst[tid] = (e < E) ? edge_index[E + e] : 0;
    }

    float acc[2][8][4];
#pragma unroll
    for (int mt = 0; mt < 2; mt++)
#pragma unroll
        for (int nt = 0; nt < 8; nt++)
#pragma unroll
            for (int i = 0; i < 4; i++) acc[mt][nt][i] = 0.0f;

    auto prefetchB = [&](int t, int buf) {
        const char* wsrc = (const char*)wt + (size_t)t * 32768;
        uint32_t dbase = sb + BBUF + buf * 40960;
#pragma unroll
        for (int it = 0; it < 4; it++) {
            int id = tid + it * 512;
            int n = id & 255, rest = id >> 8;
            int seg = rest & 3, hl = rest >> 2;
            cp_async16(dbase + hl * 20480 + n * 80 + seg * 16,
                       wsrc + hl * 16384 + n * 64 + seg * 16);
        }
    };
    auto loadACT = [&]() {
#pragma unroll
        for (int it = 0; it < 16; it++) {
            int id = tid + it * 512;
            int seg = id & 31;
            int hl = (id >> 5) & 1;
            int row = id >> 6;
            int e = e0 + row;
            if (e >= E) e = E - 1;
            const char* sp = (const char*)(hl ? a1l : a1h) + (size_t)e * 512 + seg * 16;
            cp_async16(sb + (hl ? ACT_LO : ACT_HI) + (uint32_t)row * 528 + seg * 16, sp);
        }
    };
    auto compute = [&](uint32_t abase, uint32_t bbase) {
#pragma unroll
        for (int s = 0; s < 2; s++) {
            int ko2 = s * 32;
            uint32_t ah[2][4], al[2][4];
#pragma unroll
            for (int mt = 0; mt < 2; mt++) {
                uint32_t ad = abase + (uint32_t)(r0 + mt * 16 + (lane & 15)) * 528 +
                              ko2 + ((lane >> 4) << 4);
                ldsm4(ah[mt], ad);
                ldsm4(al[mt], ad + (ACT_LO - ACT_HI));
            }
#pragma unroll
            for (int q = 0; q < 4; q++) {
                int n = c0 + q * 16 + (lane & 7) + ((lane & 16) >> 1);
                uint32_t bd = bbase + (uint32_t)n * 80 + ko2 + ((lane & 8) << 1);
                uint32_t bh[4], bl[4];
                ldsm4(bh, bd);
                ldsm4(bl, bd + 20480);
#pragma unroll
                for (int mt = 0; mt < 2; mt++) {
                    mma16816(acc[mt][2 * q + 0], ah[mt], bh[0], bh[1]);
                    mma16816(acc[mt][2 * q + 1], ah[mt], bh[2], bh[3]);
                    mma16816(acc[mt][2 * q + 0], al[mt], bh[0], bh[1]);
                    mma16816(acc[mt][2 * q + 1], al[mt], bh[2], bh[3]);
                    mma16816(acc[mt][2 * q + 0], ah[mt], bl[0], bl[1]);
                    mma16816(acc[mt][2 * q + 1], ah[mt], bl[2], bl[3]);
                }
            }
        }
    };
    auto epilogue_act = [&](int bidx) {
#pragma unroll
        for (int mt = 0; mt < 2; mt++) {
#pragma unroll
            for (int nt = 0; nt < 8; nt++) {
                int ra = r0 + mt * 16 + (lane >> 2);
                int ca = c0 + nt * 8 + 2 * (lane & 3);
                float bv0 = s_bias[bidx * 256 + ca], bv1 = s_bias[bidx * 256 + ca + 1];
#pragma unroll
                for (int half = 0; half < 2; half++) {
                    int r = ra + half * 8;
                    float v0 = lrelu_f(acc[mt][nt][half * 2 + 0] + bv0);
                    float v1 = lrelu_f(acc[mt][nt][half * 2 + 1] + bv1);
                    __nv_bfloat16 h0 = __float2bfloat16(v0);
                    __nv_bfloat16 h1 = __float2bfloat16(v1);
                    __nv_bfloat162 hp; hp.x = h0; hp.y = h1;
                    __nv_bfloat162 lp;
                    lp.x = __float2bfloat16(v0 - __bfloat162float(h0));
                    lp.y = __float2bfloat16(v1 - __bfloat162float(h1));
                    uint32_t off = (uint32_t)r * 528 + (uint32_t)ca * 2;
                    *(__nv_bfloat162*)(dsm + ACT_HI + off) = hp;
                    *(__nv_bfloat162*)(dsm + ACT_LO + off) = lp;
                    acc[mt][nt][half * 2 + 0] = 0.0f;
                    acc[mt][nt][half * 2 + 1] = 0.0f;
                }
            }
        }
    };

    // prime: group0 = ACT + B(0) -> buf0, group1 = B(1) -> buf1
    loadACT();
    prefetchB(0, 0);
    CP_COMMIT();
    prefetchB(1, 1);
    CP_COMMIT();

    // 24 chunks: g = L*8 + c, L in {0(W2),1(W3),2(W4)}; buffer = g&1
    for (int g = 0; g < 24; g++) {
        if (g < 23) { CP_WAIT1(); } else { CP_WAIT0(); }
        __syncthreads();
        compute(sb + ACT_HI + (uint32_t)(g & 7) * 64, sb + BBUF + (g & 1) * 40960);
        __syncthreads();
        if (g + 2 < 24) {
            prefetchB(g + 2, g & 1);
            CP_COMMIT();
        }
        if ((g & 7) == 7) {
            int L = g >> 3;
            if (L < 2) {
                epilogue_act(L);
            } else {
#pragma unroll
                for (int mt = 0; mt < 2; mt++) {
#pragma unroll
                    for (int nt = 0; nt < 8; nt++) {
                        int ra = r0 + mt * 16 + (lane >> 2);
                        int ca = c0 + nt * 8 + 2 * (lane & 3);
                        float bv0 = s_bias[512 + ca], bv1 = s_bias[512 + ca + 1];
#pragma unroll
                        for (int half = 0; half < 2; half++) {
                            int r = ra + half * 8;
                            float2 v;
                            v.x = acc[mt][nt][half * 2 + 0] + bv0;
                            v.y = acc[mt][nt][half * 2 + 1] + bv1;
                            *(float2*)(dsm + (uint32_t)r * 1024 + (uint32_t)ca * 4) = v;
                        }
                    }
                }
                FENCE_ASYNC();
                __syncthreads();
                if (tid < 128 && (e0 + tid) < E) {
                    bulk_reduce_add_f32(agg + (size_t)s_dst[tid] * 256,
                                        sb + (uint32_t)tid * 1024, 1024);
                }
                BULK_COMMIT();
                BULK_WAIT0();
            }
        }
    }
}

// ---------------------------------------------------------------------------
extern "C" void kernel_launch(void* const* d_in, const int* in_sizes, int n_in,
                              void* d_out, int out_size) {
    const int* atom_types = (const int*)d_in[0];
    const float* x_extra = (const float*)d_in[1];
    const int* edge_index = (const int*)d_in[2];
    const float* dists = (const float*)d_in[3];
    const float* freq = (const float*)d_in[4];
    const float* emb_table = (const float*)d_in[5];
    const float* w_emb = (const float*)d_in[6];
    const float* b_emb = (const float*)d_in[7];
    const float* w_n2m = (const float*)d_in[8];
    const float* b_n2m = (const float*)d_in[9];
    const float* w_r2m = (const float*)d_in[10];
    const float* b_r2m = (const float*)d_in[11];
    const float* w_m2n = (const float*)d_in[12];
    const float* mw1 = (const float*)d_in[13];
    const float* mb1 = (const float*)d_in[14];
    const float* mw2 = (const float*)d_in[15];
    const float* mb2 = (const float*)d_in[16];
    const float* mw3 = (const float*)d_in[17];
    const float* mb3 = (const float*)d_in[18];
    const float* mw4 = (const float*)d_in[19];
    const float* mb4 = (const float*)d_in[20];
    const float* fw1 = (const float*)d_in[21];
    const float* fb1 = (const float*)d_in[22];
    const float* fw2 = (const float*)d_in[23];
    const float* fb2 = (const float*)d_in[24];
    float* out = (float*)d_out;

    int N = in_sizes[0];
    int E = in_sizes[2] / 2;

    float *p_h, *p_p, *p_q, *p_agg, *p_t, *p_u;
    float *p_wpa, *p_wqb, *p_wr2, *p_cz;
    __nv_bfloat16 *p_a1h, *p_a1l, *p_wt;
    cudaGetSymbolAddress((void**)&p_h, g_h);
    cudaGetSymbolAddress((void**)&p_p, g_p);
    cudaGetSymbolAddress((void**)&p_q, g_q);
    cudaGetSymbolAddress((void**)&p_agg, g_agg);
    cudaGetSymbolAddress((void**)&p_t, g_t);
    cudaGetSymbolAddress((void**)&p_u, g_u);
    cudaGetSymbolAddress((void**)&p_wpa, g_wpa);
    cudaGetSymbolAddress((void**)&p_wqb, g_wqb);
    cudaGetSymbolAddress((void**)&p_wr2, g_wr2);
    cudaGetSymbolAddress((void**)&p_cz, g_cz);
    cudaGetSymbolAddress((void**)&p_a1h, g_a1h);
    cudaGetSymbolAddress((void**)&p_a1l, g_a1l);
    cudaGetSymbolAddress((void**)&p_wt, g_wt);

    cudaFuncSetAttribute(edge_mlp_hmma, cudaFuncAttributeMaxDynamicSharedMemorySize, DSMEM);

    dim3 gMega((N + 63) / 64, 2, 4);
    dim3 gPQ((N + 63) / 64, 2, 2);
    dim3 gN((N + 63) / 64, 2, 1);
    int gE64 = (E + 63) / 64;
    int gE128 = (E + 127) / 128;

    // 0: h + wpa + wqb + all scalar prep (wt tiles, wr2, cz)
    k0_mega<<<gMega, 256>>>(atom_types, x_extra, emb_table, w_emb, b_emb,
                            w_n2m, b_n2m, w_r2m, b_r2m, mw1, mb1, mw2, mw3, mw4,
                            p_h, p_wpa, p_wqb, p_wr2, p_cz, p_wt, N);
    // 1: p & q (+ zero agg)
    gemm_bn128<<<gPQ, 256>>>(p_h, 256, p_wpa, nullptr, nullptr, p_p, N, 0,
                             p_wqb, p_q, p_agg);
    // 2: edge combine -> a1 hi/lo
    edge_combine<<<gE64, 256>>>(dists, freq, p_wr2, p_p, p_q, p_cz, edge_index,
                                p_a1h, p_a1l, E);
    // 3: fused edge MLP (profiled launch)
    edge_mlp_hmma<<<gE128, 512, DSMEM>>>(p_a1h, p_a1l, edge_index, p_wt,
                                         mb2, mb3, mb4, p_agg, E);
    // 4-6: output chain
    gemm_bn128<<<gN, 256>>>(p_agg, 256, w_m2n, nullptr, p_h, p_t, N, 0,
                            nullptr, nullptr, nullptr);
    gemm_bn128<<<gN, 256>>>(p_t, 256, fw1, fb1, nullptr, p_u, N, 1,
                            nullptr, nullptr, nullptr);
    gemm_bn128<<<gN, 256>>>(p_u, 256, fw2, fb2, p_t, out, N, 0,
                            nullptr, nullptr, nullptr);
}

// round 12
// speedup vs baseline: 1.1217x; 1.1217x over previous
#include <cuda_runtime.h>
#include <cuda_bf16.h>
#include <math.h>
#include <stdint.h>

#define NN 10000
#define EE 160000
#define HH 256

// ---------------------------------------------------------------------------
// Scratch (no runtime allocation allowed)
// ---------------------------------------------------------------------------
__device__ float g_h[NN * HH];
__device__ float g_p[NN * HH];
__device__ float g_q[NN * HH];
__device__ float g_agg[NN * HH];
__device__ float g_t[NN * HH];
__device__ float g_u[NN * HH];
__device__ float g_wpa[256 * 256];
__device__ float g_wqb[256 * 256];
__device__ float g_wr2[32 * 256];
__device__ float g_cz[256];
// act1 (layer-1 activations) hi/lo bf16, [E, 256]
__device__ __nv_bfloat16 g_a1h[(size_t)EE * HH];
__device__ __nv_bfloat16 g_a1l[(size_t)EE * HH];
// Transposed weights W^T[N=256, Kc=32] tiles (24): 0..7=W2, 8..15=W3, 16..23=W4
__device__ __align__(16) __nv_bfloat16 g_wt[24 * 16384];

__device__ __forceinline__ float gelu_f(float x) {
    float x3 = x * x * x;
    return 0.5f * x * (1.0f + tanhf(0.7978845608028654f * (x + 0.044715f * x3)));
}
__device__ __forceinline__ float lrelu_f(float x) { return x > 0.0f ? x : 0.01f * x; }

// ---------------------------------------------------------------------------
// PTX helpers (sm_80/sm_90 base ISA: valid at .target sm_100)
// ---------------------------------------------------------------------------
__device__ __forceinline__ uint32_t smem_u32(const void* p) {
    uint32_t a;
    asm("{ .reg .u64 t; cvta.to.shared.u64 t, %1; cvt.u32.u64 %0, t; }" : "=r"(a) : "l"(p));
    return a;
}
__device__ __forceinline__ void cp_async16(uint32_t smem_addr, const void* gptr) {
    asm volatile("cp.async.cg.shared.global [%0], [%1], 16;\n" :: "r"(smem_addr), "l"(gptr));
}
#define CP_COMMIT() asm volatile("cp.async.commit_group;\n" ::: "memory")
#define CP_WAIT0()  asm volatile("cp.async.wait_group 0;\n" ::: "memory")
#define CP_WAIT1()  asm volatile("cp.async.wait_group 1;\n" ::: "memory")

__device__ __forceinline__ void bulk_reduce_add_f32(void* gdst, uint32_t ssrc, uint32_t bytes) {
    asm volatile("cp.reduce.async.bulk.global.shared::cta.bulk_group.add.f32 [%0], [%1], %2;\n"
                 :: "l"(gdst), "r"(ssrc), "r"(bytes) : "memory");
}
#define BULK_COMMIT() asm volatile("cp.async.bulk.commit_group;" ::: "memory")
#define BULK_WAIT0()  asm volatile("cp.async.bulk.wait_group 0;" ::: "memory")
#define FENCE_ASYNC() asm volatile("fence.proxy.async.shared::cta;" ::: "memory")

__device__ __forceinline__ void ldsm4(uint32_t* f, uint32_t a) {
    asm volatile("ldmatrix.sync.aligned.m8n8.x4.shared.b16 {%0,%1,%2,%3}, [%4];\n"
                 : "=r"(f[0]), "=r"(f[1]), "=r"(f[2]), "=r"(f[3]) : "r"(a));
}
__device__ __forceinline__ void mma16816(float* d, const uint32_t* a, uint32_t b0, uint32_t b1) {
    asm volatile(
        "mma.sync.aligned.m16n8k16.row.col.f32.bf16.bf16.f32 "
        "{%0,%1,%2,%3}, {%4,%5,%6,%7}, {%8,%9}, {%0,%1,%2,%3};\n"
        : "+f"(d[0]), "+f"(d[1]), "+f"(d[2]), "+f"(d[3])
        : "r"(a[0]), "r"(a[1]), "r"(a[2]), "r"(a[3]), "r"(b0), "r"(b1));
}

// ---------------------------------------------------------------------------
// Mega kernel 0:
//   z=0 -> h = gelu(xcat@w_emb+b)   (xcat gathered on the fly)
//   z=1 -> wpa = w_n2m @ mw1a ; z=2 -> wqb = w_n2m @ mw1b
//   z=3 -> wr2 = w_r2m @ mw1c (rows=32 GEMM)
//   z=4 -> flat prep: wt tiles (W2/3/4) + cz
// ---------------------------------------------------------------------------
__global__ __launch_bounds__(256, 2) void k0_mega(
    const int* __restrict__ atom_types, const float* __restrict__ x_extra,
    const float* __restrict__ emb_table,
    const float* __restrict__ w_emb, const float* __restrict__ b_emb,
    const float* __restrict__ w_n2m, const float* __restrict__ b_n2m,
    const float* __restrict__ w_r2m, const float* __restrict__ b_r2m,
    const float* __restrict__ mw1, const float* __restrict__ mb1,
    const float* __restrict__ mw2, const float* __restrict__ mw3,
    const float* __restrict__ mw4,
    float* __restrict__ h, float* __restrict__ wpa, float* __restrict__ wqb,
    float* __restrict__ wr2, float* __restrict__ cz,
    __nv_bfloat16* __restrict__ wt, int N) {
    int z = blockIdx.z;
    if (z == 4) {
        // flat prep: [0,196608) wt tiles; [196608,196864) cz
        int bid = blockIdx.x * 2 + blockIdx.y;
        int flat = bid * 256 + (int)threadIdx.x;     // stride 80384
        for (int item = flat; item < 196864; item += 80384) {
            if (item < 196608) {
                int kg = item >> 8, n = item & 255;
                const float* w; int kl, t;
                if (kg < 256)      { w = mw2; kl = kg;       t = kl >> 5; }
                else if (kg < 512) { w = mw3; kl = kg - 256; t = 8 + (kl >> 5); }
                else               { w = mw4; kl = kg - 512; t = 16 + (kl >> 5); }
                int kk = kl & 31;
                float v = w[(long)kl * 256 + n];
                __nv_bfloat16 hh = __float2bfloat16(v);
                __nv_bfloat16 ll = __float2bfloat16(v - __bfloat162float(hh));
                size_t base = (size_t)t * 16384 + n * 32 + kk;
                wt[base] = hh;
                wt[base + 8192] = ll;
            } else {
                int n = item - 196608;
                float s = mb1[n];
                for (int k = 0; k < 256; k++) {
                    s += b_n2m[k] * (mw1[(long)k * 256 + n] + mw1[(long)(256 + k) * 256 + n]);
                    s += b_r2m[k] * mw1[(long)(512 + k) * 256 + n];
                }
                cz[n] = s;
            }
        }
        return;
    }

    // ---- GEMM path ----
    __shared__ float As[64 * 33];
    __shared__ float Bs[32 * 132];
    const float* A = nullptr;
    const float* W;
    const float* bias = nullptr;
    float* C;
    int K, rows, act = 0;
    bool gather = false;
    if (z == 0)      { gather = true; K = 48; W = w_emb; bias = b_emb; C = h; rows = N; act = 1; }
    else if (z == 1) { A = w_n2m; K = 256; W = mw1;               C = wpa; rows = 256; }
    else if (z == 2) { A = w_n2m; K = 256; W = mw1 + 65536;       C = wqb; rows = 256; }
    else             { A = w_r2m; K = 256; W = mw1 + 131072;      C = wr2; rows = 32; }

    int tid = threadIdx.x, tx = tid & 15, ty = tid >> 4;
    int row0 = blockIdx.x * 64;
    int col0 = blockIdx.y * 128;
    if (row0 >= rows) return;

    float acc[4][8];
#pragma unroll
    for (int i = 0; i < 4; i++)
#pragma unroll
        for (int j = 0; j < 8; j++) acc[i][j] = 0.0f;
    for (int k0 = 0; k0 < K; k0 += 32) {
#pragma unroll
        for (int i = 0; i < 8; i++) {
            int idx = tid + i * 256, r = idx >> 5, c = idx & 31;
            int gr = row0 + r, gk = k0 + c;
            float v = 0.0f;
            if (gr < rows && gk < K) {
                if (gather)
                    v = (gk < 32) ? emb_table[atom_types[gr] * 32 + gk]
                                  : x_extra[gr * 16 + gk - 32];
                else
                    v = A[(long)gr * K + gk];
            }
            As[r * 33 + c] = v;
        }
#pragma unroll
        for (int i = 0; i < 16; i++) {
            int idx = tid + i * 256, r = idx >> 7, c = idx & 127;
            int gk = k0 + r;
            Bs[r * 132 + c] = (gk < K) ? W[(long)gk * 256 + col0 + c] : 0.0f;
        }
        __syncthreads();
#pragma unroll
        for (int kk = 0; kk < 32; kk++) {
            float a[4];
#pragma unroll
            for (int i = 0; i < 4; i++) a[i] = As[(ty * 4 + i) * 33 + kk];
#pragma unroll
            for (int j = 0; j < 8; j++) {
                float b = Bs[kk * 132 + tx + 16 * j];
#pragma unroll
                for (int i = 0; i < 4; i++) acc[i][j] = fmaf(a[i], b, acc[i][j]);
            }
        }
        __syncthreads();
    }
#pragma unroll
    for (int i = 0; i < 4; i++) {
        int r = row0 + ty * 4 + i;
        if (r < rows) {
#pragma unroll
            for (int j = 0; j < 8; j++) {
                int col = col0 + tx + 16 * j;
                float v = acc[i][j];
                if (bias) v += bias[col];
                if (act == 1) v = gelu_f(v);
                C[(long)r * 256 + col] = v;
            }
        }
    }
}

// ---------------------------------------------------------------------------
// Node-side GEMM, BM=64, BN=128 (gridDim.y=2); blockIdx.z==1 selects (W2,C2);
// zbuf (if set, z==0) is zeroed over the same tile footprint.
// ---------------------------------------------------------------------------
__global__ __launch_bounds__(256, 2) void gemm_bn128(
    const float* __restrict__ A, int K, const float* __restrict__ W,
    const float* __restrict__ bias, const float* __restrict__ res,
    float* __restrict__ C, int rows, int act,
    const float* __restrict__ W2, float* __restrict__ C2,
    float* __restrict__ zbuf) {
    __shared__ float As[64 * 33];
    __shared__ float Bs[32 * 132];
    if (blockIdx.z == 1) { W = W2; C = C2; }
    int tid = threadIdx.x, tx = tid & 15, ty = tid >> 4;
    int row0 = blockIdx.x * 64;
    int col0 = blockIdx.y * 128;
    if (row0 >= rows) return;
    float acc[4][8];
#pragma unroll
    for (int i = 0; i < 4; i++)
#pragma unroll
        for (int j = 0; j < 8; j++) acc[i][j] = 0.0f;
    for (int k0 = 0; k0 < K; k0 += 32) {
#pragma unroll
        for (int i = 0; i < 8; i++) {
            int idx = tid + i * 256, r = idx >> 5, c = idx & 31;
            int gr = row0 + r, gk = k0 + c;
            As[r * 33 + c] = (gr < rows && gk < K) ? A[(long)gr * K + gk] : 0.0f;
        }
#pragma unroll
        for (int i = 0; i < 16; i++) {
            int idx = tid + i * 256, r = idx >> 7, c = idx & 127;
            int gk = k0 + r;
            Bs[r * 132 + c] = (gk < K) ? W[(long)gk * 256 + col0 + c] : 0.0f;
        }
        __syncthreads();
#pragma unroll
        for (int kk = 0; kk < 32; kk++) {
            float a[4];
#pragma unroll
            for (int i = 0; i < 4; i++) a[i] = As[(ty * 4 + i) * 33 + kk];
#pragma unroll
            for (int j = 0; j < 8; j++) {
                float b = Bs[kk * 132 + tx + 16 * j];
#pragma unroll
                for (int i = 0; i < 4; i++) acc[i][j] = fmaf(a[i], b, acc[i][j]);
            }
        }
        __syncthreads();
    }
#pragma unroll
    for (int i = 0; i < 4; i++) {
        int r = row0 + ty * 4 + i;
        if (r < rows) {
#pragma unroll
            for (int j = 0; j < 8; j++) {
                int col = col0 + tx + 16 * j;
                float v = acc[i][j];
                if (bias) v += bias[col];
                if (act == 1) v = gelu_f(v);
                if (res) v += res[(long)r * 256 + col];
                C[(long)r * 256 + col] = v;
                if (zbuf && blockIdx.z == 0) zbuf[(long)r * 256 + col] = 0.0f;
            }
        }
    }
}

// ---------------------------------------------------------------------------
// edge combine: act1 = lrelu( rbf@Wr2 + p[src] + q[dst] + cz ) -> bf16 hi/lo
// ---------------------------------------------------------------------------
__global__ __launch_bounds__(256, 2) void edge_combine(
    const float* __restrict__ dists, const float* __restrict__ freq,
    const float* __restrict__ wr2, const float* __restrict__ p,
    const float* __restrict__ q, const float* __restrict__ cz,
    const int* __restrict__ edge_index,
    __nv_bfloat16* __restrict__ a1h, __nv_bfloat16* __restrict__ a1l, int E) {
    __shared__ float Rs[64 * 33];
    __shared__ float Bs[32 * 256];
    __shared__ float s_freq[32];
    __shared__ float s_cz[256];
    __shared__ int s_src[64], s_dst[64];
    int tid = threadIdx.x, tx = tid & 15, ty = tid >> 4;
    int e0 = blockIdx.x * 64;
    if (tid < 32) s_freq[tid] = freq[tid];
    s_cz[tid] = cz[tid];
    if (tid < 64) {
        int e = e0 + tid;
        s_src[tid] = (e < E) ? edge_index[e] : 0;
        s_dst[tid] = (e < E) ? edge_index[E + e] : 0;
    }
#pragma unroll
    for (int i = 0; i < 32; i++) Bs[i * 256 + tid] = wr2[i * 256 + tid];
    __syncthreads();
#pragma unroll
    for (int i = 0; i < 8; i++) {
        int idx = tid + i * 256, el = idx >> 5, r = idx & 31;
        int e = e0 + el;
        float d = (e < E) ? dists[e] * 0.2f : 1.0f;
        float d2 = d * d, d5 = d2 * d2 * d;
        float env = 1.0f / d + d5 * (-28.0f + d * (48.0f + d * (-21.0f)));
        Rs[el * 33 + r] = env * sinf(s_freq[r] * d);
    }
    __syncthreads();
    float acc[4][16];
#pragma unroll
    for (int i = 0; i < 4; i++)
#pragma unroll
        for (int j = 0; j < 16; j++) acc[i][j] = 0.0f;
#pragma unroll
    for (int kk = 0; kk < 32; kk++) {
        float a[4];
#pragma unroll
        for (int i = 0; i < 4; i++) a[i] = Rs[(ty * 4 + i) * 33 + kk];
#pragma unroll
        for (int j = 0; j < 16; j++) {
            float b = Bs[kk * 256 + tx + 16 * j];
#pragma unroll
            for (int i = 0; i < 4; i++) acc[i][j] = fmaf(a[i], b, acc[i][j]);
        }
    }
#pragma unroll
    for (int i = 0; i < 4; i++) {
        int r = ty * 4 + i;
        int e = e0 + r;
        if (e < E) {
            const float* prow = p + (size_t)s_src[r] * 256;
            const float* qrow = q + (size_t)s_dst[r] * 256;
#pragma unroll
            for (int j = 0; j < 16; j++) {
                int col = tx + 16 * j;
                float v = acc[i][j] + prow[col] + qrow[col] + s_cz[col];
                v = lrelu_f(v);
                __nv_bfloat16 h = __float2bfloat16(v);
                a1h[(size_t)e * 256 + col] = h;
                a1l[(size_t)e * 256 + col] = __float2bfloat16(v - __bfloat162float(h));
            }
        }
    }
}

// ---------------------------------------------------------------------------
// HMMA fused edge MLP (layers 2..4). CTA = 128 edges x 256 outputs, 16 warps.
// Per-N-group pipelines: the 4 warps sharing wn (= one SMSP) prefetch their own
// 64-col B slice and sync via a 128-thread named barrier. Full __syncthreads
// only at layer boundaries (ACT hand-off) and before the final FOUT staging.
// Dynamic SMEM:
//   ACT_HI [0,      67584) : 128 rows x 264 bf16 (stride 528B)  (also FOUT fp32)
//   ACT_LO [67584, 135168)
//   BBUF   [135168,217088): 2 x (hi 256x40 bf16 stride 80B | lo +20480)
// ---------------------------------------------------------------------------
#define ACT_HI 0
#define ACT_LO 67584
#define BBUF   135168
#define DSMEM  217088

__global__ __launch_bounds__(512, 1) void edge_mlp_hmma(
    const __nv_bfloat16* __restrict__ a1h, const __nv_bfloat16* __restrict__ a1l,
    const int* __restrict__ edge_index, const __nv_bfloat16* __restrict__ wt,
    const float* __restrict__ b2, const float* __restrict__ b3,
    const float* __restrict__ b4, float* __restrict__ agg, int E) {
    extern __shared__ __align__(16) char dsm[];
    __shared__ int s_dst[128];
    __shared__ float s_bias[768];

    const int tid = threadIdx.x;
    const int wid = tid >> 5, lane = tid & 31;
    const int wm = wid >> 2, wn = wid & 3;
    const int r0 = wm * 32;
    const int c0 = wn * 64;
    const int gtid = lane + wm * 32;     // 0..127 within N-group wn
    const int e0 = blockIdx.x * 128;
    const uint32_t sb = smem_u32(dsm);

    for (int i = tid; i < 768; i += 512) {
        const float* b = (i < 256) ? b2 : (i < 512) ? b3 : b4;
        s_bias[i] = b[i & 255];
    }
    if (tid < 128) {
        int e = e0 + tid;
        s_dst[tid] = (e < E) ? edge_index[E + e] : 0;
    }

    float acc[2][8][4];
#pragma unroll
    for (int mt = 0; mt < 2; mt++)
#pragma unroll
        for (int nt = 0; nt < 8; nt++)
#pragma unroll
            for (int i = 0; i < 4; i++) acc[mt][nt][i] = 0.0f;

    auto groupbar = [&]() {
        asm volatile("bar.sync %0, 128;" :: "r"(1 + wn) : "memory");
    };
    // group-scoped B prefetch: cols [c0, c0+64), 512 x 16B over 128 threads
    auto prefetchB = [&](int t, int buf) {
        const char* wsrc = (const char*)wt + (size_t)t * 32768;
        uint32_t dbase = sb + BBUF + buf * 40960;
#pragma unroll
        for (int it = 0; it < 4; it++) {
            int id = gtid + it * 128;        // 0..511
            int hl = id >> 8;
            int rest = id & 255;
            int nl = rest >> 2, seg = rest & 3;
            int n = c0 + nl;
            cp_async16(dbase + hl * 20480 + (uint32_t)n * 80 + seg * 16,
                       wsrc + hl * 16384 + (size_t)n * 64 + seg * 16);
        }
    };
    auto loadACT = [&]() {
#pragma unroll
        for (int it = 0; it < 16; it++) {
            int id = tid + it * 512;
            int seg = id & 31;
            int hl = (id >> 5) & 1;
            int row = id >> 6;
            int e = e0 + row;
            if (e >= E) e = E - 1;
            const char* sp = (const char*)(hl ? a1l : a1h) + (size_t)e * 512 + seg * 16;
            cp_async16(sb + (hl ? ACT_LO : ACT_HI) + (uint32_t)row * 528 + seg * 16, sp);
        }
    };
    auto compute = [&](uint32_t abase, uint32_t bbase) {
#pragma unroll
        for (int s = 0; s < 2; s++) {
            int ko2 = s * 32;
            uint32_t ah[2][4], al[2][4];
#pragma unroll
            for (int mt = 0; mt < 2; mt++) {
                uint32_t ad = abase + (uint32_t)(r0 + mt * 16 + (lane & 15)) * 528 +
                              ko2 + ((lane >> 4) << 4);
                ldsm4(ah[mt], ad);
                ldsm4(al[mt], ad + (ACT_LO - ACT_HI));
            }
#pragma unroll
            for (int q = 0; q < 4; q++) {
                int n = c0 + q * 16 + (lane & 7) + ((lane & 16) >> 1);
                uint32_t bd = bbase + (uint32_t)n * 80 + ko2 + ((lane & 8) << 1);
                uint32_t bh[4], bl[4];
                ldsm4(bh, bd);
                ldsm4(bl, bd + 20480);
#pragma unroll
                for (int mt = 0; mt < 2; mt++) {
                    mma16816(acc[mt][2 * q + 0], ah[mt], bh[0], bh[1]);
                    mma16816(acc[mt][2 * q + 1], ah[mt], bh[2], bh[3]);
                    mma16816(acc[mt][2 * q + 0], al[mt], bh[0], bh[1]);
                    mma16816(acc[mt][2 * q + 1], al[mt], bh[2], bh[3]);
                    mma16816(acc[mt][2 * q + 0], ah[mt], bl[0], bl[1]);
                    mma16816(acc[mt][2 * q + 1], ah[mt], bl[2], bl[3]);
                }
            }
        }
    };
    auto epilogue_act = [&](int bidx) {
#pragma unroll
        for (int mt = 0; mt < 2; mt++) {
#pragma unroll
            for (int nt = 0; nt < 8; nt++) {
                int ra = r0 + mt * 16 + (lane >> 2);
                int ca = c0 + nt * 8 + 2 * (lane & 3);
                float bv0 = s_bias[bidx * 256 + ca], bv1 = s_bias[bidx * 256 + ca + 1];
#pragma unroll
                for (int half = 0; half < 2; half++) {
                    int r = ra + half * 8;
                    float v0 = lrelu_f(acc[mt][nt][half * 2 + 0] + bv0);
                    float v1 = lrelu_f(acc[mt][nt][half * 2 + 1] + bv1);
                    __nv_bfloat16 h0 = __float2bfloat16(v0);
                    __nv_bfloat16 h1 = __float2bfloat16(v1);
                    __nv_bfloat162 hp; hp.x = h0; hp.y = h1;
                    __nv_bfloat162 lp;
                    lp.x = __float2bfloat16(v0 - __bfloat162float(h0));
                    lp.y = __float2bfloat16(v1 - __bfloat162float(h1));
                    uint32_t off = (uint32_t)r * 528 + (uint32_t)ca * 2;
                    *(__nv_bfloat162*)(dsm + ACT_HI + off) = hp;
                    *(__nv_bfloat162*)(dsm + ACT_LO + off) = lp;
                    acc[mt][nt][half * 2 + 0] = 0.0f;
                    acc[mt][nt][half * 2 + 1] = 0.0f;
                }
            }
        }
    };

    // prime: group0 = {ACT + B(0) slice}, group1 = {B(1) slice}
    loadACT();
    prefetchB(0, 0);
    CP_COMMIT();
    prefetchB(1, 1);
    CP_COMMIT();

    // 24 chunks: g = L*8 + c, L in {0(W2),1(W3),2(W4)}; buffer = g&1
    for (int g = 0; g < 24; g++) {
        if (g < 23) { CP_WAIT1(); } else { CP_WAIT0(); }
        if (g == 0 || g == 8 || g == 16) __syncthreads();  // ACT visibility
        else groupbar();                                   // B(g) visibility (group)
        compute(sb + ACT_HI + (uint32_t)(g & 7) * 64, sb + BBUF + (g & 1) * 40960);
        if (g + 2 < 24) {
            groupbar();                  // group done reading buf g&1
            prefetchB(g + 2, g & 1);
            CP_COMMIT();
        }
        if (g == 7 || g == 15) {
            __syncthreads();             // all groups done reading ACT this layer
            epilogue_act(g >> 3);
            // ACT published by the __syncthreads at g==8 / g==16
        } else if (g == 23) {
            __syncthreads();             // all groups done reading ACT (layer 4)
            // final: bias -> fp32 rows in SMEM (reuse ACT area), bulk-reduce
#pragma unroll
            for (int mt = 0; mt < 2; mt++) {
#pragma unroll
                for (int nt = 0; nt < 8; nt++) {
                    int ra = r0 + mt * 16 + (lane >> 2);
                    int ca = c0 + nt * 8 + 2 * (lane & 3);
                    float bv0 = s_bias[512 + ca], bv1 = s_bias[512 + ca + 1];
#pragma unroll
                    for (int half = 0; half < 2; half++) {
                        int r = ra + half * 8;
                        float2 v;
                        v.x = acc[mt][nt][half * 2 + 0] + bv0;
                        v.y = acc[mt][nt][half * 2 + 1] + bv1;
                        *(float2*)(dsm + (uint32_t)r * 1024 + (uint32_t)ca * 4) = v;
                    }
                }
            }
            FENCE_ASYNC();
            __syncthreads();
            if (tid < 128 && (e0 + tid) < E) {
                bulk_reduce_add_f32(agg + (size_t)s_dst[tid] * 256,
                                    sb + (uint32_t)tid * 1024, 1024);
            }
            BULK_COMMIT();
            BULK_WAIT0();
        }
    }
}

// ---------------------------------------------------------------------------
extern "C" void kernel_launch(void* const* d_in, const int* in_sizes, int n_in,
                              void* d_out, int out_size) {
    const int* atom_types = (const int*)d_in[0];
    const float* x_extra = (const float*)d_in[1];
    const int* edge_index = (const int*)d_in[2];
    const float* dists = (const float*)d_in[3];
    const float* freq = (const float*)d_in[4];
    const float* emb_table = (const float*)d_in[5];
    const float* w_emb = (const float*)d_in[6];
    const float* b_emb = (const float*)d_in[7];
    const float* w_n2m = (const float*)d_in[8];
    const float* b_n2m = (const float*)d_in[9];
    const float* w_r2m = (const float*)d_in[10];
    const float* b_r2m = (const float*)d_in[11];
    const float* w_m2n = (const float*)d_in[12];
    const float* mw1 = (const float*)d_in[13];
    const float* mb1 = (const float*)d_in[14];
    const float* mw2 = (const float*)d_in[15];
    const float* mb2 = (const float*)d_in[16];
    const float* mw3 = (const float*)d_in[17];
    const float* mb3 = (const float*)d_in[18];
    const float* mw4 = (const float*)d_in[19];
    const float* mb4 = (const float*)d_in[20];
    const float* fw1 = (const float*)d_in[21];
    const float* fb1 = (const float*)d_in[22];
    const float* fw2 = (const float*)d_in[23];
    const float* fb2 = (const float*)d_in[24];
    float* out = (float*)d_out;

    int N = in_sizes[0];
    int E = in_sizes[2] / 2;

    float *p_h, *p_p, *p_q, *p_agg, *p_t, *p_u;
    float *p_wpa, *p_wqb, *p_wr2, *p_cz;
    __nv_bfloat16 *p_a1h, *p_a1l, *p_wt;
    cudaGetSymbolAddress((void**)&p_h, g_h);
    cudaGetSymbolAddress((void**)&p_p, g_p);
    cudaGetSymbolAddress((void**)&p_q, g_q);
    cudaGetSymbolAddress((void**)&p_agg, g_agg);
    cudaGetSymbolAddress((void**)&p_t, g_t);
    cudaGetSymbolAddress((void**)&p_u, g_u);
    cudaGetSymbolAddress((void**)&p_wpa, g_wpa);
    cudaGetSymbolAddress((void**)&p_wqb, g_wqb);
    cudaGetSymbolAddress((void**)&p_wr2, g_wr2);
    cudaGetSymbolAddress((void**)&p_cz, g_cz);
    cudaGetSymbolAddress((void**)&p_a1h, g_a1h);
    cudaGetSymbolAddress((void**)&p_a1l, g_a1l);
    cudaGetSymbolAddress((void**)&p_wt, g_wt);

    cudaFuncSetAttribute(edge_mlp_hmma, cudaFuncAttributeMaxDynamicSharedMemorySize, DSMEM);

    dim3 gMega((N + 63) / 64, 2, 5);
    dim3 gPQ((N + 63) / 64, 2, 2);
    dim3 gN((N + 63) / 64, 2, 1);
    int gE64 = (E + 63) / 64;
    int gE128 = (E + 127) / 128;

    // 0: h + wpa + wqb + wr2 + scalar prep (wt tiles, cz)
    k0_mega<<<gMega, 256>>>(atom_types, x_extra, emb_table, w_emb, b_emb,
                            w_n2m, b_n2m, w_r2m, b_r2m, mw1, mb1, mw2, mw3, mw4,
                            p_h, p_wpa, p_wqb, p_wr2, p_cz, p_wt, N);
    // 1: p & q (+ zero agg)
    gemm_bn128<<<gPQ, 256>>>(p_h, 256, p_wpa, nullptr, nullptr, p_p, N, 0,
                             p_wqb, p_q, p_agg);
    // 2: edge combine -> a1 hi/lo
    edge_combine<<<gE64, 256>>>(dists, freq, p_wr2, p_p, p_q, p_cz, edge_index,
                                p_a1h, p_a1l, E);
    // 3: fused edge MLP (profiled launch)
    edge_mlp_hmma<<<gE128, 512, DSMEM>>>(p_a1h, p_a1l, edge_index, p_wt,
                                         mb2, mb3, mb4, p_agg, E);
    // 4-6: output chain
    gemm_bn128<<<gN, 256>>>(p_agg, 256, w_m2n, nullptr, p_h, p_t, N, 0,
                            nullptr, nullptr, nullptr);
    gemm_bn128<<<gN, 256>>>(p_t, 256, fw1, fb1, nullptr, p_u, N, 1,
                            nullptr, nullptr, nullptr);
    gemm_bn128<<<gN, 256>>>(p_u, 256, fw2, fb2, p_t, out, N, 0,
                            nullptr, nullptr, nullptr);
}

// round 13
// speedup vs baseline: 1.4637x; 1.3049x over previous
#include <cuda_runtime.h>
#include <cuda_bf16.h>
#include <math.h>
#include <stdint.h>

#define NN 10000
#define EE 160000
#define HH 256

// ---------------------------------------------------------------------------
// Scratch (no runtime allocation allowed)
// ---------------------------------------------------------------------------
__device__ float g_h[NN * HH];
__device__ float g_p[NN * HH];
__device__ float g_q[NN * HH];
__device__ float g_agg[NN * HH];
__device__ float g_t[NN * HH];
__device__ float g_wr2[32 * 256];
__device__ float g_cz[256];
__device__ __nv_bfloat16 g_hh[NN * HH], g_hl[NN * HH];
__device__ __nv_bfloat16 g_aggh[NN * HH], g_aggl[NN * HH];
__device__ __nv_bfloat16 g_th[NN * HH], g_tl[NN * HH];
__device__ __nv_bfloat16 g_uh[NN * HH], g_ul[NN * HH];
// act1 hi/lo bf16, [E, 256]
__device__ __nv_bfloat16 g_a1h[(size_t)EE * HH];
__device__ __nv_bfloat16 g_a1l[(size_t)EE * HH];
// W^T[N=256, Kc=32] tiles (hi 8192 + lo 8192 bf16 each):
// 0..7 W2 | 8..15 W3 | 16..23 W4 | 24..31 w_m2n | 32..39 fw1 | 40..47 fw2
// 48..55 wpa (runtime fold) | 56..63 wqb (runtime fold)
__device__ __align__(16) __nv_bfloat16 g_wt[64 * 16384];

__device__ __forceinline__ float gelu_f(float x) {
    float x3 = x * x * x;
    return 0.5f * x * (1.0f + tanhf(0.7978845608028654f * (x + 0.044715f * x3)));
}
__device__ __forceinline__ float lrelu_f(float x) { return x > 0.0f ? x : 0.01f * x; }

// ---------------------------------------------------------------------------
// PTX helpers (sm_80/sm_90 base ISA: valid at .target sm_100)
// ---------------------------------------------------------------------------
__device__ __forceinline__ uint32_t smem_u32(const void* p) {
    uint32_t a;
    asm("{ .reg .u64 t; cvta.to.shared.u64 t, %1; cvt.u32.u64 %0, t; }" : "=r"(a) : "l"(p));
    return a;
}
__device__ __forceinline__ void cp_async16(uint32_t smem_addr, const void* gptr) {
    asm volatile("cp.async.cg.shared.global [%0], [%1], 16;\n" :: "r"(smem_addr), "l"(gptr));
}
#define CP_COMMIT() asm volatile("cp.async.commit_group;\n" ::: "memory")
#define CP_WAIT0()  asm volatile("cp.async.wait_group 0;\n" ::: "memory")
#define CP_WAIT1()  asm volatile("cp.async.wait_group 1;\n" ::: "memory")

__device__ __forceinline__ void bulk_reduce_add_f32(void* gdst, uint32_t ssrc, uint32_t bytes) {
    asm volatile("cp.reduce.async.bulk.global.shared::cta.bulk_group.add.f32 [%0], [%1], %2;\n"
                 :: "l"(gdst), "r"(ssrc), "r"(bytes) : "memory");
}
#define BULK_COMMIT() asm volatile("cp.async.bulk.commit_group;" ::: "memory")
#define BULK_WAIT0()  asm volatile("cp.async.bulk.wait_group 0;" ::: "memory")
#define FENCE_ASYNC() asm volatile("fence.proxy.async.shared::cta;" ::: "memory")

__device__ __forceinline__ void ldsm4(uint32_t* f, uint32_t a) {
    asm volatile("ldmatrix.sync.aligned.m8n8.x4.shared.b16 {%0,%1,%2,%3}, [%4];\n"
                 : "=r"(f[0]), "=r"(f[1]), "=r"(f[2]), "=r"(f[3]) : "r"(a));
}
__device__ __forceinline__ void mma16816(float* d, const uint32_t* a, uint32_t b0, uint32_t b1) {
    asm volatile(
        "mma.sync.aligned.m16n8k16.row.col.f32.bf16.bf16.f32 "
        "{%0,%1,%2,%3}, {%4,%5,%6,%7}, {%8,%9}, {%0,%1,%2,%3};\n"
        : "+f"(d[0]), "+f"(d[1]), "+f"(d[2]), "+f"(d[3])
        : "r"(a[0]), "r"(a[1]), "r"(a[2]), "r"(a[3]), "r"(b0), "r"(b1));
}

// SMEM layout (edge + node HMMA kernels)
#define ACT_HI 0
#define ACT_LO 67584
#define BBUF   135168
#define DSMEM  217088

// ---------------------------------------------------------------------------
// Mega kernel 0:
//   z=0 -> h = gelu(xcat@w_emb+b) (gathered) + h hi/lo
//   z=1 -> wpa = w_n2m @ mw1a -> wt tiles 48..55
//   z=2 -> wqb = w_n2m @ mw1b -> wt tiles 56..63
//   z=3 -> wr2 = w_r2m @ mw1c (rows=32, fp32)
//   z=4 -> flat prep: wt tiles for W2/W3/W4/w_m2n/fw1/fw2 + cz
// ---------------------------------------------------------------------------
__global__ __launch_bounds__(256, 2) void k0_mega(
    const int* __restrict__ atom_types, const float* __restrict__ x_extra,
    const float* __restrict__ emb_table,
    const float* __restrict__ w_emb, const float* __restrict__ b_emb,
    const float* __restrict__ w_n2m, const float* __restrict__ b_n2m,
    const float* __restrict__ w_r2m, const float* __restrict__ b_r2m,
    const float* __restrict__ mw1, const float* __restrict__ mb1,
    const float* __restrict__ mw2, const float* __restrict__ mw3,
    const float* __restrict__ mw4, const float* __restrict__ w_m2n,
    const float* __restrict__ fw1, const float* __restrict__ fw2,
    float* __restrict__ h, __nv_bfloat16* __restrict__ hh, __nv_bfloat16* __restrict__ hl,
    float* __restrict__ wr2, float* __restrict__ cz,
    __nv_bfloat16* __restrict__ wt, int N) {
    int z = blockIdx.z;
    if (z == 4) {
        // flat: [0,393216) = 6 weights x 8 tiles; [393216,393472) cz
        int bid = blockIdx.x * 2 + blockIdx.y;
        int flat = bid * 256 + (int)threadIdx.x;     // stride 80384
        for (int item = flat; item < 393472; item += 80384) {
            if (item < 393216) {
                int kg = item >> 8, n = item & 255;
                const float* w; int kl, t;
                if (kg < 256)       { w = mw2;   kl = kg;        t = (kl >> 5); }
                else if (kg < 512)  { w = mw3;   kl = kg - 256;  t = 8 + (kl >> 5); }
                else if (kg < 768)  { w = mw4;   kl = kg - 512;  t = 16 + (kl >> 5); }
                else if (kg < 1024) { w = w_m2n; kl = kg - 768;  t = 24 + (kl >> 5); }
                else if (kg < 1280) { w = fw1;   kl = kg - 1024; t = 32 + (kl >> 5); }
                else                { w = fw2;   kl = kg - 1280; t = 40 + (kl >> 5); }
                int kk = kl & 31;
                float v = w[(long)kl * 256 + n];
                __nv_bfloat16 vh = __float2bfloat16(v);
                __nv_bfloat16 vl = __float2bfloat16(v - __bfloat162float(vh));
                size_t base = (size_t)t * 16384 + n * 32 + kk;
                wt[base] = vh;
                wt[base + 8192] = vl;
            } else {
                int n = item - 393216;
                float s = mb1[n];
                for (int k = 0; k < 256; k++) {
                    s += b_n2m[k] * (mw1[(long)k * 256 + n] + mw1[(long)(256 + k) * 256 + n]);
                    s += b_r2m[k] * mw1[(long)(512 + k) * 256 + n];
                }
                cz[n] = s;
            }
        }
        return;
    }

    // ---- GEMM path ----
    __shared__ float As[64 * 33];
    __shared__ float Bs[32 * 132];
    const float* A = nullptr;
    const float* W;
    const float* bias = nullptr;
    int K, rows, act = 0, foldt = -1;
    bool gather = false;
    if (z == 0)      { gather = true; K = 48; W = w_emb; bias = b_emb; rows = N; act = 1; }
    else if (z == 1) { A = w_n2m; K = 256; W = mw1;          rows = 256; foldt = 48; }
    else if (z == 2) { A = w_n2m; K = 256; W = mw1 + 65536;  rows = 256; foldt = 56; }
    else             { A = w_r2m; K = 256; W = mw1 + 131072; rows = 32; }

    int tid = threadIdx.x, tx = tid & 15, ty = tid >> 4;
    int row0 = blockIdx.x * 64;
    int col0 = blockIdx.y * 128;
    if (row0 >= rows) return;

    float acc[4][8];
#pragma unroll
    for (int i = 0; i < 4; i++)
#pragma unroll
        for (int j = 0; j < 8; j++) acc[i][j] = 0.0f;
    for (int k0 = 0; k0 < K; k0 += 32) {
#pragma unroll
        for (int i = 0; i < 8; i++) {
            int idx = tid + i * 256, r = idx >> 5, c = idx & 31;
            int gr = row0 + r, gk = k0 + c;
            float v = 0.0f;
            if (gr < rows && gk < K) {
                if (gather)
                    v = (gk < 32) ? emb_table[atom_types[gr] * 32 + gk]
                                  : x_extra[gr * 16 + gk - 32];
                else
                    v = A[(long)gr * K + gk];
            }
            As[r * 33 + c] = v;
        }
#pragma unroll
        for (int i = 0; i < 16; i++) {
            int idx = tid + i * 256, r = idx >> 7, c = idx & 127;
            int gk = k0 + r;
            Bs[r * 132 + c] = (gk < K) ? W[(long)gk * 256 + col0 + c] : 0.0f;
        }
        __syncthreads();
#pragma unroll
        for (int kk = 0; kk < 32; kk++) {
            float a[4];
#pragma unroll
            for (int i = 0; i < 4; i++) a[i] = As[(ty * 4 + i) * 33 + kk];
#pragma unroll
            for (int j = 0; j < 8; j++) {
                float b = Bs[kk * 132 + tx + 16 * j];
#pragma unroll
                for (int i = 0; i < 4; i++) acc[i][j] = fmaf(a[i], b, acc[i][j]);
            }
        }
        __syncthreads();
    }
#pragma unroll
    for (int i = 0; i < 4; i++) {
        int r = row0 + ty * 4 + i;
        if (r < rows) {
#pragma unroll
            for (int j = 0; j < 8; j++) {
                int col = col0 + tx + 16 * j;
                float v = acc[i][j];
                if (bias) v += bias[col];
                if (act == 1) v = gelu_f(v);
                if (foldt >= 0) {
                    int t = foldt + (r >> 5);
                    size_t base = (size_t)t * 16384 + (size_t)col * 32 + (r & 31);
                    __nv_bfloat16 vh = __float2bfloat16(v);
                    wt[base] = vh;
                    wt[base + 8192] = __float2bfloat16(v - __bfloat162float(vh));
                } else if (z == 0) {
                    h[(long)r * 256 + col] = v;
                    __nv_bfloat16 vh = __float2bfloat16(v);
                    hh[(long)r * 256 + col] = vh;
                    hl[(long)r * 256 + col] = __float2bfloat16(v - __bfloat162float(vh));
                } else {
                    wr2[(long)r * 256 + col] = v;
                }
            }
        }
    }
}

// fp32 -> hi/lo bf16
__global__ void conv_hilo(const float* __restrict__ x, __nv_bfloat16* __restrict__ xh,
                          __nv_bfloat16* __restrict__ xl, int total) {
    int i = blockIdx.x * blockDim.x + threadIdx.x;
    if (i < total) {
        float v = x[i];
        __nv_bfloat16 h = __float2bfloat16(v);
        xh[i] = h;
        xl[i] = __float2bfloat16(v - __bfloat162float(h));
    }
}

// ---------------------------------------------------------------------------
// edge combine: act1 = lrelu( rbf@Wr2 + p[src] + q[dst] + cz ) -> bf16 hi/lo
// ---------------------------------------------------------------------------
__global__ __launch_bounds__(256, 2) void edge_combine(
    const float* __restrict__ dists, const float* __restrict__ freq,
    const float* __restrict__ wr2, const float* __restrict__ p,
    const float* __restrict__ q, const float* __restrict__ cz,
    const int* __restrict__ edge_index,
    __nv_bfloat16* __restrict__ a1h, __nv_bfloat16* __restrict__ a1l, int E) {
    __shared__ float Rs[64 * 33];
    __shared__ float Bs[32 * 256];
    __shared__ float s_freq[32];
    __shared__ float s_cz[256];
    __shared__ int s_src[64], s_dst[64];
    int tid = threadIdx.x, tx = tid & 15, ty = tid >> 4;
    int e0 = blockIdx.x * 64;
    if (tid < 32) s_freq[tid] = freq[tid];
    s_cz[tid] = cz[tid];
    if (tid < 64) {
        int e = e0 + tid;
        s_src[tid] = (e < E) ? edge_index[e] : 0;
        s_dst[tid] = (e < E) ? edge_index[E + e] : 0;
    }
#pragma unroll
    for (int i = 0; i < 32; i++) Bs[i * 256 + tid] = wr2[i * 256 + tid];
    __syncthreads();
#pragma unroll
    for (int i = 0; i < 8; i++) {
        int idx = tid + i * 256, el = idx >> 5, r = idx & 31;
        int e = e0 + el;
        float d = (e < E) ? dists[e] * 0.2f : 1.0f;
        float d2 = d * d, d5 = d2 * d2 * d;
        float env = 1.0f / d + d5 * (-28.0f + d * (48.0f + d * (-21.0f)));
        Rs[el * 33 + r] = env * sinf(s_freq[r] * d);
    }
    __syncthreads();
    float acc[4][16];
#pragma unroll
    for (int i = 0; i < 4; i++)
#pragma unroll
        for (int j = 0; j < 16; j++) acc[i][j] = 0.0f;
#pragma unroll
    for (int kk = 0; kk < 32; kk++) {
        float a[4];
#pragma unroll
        for (int i = 0; i < 4; i++) a[i] = Rs[(ty * 4 + i) * 33 + kk];
#pragma unroll
        for (int j = 0; j < 16; j++) {
            float b = Bs[kk * 256 + tx + 16 * j];
#pragma unroll
            for (int i = 0; i < 4; i++) acc[i][j] = fmaf(a[i], b, acc[i][j]);
        }
    }
#pragma unroll
    for (int i = 0; i < 4; i++) {
        int r = ty * 4 + i;
        int e = e0 + r;
        if (e < E) {
            const float* prow = p + (size_t)s_src[r] * 256;
            const float* qrow = q + (size_t)s_dst[r] * 256;
#pragma unroll
            for (int j = 0; j < 16; j++) {
                int col = tx + 16 * j;
                float v = acc[i][j] + prow[col] + qrow[col] + s_cz[col];
                v = lrelu_f(v);
                __nv_bfloat16 h = __float2bfloat16(v);
                a1h[(size_t)e * 256 + col] = h;
                a1l[(size_t)e * 256 + col] = __float2bfloat16(v - __bfloat162float(h));
            }
        }
    }
}

// ---------------------------------------------------------------------------
// HMMA fused edge MLP (layers 2..4) — unchanged from R12 (validated).
// ---------------------------------------------------------------------------
__global__ __launch_bounds__(512, 1) void edge_mlp_hmma(
    const __nv_bfloat16* __restrict__ a1h, const __nv_bfloat16* __restrict__ a1l,
    const int* __restrict__ edge_index, const __nv_bfloat16* __restrict__ wt,
    const float* __restrict__ b2, const float* __restrict__ b3,
    const float* __restrict__ b4, float* __restrict__ agg, int E) {
    extern __shared__ __align__(16) char dsm[];
    __shared__ int s_dst[128];
    __shared__ float s_bias[768];

    const int tid = threadIdx.x;
    const int wid = tid >> 5, lane = tid & 31;
    const int wm = wid >> 2, wn = wid & 3;
    const int r0 = wm * 32;
    const int c0 = wn * 64;
    const int gtid = lane + wm * 32;
    const int e0 = blockIdx.x * 128;
    const uint32_t sb = smem_u32(dsm);

    for (int i = tid; i < 768; i += 512) {
        const float* b = (i < 256) ? b2 : (i < 512) ? b3 : b4;
        s_bias[i] = b[i & 255];
    }
    if (tid < 128) {
        int e = e0 + tid;
        s_dst[tid] = (e < E) ? edge_index[E + e] : 0;
    }

    float acc[2][8][4];
#pragma unroll
    for (int mt = 0; mt < 2; mt++)
#pragma unroll
        for (int nt = 0; nt < 8; nt++)
#pragma unroll
            for (int i = 0; i < 4; i++) acc[mt][nt][i] = 0.0f;

    auto groupbar = [&]() {
        asm volatile("bar.sync %0, 128;" :: "r"(1 + wn) : "memory");
    };
    auto prefetchB = [&](int t, int buf) {
        const char* wsrc = (const char*)wt + (size_t)t * 32768;
        uint32_t dbase = sb + BBUF + buf * 40960;
#pragma unroll
        for (int it = 0; it < 4; it++) {
            int id = gtid + it * 128;
            int hl = id >> 8;
            int rest = id & 255;
            int nl = rest >> 2, seg = rest & 3;
            int n = c0 + nl;
            cp_async16(dbase + hl * 20480 + (uint32_t)n * 80 + seg * 16,
                       wsrc + hl * 16384 + (size_t)n * 64 + seg * 16);
        }
    };
    auto loadACT = [&]() {
#pragma unroll
        for (int it = 0; it < 16; it++) {
            int id = tid + it * 512;
            int seg = id & 31;
            int hl = (id >> 5) & 1;
            int row = id >> 6;
            int e = e0 + row;
            if (e >= E) e = E - 1;
            const char* sp = (const char*)(hl ? a1l : a1h) + (size_t)e * 512 + seg * 16;
            cp_async16(sb + (hl ? ACT_LO : ACT_HI) + (uint32_t)row * 528 + seg * 16, sp);
        }
    };
    auto compute = [&](uint32_t abase, uint32_t bbase) {
#pragma unroll
        for (int s = 0; s < 2; s++) {
            int ko2 = s * 32;
            uint32_t ah[2][4], al[2][4];
#pragma unroll
            for (int mt = 0; mt < 2; mt++) {
                uint32_t ad = abase + (uint32_t)(r0 + mt * 16 + (lane & 15)) * 528 +
                              ko2 + ((lane >> 4) << 4);
                ldsm4(ah[mt], ad);
                ldsm4(al[mt], ad + (ACT_LO - ACT_HI));
            }
#pragma unroll
            for (int q = 0; q < 4; q++) {
                int n = c0 + q * 16 + (lane & 7) + ((lane & 16) >> 1);
                uint32_t bd = bbase + (uint32_t)n * 80 + ko2 + ((lane & 8) << 1);
                uint32_t bh[4], bl[4];
                ldsm4(bh, bd);
                ldsm4(bl, bd + 20480);
#pragma unroll
                for (int mt = 0; mt < 2; mt++) {
                    mma16816(acc[mt][2 * q + 0], ah[mt], bh[0], bh[1]);
                    mma16816(acc[mt][2 * q + 1], ah[mt], bh[2], bh[3]);
                    mma16816(acc[mt][2 * q + 0], al[mt], bh[0], bh[1]);
                    mma16816(acc[mt][2 * q + 1], al[mt], bh[2], bh[3]);
                    mma16816(acc[mt][2 * q + 0], ah[mt], bl[0], bl[1]);
                    mma16816(acc[mt][2 * q + 1], ah[mt], bl[2], bl[3]);
                }
            }
        }
    };
    auto epilogue_act = [&](int bidx) {
#pragma unroll
        for (int mt = 0; mt < 2; mt++) {
#pragma unroll
            for (int nt = 0; nt < 8; nt++) {
                int ra = r0 + mt * 16 + (lane >> 2);
                int ca = c0 + nt * 8 + 2 * (lane & 3);
                float bv0 = s_bias[bidx * 256 + ca], bv1 = s_bias[bidx * 256 + ca + 1];
#pragma unroll
                for (int half = 0; half < 2; half++) {
                    int r = ra + half * 8;
                    float v0 = lrelu_f(acc[mt][nt][half * 2 + 0] + bv0);
                    float v1 = lrelu_f(acc[mt][nt][half * 2 + 1] + bv1);
                    __nv_bfloat16 h0 = __float2bfloat16(v0);
                    __nv_bfloat16 h1 = __float2bfloat16(v1);
                    __nv_bfloat162 hp; hp.x = h0; hp.y = h1;
                    __nv_bfloat162 lp;
                    lp.x = __float2bfloat16(v0 - __bfloat162float(h0));
                    lp.y = __float2bfloat16(v1 - __bfloat162float(h1));
                    uint32_t off = (uint32_t)r * 528 + (uint32_t)ca * 2;
                    *(__nv_bfloat162*)(dsm + ACT_HI + off) = hp;
                    *(__nv_bfloat162*)(dsm + ACT_LO + off) = lp;
                    acc[mt][nt][half * 2 + 0] = 0.0f;
                    acc[mt][nt][half * 2 + 1] = 0.0f;
                }
            }
        }
    };

    loadACT();
    prefetchB(0, 0);
    CP_COMMIT();
    prefetchB(1, 1);
    CP_COMMIT();

    for (int g = 0; g < 24; g++) {
        if (g < 23) { CP_WAIT1(); } else { CP_WAIT0(); }
        if (g == 0 || g == 8 || g == 16) __syncthreads();
        else groupbar();
        compute(sb + ACT_HI + (uint32_t)(g & 7) * 64, sb + BBUF + (g & 1) * 40960);
        if (g + 2 < 24) {
            groupbar();
            prefetchB(g + 2, g & 1);
            CP_COMMIT();
        }
        if (g == 7 || g == 15) {
            __syncthreads();
            epilogue_act(g >> 3);
        } else if (g == 23) {
            __syncthreads();
#pragma unroll
            for (int mt = 0; mt < 2; mt++) {
#pragma unroll
                for (int nt = 0; nt < 8; nt++) {
                    int ra = r0 + mt * 16 + (lane >> 2);
                    int ca = c0 + nt * 8 + 2 * (lane & 3);
                    float bv0 = s_bias[512 + ca], bv1 = s_bias[512 + ca + 1];
#pragma unroll
                    for (int half = 0; half < 2; half++) {
                        int r = ra + half * 8;
                        float2 v;
                        v.x = acc[mt][nt][half * 2 + 0] + bv0;
                        v.y = acc[mt][nt][half * 2 + 1] + bv1;
                        *(float2*)(dsm + (uint32_t)r * 1024 + (uint32_t)ca * 4) = v;
                    }
                }
            }
            FENCE_ASYNC();
            __syncthreads();
            if (tid < 128 && (e0 + tid) < E) {
                bulk_reduce_add_f32(agg + (size_t)s_dst[tid] * 256,
                                    sb + (uint32_t)tid * 1024, 1024);
            }
            BULK_COMMIT();
            BULK_WAIT0();
        }
    }
}

// ---------------------------------------------------------------------------
// Node HMMA GEMM: C[rows,256] = act(A@W + bias) + res, A = hi/lo bf16 arrays,
// W = wt tiles (tb + 0..7). blockIdx.y selects (tb1, C1). Same 16-warp / named-
// barrier pipeline as the edge kernel. Optional fp32 C, optional hi/lo C out,
// optional zbuf zeroing (y==0 blocks).
// ---------------------------------------------------------------------------
__global__ __launch_bounds__(512, 1) void node_hmma(
    const __nv_bfloat16* __restrict__ Ah, const __nv_bfloat16* __restrict__ Al,
    const __nv_bfloat16* __restrict__ wt, int tb0, int tb1,
    const float* __restrict__ bias, const float* __restrict__ res,
    float* __restrict__ C0, float* __restrict__ C1,
    __nv_bfloat16* __restrict__ Ch, __nv_bfloat16* __restrict__ Cl,
    float* __restrict__ zbuf, int rows, int act) {
    extern __shared__ __align__(16) char dsm[];
    const int tid = threadIdx.x;
    const int wid = tid >> 5, lane = tid & 31;
    const int wm = wid >> 2, wn = wid & 3;
    const int r0 = wm * 32;
    const int c0 = wn * 64;
    const int gtid = lane + wm * 32;
    const int e0 = blockIdx.x * 128;
    const uint32_t sb = smem_u32(dsm);
    const int tb = blockIdx.y ? tb1 : tb0;
    float* C = blockIdx.y ? C1 : C0;
    if (e0 >= rows) return;

    float acc[2][8][4];
#pragma unroll
    for (int mt = 0; mt < 2; mt++)
#pragma unroll
        for (int nt = 0; nt < 8; nt++)
#pragma unroll
            for (int i = 0; i < 4; i++) acc[mt][nt][i] = 0.0f;

    auto groupbar = [&]() {
        asm volatile("bar.sync %0, 128;" :: "r"(1 + wn) : "memory");
    };
    auto prefetchB = [&](int t, int buf) {
        const char* wsrc = (const char*)wt + (size_t)(tb + t) * 32768;
        uint32_t dbase = sb + BBUF + buf * 40960;
#pragma unroll
        for (int it = 0; it < 4; it++) {
            int id = gtid + it * 128;
            int hl = id >> 8;
            int rest = id & 255;
            int nl = rest >> 2, seg = rest & 3;
            int n = c0 + nl;
            cp_async16(dbase + hl * 20480 + (uint32_t)n * 80 + seg * 16,
                       wsrc + hl * 16384 + (size_t)n * 64 + seg * 16);
        }
    };
    auto loadACT = [&]() {
#pragma unroll
        for (int it = 0; it < 16; it++) {
            int id = tid + it * 512;
            int seg = id & 31;
            int hl = (id >> 5) & 1;
            int row = id >> 6;
            int e = e0 + row;
            if (e >= rows) e = rows - 1;
            const char* sp = (const char*)(hl ? Al : Ah) + (size_t)e * 512 + seg * 16;
            cp_async16(sb + (hl ? ACT_LO : ACT_HI) + (uint32_t)row * 528 + seg * 16, sp);
        }
    };
    auto compute = [&](uint32_t abase, uint32_t bbase) {
#pragma unroll
        for (int s = 0; s < 2; s++) {
            int ko2 = s * 32;
            uint32_t ah[2][4], al[2][4];
#pragma unroll
            for (int mt = 0; mt < 2; mt++) {
                uint32_t ad = abase + (uint32_t)(r0 + mt * 16 + (lane & 15)) * 528 +
                              ko2 + ((lane >> 4) << 4);
                ldsm4(ah[mt], ad);
                ldsm4(al[mt], ad + (ACT_LO - ACT_HI));
            }
#pragma unroll
            for (int q = 0; q < 4; q++) {
                int n = c0 + q * 16 + (lane & 7) + ((lane & 16) >> 1);
                uint32_t bd = bbase + (uint32_t)n * 80 + ko2 + ((lane & 8) << 1);
                uint32_t bh[4], bl[4];
                ldsm4(bh, bd);
                ldsm4(bl, bd + 20480);
#pragma unroll
                for (int mt = 0; mt < 2; mt++) {
                    mma16816(acc[mt][2 * q + 0], ah[mt], bh[0], bh[1]);
                    mma16816(acc[mt][2 * q + 1], ah[mt], bh[2], bh[3]);
                    mma16816(acc[mt][2 * q + 0], al[mt], bh[0], bh[1]);
                    mma16816(acc[mt][2 * q + 1], al[mt], bh[2], bh[3]);
                    mma16816(acc[mt][2 * q + 0], ah[mt], bl[0], bl[1]);
                    mma16816(acc[mt][2 * q + 1], ah[mt], bl[2], bl[3]);
                }
            }
        }
    };

    loadACT();
    prefetchB(0, 0);
    CP_COMMIT();
    prefetchB(1, 1);
    CP_COMMIT();

    // zero agg rows while loads fly (pq launch, y==0 only)
    if (zbuf && blockIdx.y == 0) {
#pragma unroll
        for (int it = 0; it < 16; it++) {
            int id = tid + it * 512;     // 0..8191 float4 slots
            int row = id >> 6;
            int e = e0 + row;
            if (e < rows) {
                float4 z = {0.0f, 0.0f, 0.0f, 0.0f};
                *(float4*)(zbuf + (size_t)e * 256 + (id & 63) * 4) = z;
            }
        }
    }

    for (int g = 0; g < 8; g++) {
        if (g < 7) { CP_WAIT1(); } else { CP_WAIT0(); }
        if (g == 0) __syncthreads();
        else groupbar();
        compute(sb + ACT_HI + (uint32_t)g * 64, sb + BBUF + (g & 1) * 40960);
        if (g + 2 < 8) {
            groupbar();
            prefetchB(g + 2, g & 1);
            CP_COMMIT();
        }
    }

    // epilogue -> global
#pragma unroll
    for (int mt = 0; mt < 2; mt++) {
#pragma unroll
        for (int nt = 0; nt < 8; nt++) {
            int ra = r0 + mt * 16 + (lane >> 2);
            int ca = c0 + nt * 8 + 2 * (lane & 3);
            float bv0 = bias ? __ldg(bias + ca) : 0.0f;
            float bv1 = bias ? __ldg(bias + ca + 1) : 0.0f;
#pragma unroll
            for (int half = 0; half < 2; half++) {
                int r = e0 + ra + half * 8;
                if (r < rows) {
                    float v0 = acc[mt][nt][half * 2 + 0] + bv0;
                    float v1 = acc[mt][nt][half * 2 + 1] + bv1;
                    if (act == 1) { v0 = gelu_f(v0); v1 = gelu_f(v1); }
                    if (res) {
                        float2 rv = *(const float2*)(res + (size_t)r * 256 + ca);
                        v0 += rv.x; v1 += rv.y;
                    }
                    if (C) {
                        float2 o; o.x = v0; o.y = v1;
                        *(float2*)(C + (size_t)r * 256 + ca) = o;
                    }
                    if (Ch) {
                        __nv_bfloat16 h0 = __float2bfloat16(v0);
                        __nv_bfloat16 h1 = __float2bfloat16(v1);
                        __nv_bfloat162 hp; hp.x = h0; hp.y = h1;
                        __nv_bfloat162 lp;
                        lp.x = __float2bfloat16(v0 - __bfloat162float(h0));
                        lp.y = __float2bfloat16(v1 - __bfloat162float(h1));
                        *(__nv_bfloat162*)(Ch + (size_t)r * 256 + ca) = hp;
                        *(__nv_bfloat162*)(Cl + (size_t)r * 256 + ca) = lp;
                    }
                }
            }
        }
    }
}

// ---------------------------------------------------------------------------
extern "C" void kernel_launch(void* const* d_in, const int* in_sizes, int n_in,
                              void* d_out, int out_size) {
    const int* atom_types = (const int*)d_in[0];
    const float* x_extra = (const float*)d_in[1];
    const int* edge_index = (const int*)d_in[2];
    const float* dists = (const float*)d_in[3];
    const float* freq = (const float*)d_in[4];
    const float* emb_table = (const float*)d_in[5];
    const float* w_emb = (const float*)d_in[6];
    const float* b_emb = (const float*)d_in[7];
    const float* w_n2m = (const float*)d_in[8];
    const float* b_n2m = (const float*)d_in[9];
    const float* w_r2m = (const float*)d_in[10];
    const float* b_r2m = (const float*)d_in[11];
    const float* w_m2n = (const float*)d_in[12];
    const float* mw1 = (const float*)d_in[13];
    const float* mb1 = (const float*)d_in[14];
    const float* mw2 = (const float*)d_in[15];
    const float* mb2 = (const float*)d_in[16];
    const float* mw3 = (const float*)d_in[17];
    const float* mb3 = (const float*)d_in[18];
    const float* mw4 = (const float*)d_in[19];
    const float* mb4 = (const float*)d_in[20];
    const float* fw1 = (const float*)d_in[21];
    const float* fb1 = (const float*)d_in[22];
    const float* fw2 = (const float*)d_in[23];
    const float* fb2 = (const float*)d_in[24];
    float* out = (float*)d_out;

    int N = in_sizes[0];
    int E = in_sizes[2] / 2;

    float *p_h, *p_p, *p_q, *p_agg, *p_t, *p_wr2, *p_cz;
    __nv_bfloat16 *p_hh, *p_hl, *p_aggh, *p_aggl, *p_th, *p_tl, *p_uh, *p_ul;
    __nv_bfloat16 *p_a1h, *p_a1l, *p_wt;
    cudaGetSymbolAddress((void**)&p_h, g_h);
    cudaGetSymbolAddress((void**)&p_p, g_p);
    cudaGetSymbolAddress((void**)&p_q, g_q);
    cudaGetSymbolAddress((void**)&p_agg, g_agg);
    cudaGetSymbolAddress((void**)&p_t, g_t);
    cudaGetSymbolAddress((void**)&p_wr2, g_wr2);
    cudaGetSymbolAddress((void**)&p_cz, g_cz);
    cudaGetSymbolAddress((void**)&p_hh, g_hh);
    cudaGetSymbolAddress((void**)&p_hl, g_hl);
    cudaGetSymbolAddress((void**)&p_aggh, g_aggh);
    cudaGetSymbolAddress((void**)&p_aggl, g_aggl);
    cudaGetSymbolAddress((void**)&p_th, g_th);
    cudaGetSymbolAddress((void**)&p_tl, g_tl);
    cudaGetSymbolAddress((void**)&p_uh, g_uh);
    cudaGetSymbolAddress((void**)&p_ul, g_ul);
    cudaGetSymbolAddress((void**)&p_a1h, g_a1h);
    cudaGetSymbolAddress((void**)&p_a1l, g_a1l);
    cudaGetSymbolAddress((void**)&p_wt, g_wt);

    cudaFuncSetAttribute(edge_mlp_hmma, cudaFuncAttributeMaxDynamicSharedMemorySize, DSMEM);
    cudaFuncSetAttribute(node_hmma, cudaFuncAttributeMaxDynamicSharedMemorySize, DSMEM);

    dim3 gMega((N + 63) / 64, 2, 5);
    int gE64 = (E + 63) / 64;
    int gE128 = (E + 127) / 128;
    int gNode = (N + 127) / 128;
    dim3 gPQ(gNode, 2);
    dim3 gN1(gNode, 1);

    // 0: h (+hi/lo) + fold tiles (wpa/wqb) + wr2 + static tiles + cz
    k0_mega<<<gMega, 256>>>(atom_types, x_extra, emb_table, w_emb, b_emb,
                            w_n2m, b_n2m, w_r2m, b_r2m, mw1, mb1, mw2, mw3, mw4,
                            w_m2n, fw1, fw2, p_h, p_hh, p_hl, p_wr2, p_cz, p_wt, N);
    // 1: p & q via HMMA (+ zero agg)
    node_hmma<<<gPQ, 512, DSMEM>>>(p_hh, p_hl, p_wt, 48, 56, nullptr, nullptr,
                                   p_p, p_q, nullptr, nullptr, p_agg, N, 0);
    // 2: edge combine -> a1 hi/lo
    edge_combine<<<gE64, 256>>>(dists, freq, p_wr2, p_p, p_q, p_cz, edge_index,
                                p_a1h, p_a1l, E);
    // 3: fused edge MLP
    edge_mlp_hmma<<<gE128, 512, DSMEM>>>(p_a1h, p_a1l, edge_index, p_wt,
                                         mb2, mb3, mb4, p_agg, E);
    // 4: agg -> hi/lo
    conv_hilo<<<(N * 256 + 255) / 256, 256>>>(p_agg, p_aggh, p_aggl, N * 256);
    // 5: t = agg@w_m2n + h   (+ t hi/lo)
    node_hmma<<<gN1, 512, DSMEM>>>(p_aggh, p_aggl, p_wt, 24, 24, nullptr, p_h,
                                   p_t, nullptr, p_th, p_tl, nullptr, N, 0);
    // 6: u = gelu(t@fw1 + fb1)  (hi/lo only)
    node_hmma<<<gN1, 512, DSMEM>>>(p_th, p_tl, p_wt, 32, 32, fb1, nullptr,
                                   nullptr, nullptr, p_uh, p_ul, nullptr, N, 1);
    // 7: out = u@fw2 + fb2 + t
    node_hmma<<<gN1, 512, DSMEM>>>(p_uh, p_ul, p_wt, 40, 40, fb2, p_t,
                                   out, nullptr, nullptr, nullptr, nullptr, N, 0);
}

// round 14
// speedup vs baseline: 1.7513x; 1.1965x over previous
#include <cuda_runtime.h>
#include <cuda_bf16.h>
#include <cuda_fp16.h>
#include <math.h>
#include <stdint.h>

#define NN 10000
#define EE 160000
#define HH 256

// ---------------------------------------------------------------------------
// Scratch (no runtime allocation allowed)
// ---------------------------------------------------------------------------
__device__ float g_h[NN * HH];
__device__ float g_p[NN * HH];
__device__ float g_q[NN * HH];
__device__ float g_agg[NN * HH];
__device__ float g_t[NN * HH];
__device__ float g_wr2[32 * 256];
__device__ float g_cz[256];
__device__ __nv_bfloat16 g_hh[NN * HH], g_hl[NN * HH];
__device__ __nv_bfloat16 g_aggh[NN * HH], g_aggl[NN * HH];
__device__ __nv_bfloat16 g_th[NN * HH], g_tl[NN * HH];
__device__ __nv_bfloat16 g_uh[NN * HH], g_ul[NN * HH];
// act1 hi/lo fp16, [E, 256]
__device__ __half g_a1h[(size_t)EE * HH];
__device__ __half g_a1l[(size_t)EE * HH];
// Node-path W^T tiles, bf16 hi/lo (16384 bf16 each = hi 8192 + lo 8192):
// 24..31 w_m2n | 32..39 fw1 | 40..47 fw2 | 48..55 wpa | 56..63 wqb
__device__ __align__(16) __nv_bfloat16 g_wt[64 * 16384];
// Edge-path W^T tiles, fp16 SINGLE (8192 half each): 0..7 W2 | 8..15 W3 | 16..23 W4
__device__ __align__(16) __half g_wte[24 * 8192];

__device__ __forceinline__ float gelu_f(float x) {
    float x3 = x * x * x;
    return 0.5f * x * (1.0f + tanhf(0.7978845608028654f * (x + 0.044715f * x3)));
}
__device__ __forceinline__ float lrelu_f(float x) { return x > 0.0f ? x : 0.01f * x; }

// ---------------------------------------------------------------------------
// PTX helpers (sm_80/sm_90 base ISA: valid at .target sm_100)
// ---------------------------------------------------------------------------
__device__ __forceinline__ uint32_t smem_u32(const void* p) {
    uint32_t a;
    asm("{ .reg .u64 t; cvta.to.shared.u64 t, %1; cvt.u32.u64 %0, t; }" : "=r"(a) : "l"(p));
    return a;
}
__device__ __forceinline__ void cp_async16(uint32_t smem_addr, const void* gptr) {
    asm volatile("cp.async.cg.shared.global [%0], [%1], 16;\n" :: "r"(smem_addr), "l"(gptr));
}
#define CP_COMMIT() asm volatile("cp.async.commit_group;\n" ::: "memory")
#define CP_WAIT0()  asm volatile("cp.async.wait_group 0;\n" ::: "memory")
#define CP_WAIT1()  asm volatile("cp.async.wait_group 1;\n" ::: "memory")

__device__ __forceinline__ void bulk_reduce_add_f32(void* gdst, uint32_t ssrc, uint32_t bytes) {
    asm volatile("cp.reduce.async.bulk.global.shared::cta.bulk_group.add.f32 [%0], [%1], %2;\n"
                 :: "l"(gdst), "r"(ssrc), "r"(bytes) : "memory");
}
#define BULK_COMMIT() asm volatile("cp.async.bulk.commit_group;" ::: "memory")
#define BULK_WAIT0()  asm volatile("cp.async.bulk.wait_group 0;" ::: "memory")
#define FENCE_ASYNC() asm volatile("fence.proxy.async.shared::cta;" ::: "memory")

__device__ __forceinline__ void ldsm4(uint32_t* f, uint32_t a) {
    asm volatile("ldmatrix.sync.aligned.m8n8.x4.shared.b16 {%0,%1,%2,%3}, [%4];\n"
                 : "=r"(f[0]), "=r"(f[1]), "=r"(f[2]), "=r"(f[3]) : "r"(a));
}
// bf16 MMA (node path)
__device__ __forceinline__ void mma16816(float* d, const uint32_t* a, uint32_t b0, uint32_t b1) {
    asm volatile(
        "mma.sync.aligned.m16n8k16.row.col.f32.bf16.bf16.f32 "
        "{%0,%1,%2,%3}, {%4,%5,%6,%7}, {%8,%9}, {%0,%1,%2,%3};\n"
        : "+f"(d[0]), "+f"(d[1]), "+f"(d[2]), "+f"(d[3])
        : "r"(a[0]), "r"(a[1]), "r"(a[2]), "r"(a[3]), "r"(b0), "r"(b1));
}
// fp16 MMA (edge path)
__device__ __forceinline__ void mma16816h(float* d, const uint32_t* a, uint32_t b0, uint32_t b1) {
    asm volatile(
        "mma.sync.aligned.m16n8k16.row.col.f32.f16.f16.f32 "
        "{%0,%1,%2,%3}, {%4,%5,%6,%7}, {%8,%9}, {%0,%1,%2,%3};\n"
        : "+f"(d[0]), "+f"(d[1]), "+f"(d[2]), "+f"(d[3])
        : "r"(a[0]), "r"(a[1]), "r"(a[2]), "r"(a[3]), "r"(b0), "r"(b1));
}

// SMEM layout
#define ACT_HI 0
#define ACT_LO 67584
#define BBUF   135168
#define DSMEM_N 217088            // node kernel (bf16 hi/lo B: 2 x 40960)
#define DSMEM_E (135168 + 40960)  // edge kernel (fp16 single B: 2 x 20480)

// ---------------------------------------------------------------------------
// Mega kernel 0:
//   z=0 -> h = gelu(xcat@w_emb+b) (gathered) + h hi/lo
//   z=1 -> wpa fold -> wt tiles 48..55 ; z=2 -> wqb fold -> 56..63
//   z=3 -> wr2 = w_r2m @ mw1c (rows=32, fp32)
//   z=4 -> flat prep: wte fp16 tiles (W2/3/4), wt bf16 tiles (m2n/fw1/fw2), cz
// ---------------------------------------------------------------------------
__global__ __launch_bounds__(256, 2) void k0_mega(
    const int* __restrict__ atom_types, const float* __restrict__ x_extra,
    const float* __restrict__ emb_table,
    const float* __restrict__ w_emb, const float* __restrict__ b_emb,
    const float* __restrict__ w_n2m, const float* __restrict__ b_n2m,
    const float* __restrict__ w_r2m, const float* __restrict__ b_r2m,
    const float* __restrict__ mw1, const float* __restrict__ mb1,
    const float* __restrict__ mw2, const float* __restrict__ mw3,
    const float* __restrict__ mw4, const float* __restrict__ w_m2n,
    const float* __restrict__ fw1, const float* __restrict__ fw2,
    float* __restrict__ h, __nv_bfloat16* __restrict__ hh, __nv_bfloat16* __restrict__ hl,
    float* __restrict__ wr2, float* __restrict__ cz,
    __nv_bfloat16* __restrict__ wt, __half* __restrict__ wte, int N) {
    int z = blockIdx.z;
    if (z == 4) {
        // [0,196608) W2/3/4 fp16 single; [196608,393216) m2n/fw1/fw2 bf16 hi/lo; cz
        int bid = blockIdx.x * 2 + blockIdx.y;
        int flat = bid * 256 + (int)threadIdx.x;     // stride 80384
        for (int item = flat; item < 393472; item += 80384) {
            if (item < 196608) {
                int kg = item >> 8, n = item & 255;
                const float* w; int kl, t;
                if (kg < 256)      { w = mw2; kl = kg;       t = (kl >> 5); }
                else if (kg < 512) { w = mw3; kl = kg - 256; t = 8 + (kl >> 5); }
                else               { w = mw4; kl = kg - 512; t = 16 + (kl >> 5); }
                int kk = kl & 31;
                wte[(size_t)t * 8192 + n * 32 + kk] = __float2half(w[(long)kl * 256 + n]);
            } else if (item < 393216) {
                int it2 = item - 196608;
                int kg = it2 >> 8, n = it2 & 255;
                const float* w; int kl, t;
                if (kg < 256)      { w = w_m2n; kl = kg;       t = 24 + (kl >> 5); }
                else if (kg < 512) { w = fw1;   kl = kg - 256; t = 32 + (kl >> 5); }
                else               { w = fw2;   kl = kg - 512; t = 40 + (kl >> 5); }
                int kk = kl & 31;
                float v = w[(long)kl * 256 + n];
                __nv_bfloat16 vh = __float2bfloat16(v);
                __nv_bfloat16 vl = __float2bfloat16(v - __bfloat162float(vh));
                size_t base = (size_t)t * 16384 + n * 32 + kk;
                wt[base] = vh;
                wt[base + 8192] = vl;
            } else {
                int n = item - 393216;
                float s = mb1[n];
                for (int k = 0; k < 256; k++) {
                    s += b_n2m[k] * (mw1[(long)k * 256 + n] + mw1[(long)(256 + k) * 256 + n]);
                    s += b_r2m[k] * mw1[(long)(512 + k) * 256 + n];
                }
                cz[n] = s;
            }
        }
        return;
    }

    // ---- GEMM path ----
    __shared__ float As[64 * 33];
    __shared__ float Bs[32 * 132];
    const float* A = nullptr;
    const float* W;
    const float* bias = nullptr;
    int K, rows, act = 0, foldt = -1;
    bool gather = false;
    if (z == 0)      { gather = true; K = 48; W = w_emb; bias = b_emb; rows = N; act = 1; }
    else if (z == 1) { A = w_n2m; K = 256; W = mw1;          rows = 256; foldt = 48; }
    else if (z == 2) { A = w_n2m; K = 256; W = mw1 + 65536;  rows = 256; foldt = 56; }
    else             { A = w_r2m; K = 256; W = mw1 + 131072; rows = 32; }

    int tid = threadIdx.x, tx = tid & 15, ty = tid >> 4;
    int row0 = blockIdx.x * 64;
    int col0 = blockIdx.y * 128;
    if (row0 >= rows) return;

    float acc[4][8];
#pragma unroll
    for (int i = 0; i < 4; i++)
#pragma unroll
        for (int j = 0; j < 8; j++) acc[i][j] = 0.0f;
    for (int k0 = 0; k0 < K; k0 += 32) {
#pragma unroll
        for (int i = 0; i < 8; i++) {
            int idx = tid + i * 256, r = idx >> 5, c = idx & 31;
            int gr = row0 + r, gk = k0 + c;
            float v = 0.0f;
            if (gr < rows && gk < K) {
                if (gather)
                    v = (gk < 32) ? emb_table[atom_types[gr] * 32 + gk]
                                  : x_extra[gr * 16 + gk - 32];
                else
                    v = A[(long)gr * K + gk];
            }
            As[r * 33 + c] = v;
        }
#pragma unroll
        for (int i = 0; i < 16; i++) {
            int idx = tid + i * 256, r = idx >> 7, c = idx & 127;
            int gk = k0 + r;
            Bs[r * 132 + c] = (gk < K) ? W[(long)gk * 256 + col0 + c] : 0.0f;
        }
        __syncthreads();
#pragma unroll
        for (int kk = 0; kk < 32; kk++) {
            float a[4];
#pragma unroll
            for (int i = 0; i < 4; i++) a[i] = As[(ty * 4 + i) * 33 + kk];
#pragma unroll
            for (int j = 0; j < 8; j++) {
                float b = Bs[kk * 132 + tx + 16 * j];
#pragma unroll
                for (int i = 0; i < 4; i++) acc[i][j] = fmaf(a[i], b, acc[i][j]);
            }
        }
        __syncthreads();
    }
#pragma unroll
    for (int i = 0; i < 4; i++) {
        int r = row0 + ty * 4 + i;
        if (r < rows) {
#pragma unroll
            for (int j = 0; j < 8; j++) {
                int col = col0 + tx + 16 * j;
                float v = acc[i][j];
                if (bias) v += bias[col];
                if (act == 1) v = gelu_f(v);
                if (foldt >= 0) {
                    int t = foldt + (r >> 5);
                    size_t base = (size_t)t * 16384 + (size_t)col * 32 + (r & 31);
                    __nv_bfloat16 vh = __float2bfloat16(v);
                    wt[base] = vh;
                    wt[base + 8192] = __float2bfloat16(v - __bfloat162float(vh));
                } else if (z == 0) {
                    h[(long)r * 256 + col] = v;
                    __nv_bfloat16 vh = __float2bfloat16(v);
                    hh[(long)r * 256 + col] = vh;
                    hl[(long)r * 256 + col] = __float2bfloat16(v - __bfloat162float(vh));
                } else {
                    wr2[(long)r * 256 + col] = v;
                }
            }
        }
    }
}

// fp32 -> hi/lo bf16
__global__ void conv_hilo(const float* __restrict__ x, __nv_bfloat16* __restrict__ xh,
                          __nv_bfloat16* __restrict__ xl, int total) {
    int i = blockIdx.x * blockDim.x + threadIdx.x;
    if (i < total) {
        float v = x[i];
        __nv_bfloat16 h = __float2bfloat16(v);
        xh[i] = h;
        xl[i] = __float2bfloat16(v - __bfloat162float(h));
    }
}

// ---------------------------------------------------------------------------
// edge combine: act1 = lrelu( rbf@Wr2 + p[src] + q[dst] + cz ) -> fp16 hi/lo
// ---------------------------------------------------------------------------
__global__ __launch_bounds__(256, 2) void edge_combine(
    const float* __restrict__ dists, const float* __restrict__ freq,
    const float* __restrict__ wr2, const float* __restrict__ p,
    const float* __restrict__ q, const float* __restrict__ cz,
    const int* __restrict__ edge_index,
    __half* __restrict__ a1h, __half* __restrict__ a1l, int E) {
    __shared__ float Rs[64 * 33];
    __shared__ float Bs[32 * 256];
    __shared__ float s_freq[32];
    __shared__ float s_cz[256];
    __shared__ int s_src[64], s_dst[64];
    int tid = threadIdx.x, tx = tid & 15, ty = tid >> 4;
    int e0 = blockIdx.x * 64;
    if (tid < 32) s_freq[tid] = freq[tid];
    s_cz[tid] = cz[tid];
    if (tid < 64) {
        int e = e0 + tid;
        s_src[tid] = (e < E) ? edge_index[e] : 0;
        s_dst[tid] = (e < E) ? edge_index[E + e] : 0;
    }
#pragma unroll
    for (int i = 0; i < 32; i++) Bs[i * 256 + tid] = wr2[i * 256 + tid];
    __syncthreads();
#pragma unroll
    for (int i = 0; i < 8; i++) {
        int idx = tid + i * 256, el = idx >> 5, r = idx & 31;
        int e = e0 + el;
        float d = (e < E) ? dists[e] * 0.2f : 1.0f;
        float d2 = d * d, d5 = d2 * d2 * d;
        float env = 1.0f / d + d5 * (-28.0f + d * (48.0f + d * (-21.0f)));
        Rs[el * 33 + r] = env * sinf(s_freq[r] * d);
    }
    __syncthreads();
    float acc[4][16];
#pragma unroll
    for (int i = 0; i < 4; i++)
#pragma unroll
        for (int j = 0; j < 16; j++) acc[i][j] = 0.0f;
#pragma unroll
    for (int kk = 0; kk < 32; kk++) {
        float a[4];
#pragma unroll
        for (int i = 0; i < 4; i++) a[i] = Rs[(ty * 4 + i) * 33 + kk];
#pragma unroll
        for (int j = 0; j < 16; j++) {
            float b = Bs[kk * 256 + tx + 16 * j];
#pragma unroll
            for (int i = 0; i < 4; i++) acc[i][j] = fmaf(a[i], b, acc[i][j]);
        }
    }
#pragma unroll
    for (int i = 0; i < 4; i++) {
        int r = ty * 4 + i;
        int e = e0 + r;
        if (e < E) {
            const float* prow = p + (size_t)s_src[r] * 256;
            const float* qrow = q + (size_t)s_dst[r] * 256;
#pragma unroll
            for (int j = 0; j < 16; j++) {
                int col = tx + 16 * j;
                float v = acc[i][j] + prow[col] + qrow[col] + s_cz[col];
                v = lrelu_f(v);
                __half h = __float2half(v);
                a1h[(size_t)e * 256 + col] = h;
                a1l[(size_t)e * 256 + col] = __float2half(v - __half2float(h));
            }
        }
    }
}

// ---------------------------------------------------------------------------
// fp16 HMMA fused edge MLP (layers 2..4). CTA = 128 edges x 256 outputs,
// 16 warps, per-SMSP named-barrier pipelines. A = hi/lo fp16, W = single fp16
// -> 2 products (ah*b, al*b), B smem traffic halved.
// SMEM: ACT_HI/LO as before; BBUF = 2 x 20480 (fp16 single, 80B col stride).
// ---------------------------------------------------------------------------
__global__ __launch_bounds__(512, 1) void edge_mlp_hmma(
    const __half* __restrict__ a1h, const __half* __restrict__ a1l,
    const int* __restrict__ edge_index, const __half* __restrict__ wte,
    const float* __restrict__ b2, const float* __restrict__ b3,
    const float* __restrict__ b4, float* __restrict__ agg, int E) {
    extern __shared__ __align__(16) char dsm[];
    __shared__ int s_dst[128];
    __shared__ float s_bias[768];

    const int tid = threadIdx.x;
    const int wid = tid >> 5, lane = tid & 31;
    const int wm = wid >> 2, wn = wid & 3;
    const int r0 = wm * 32;
    const int c0 = wn * 64;
    const int gtid = lane + wm * 32;
    const int e0 = blockIdx.x * 128;
    const uint32_t sb = smem_u32(dsm);

    for (int i = tid; i < 768; i += 512) {
        const float* b = (i < 256) ? b2 : (i < 512) ? b3 : b4;
        s_bias[i] = b[i & 255];
    }
    if (tid < 128) {
        int e = e0 + tid;
        s_dst[tid] = (e < E) ? edge_index[E + e] : 0;
    }

    float acc[2][8][4];
#pragma unroll
    for (int mt = 0; mt < 2; mt++)
#pragma unroll
        for (int nt = 0; nt < 8; nt++)
#pragma unroll
            for (int i = 0; i < 4; i++) acc[mt][nt][i] = 0.0f;

    auto groupbar = [&]() {
        asm volatile("bar.sync %0, 128;" :: "r"(1 + wn) : "memory");
    };
    // group slice: cols [c0,c0+64), each col 64B data (32 half) at 80B stride
    auto prefetchB = [&](int t, int buf) {
        const char* wsrc = (const char*)wte + (size_t)t * 16384;
        uint32_t dbase = sb + BBUF + buf * 20480;
#pragma unroll
        for (int it = 0; it < 2; it++) {
            int id = gtid + it * 128;        // 0..255
            int nl = id >> 2, seg = id & 3;
            int n = c0 + nl;
            cp_async16(dbase + (uint32_t)n * 80 + seg * 16,
                       wsrc + (size_t)n * 64 + seg * 16);
        }
    };
    auto loadACT = [&]() {
#pragma unroll
        for (int it = 0; it < 16; it++) {
            int id = tid + it * 512;
            int seg = id & 31;
            int hl = (id >> 5) & 1;
            int row = id >> 6;
            int e = e0 + row;
            if (e >= E) e = E - 1;
            const char* sp = (const char*)(hl ? a1l : a1h) + (size_t)e * 512 + seg * 16;
            cp_async16(sb + (hl ? ACT_LO : ACT_HI) + (uint32_t)row * 528 + seg * 16, sp);
        }
    };
    auto compute = [&](uint32_t abase, uint32_t bbase) {
#pragma unroll
        for (int s = 0; s < 2; s++) {
            int ko2 = s * 32;
            uint32_t ah[2][4], al[2][4];
#pragma unroll
            for (int mt = 0; mt < 2; mt++) {
                uint32_t ad = abase + (uint32_t)(r0 + mt * 16 + (lane & 15)) * 528 +
                              ko2 + ((lane >> 4) << 4);
                ldsm4(ah[mt], ad);
                ldsm4(al[mt], ad + (ACT_LO - ACT_HI));
            }
#pragma unroll
            for (int q = 0; q < 4; q++) {
                int n = c0 + q * 16 + (lane & 7) + ((lane & 16) >> 1);
                uint32_t bd = bbase + (uint32_t)n * 80 + ko2 + ((lane & 8) << 1);
                uint32_t bh[4];
                ldsm4(bh, bd);
#pragma unroll
                for (int mt = 0; mt < 2; mt++) {
                    mma16816h(acc[mt][2 * q + 0], ah[mt], bh[0], bh[1]);
                    mma16816h(acc[mt][2 * q + 1], ah[mt], bh[2], bh[3]);
                    mma16816h(acc[mt][2 * q + 0], al[mt], bh[0], bh[1]);
                    mma16816h(acc[mt][2 * q + 1], al[mt], bh[2], bh[3]);
                }
            }
        }
    };
    auto epilogue_act = [&](int bidx) {
#pragma unroll
        for (int mt = 0; mt < 2; mt++) {
#pragma unroll
            for (int nt = 0; nt < 8; nt++) {
                int ra = r0 + mt * 16 + (lane >> 2);
                int ca = c0 + nt * 8 + 2 * (lane & 3);
                float bv0 = s_bias[bidx * 256 + ca], bv1 = s_bias[bidx * 256 + ca + 1];
#pragma unroll
                for (int half = 0; half < 2; half++) {
                    int r = ra + half * 8;
                    float v0 = lrelu_f(acc[mt][nt][half * 2 + 0] + bv0);
                    float v1 = lrelu_f(acc[mt][nt][half * 2 + 1] + bv1);
                    __half h0 = __float2half(v0);
                    __half h1 = __float2half(v1);
                    __half2 hp; hp.x = h0; hp.y = h1;
                    __half2 lp;
                    lp.x = __float2half(v0 - __half2float(h0));
                    lp.y = __float2half(v1 - __half2float(h1));
                    uint32_t off = (uint32_t)r * 528 + (uint32_t)ca * 2;
                    *(__half2*)(dsm + ACT_HI + off) = hp;
                    *(__half2*)(dsm + ACT_LO + off) = lp;
                    acc[mt][nt][half * 2 + 0] = 0.0f;
                    acc[mt][nt][half * 2 + 1] = 0.0f;
                }
            }
        }
    };

    loadACT();
    prefetchB(0, 0);
    CP_COMMIT();
    prefetchB(1, 1);
    CP_COMMIT();

    for (int g = 0; g < 24; g++) {
        if (g < 23) { CP_WAIT1(); } else { CP_WAIT0(); }
        if (g == 0 || g == 8 || g == 16) __syncthreads();
        else groupbar();
        compute(sb + ACT_HI + (uint32_t)(g & 7) * 64, sb + BBUF + (g & 1) * 20480);
        if (g + 2 < 24) {
            groupbar();
            prefetchB(g + 2, g & 1);
            CP_COMMIT();
        }
        if (g == 7 || g == 15) {
            __syncthreads();
            epilogue_act(g >> 3);
        } else if (g == 23) {
            __syncthreads();
#pragma unroll
            for (int mt = 0; mt < 2; mt++) {
#pragma unroll
                for (int nt = 0; nt < 8; nt++) {
                    int ra = r0 + mt * 16 + (lane >> 2);
                    int ca = c0 + nt * 8 + 2 * (lane & 3);
                    float bv0 = s_bias[512 + ca], bv1 = s_bias[512 + ca + 1];
#pragma unroll
                    for (int half = 0; half < 2; half++) {
                        int r = ra + half * 8;
                        float2 v;
                        v.x = acc[mt][nt][half * 2 + 0] + bv0;
                        v.y = acc[mt][nt][half * 2 + 1] + bv1;
                        *(float2*)(dsm + (uint32_t)r * 1024 + (uint32_t)ca * 4) = v;
                    }
                }
            }
            FENCE_ASYNC();
            __syncthreads();
            if (tid < 128 && (e0 + tid) < E) {
                bulk_reduce_add_f32(agg + (size_t)s_dst[tid] * 256,
                                    sb + (uint32_t)tid * 1024, 1024);
            }
            BULK_COMMIT();
            BULK_WAIT0();
        }
    }
}

// ---------------------------------------------------------------------------
// Node HMMA GEMM (bf16 3-product, unchanged from R13 — validated).
// ---------------------------------------------------------------------------
__global__ __launch_bounds__(512, 1) void node_hmma(
    const __nv_bfloat16* __restrict__ Ah, const __nv_bfloat16* __restrict__ Al,
    const __nv_bfloat16* __restrict__ wt, int tb0, int tb1,
    const float* __restrict__ bias, const float* __restrict__ res,
    float* __restrict__ C0, float* __restrict__ C1,
    __nv_bfloat16* __restrict__ Ch, __nv_bfloat16* __restrict__ Cl,
    float* __restrict__ zbuf, int rows, int act) {
    extern __shared__ __align__(16) char dsm[];
    const int tid = threadIdx.x;
    const int wid = tid >> 5, lane = tid & 31;
    const int wm = wid >> 2, wn = wid & 3;
    const int r0 = wm * 32;
    const int c0 = wn * 64;
    const int gtid = lane + wm * 32;
    const int e0 = blockIdx.x * 128;
    const uint32_t sb = smem_u32(dsm);
    const int tb = blockIdx.y ? tb1 : tb0;
    float* C = blockIdx.y ? C1 : C0;
    if (e0 >= rows) return;

    float acc[2][8][4];
#pragma unroll
    for (int mt = 0; mt < 2; mt++)
#pragma unroll
        for (int nt = 0; nt < 8; nt++)
#pragma unroll
            for (int i = 0; i < 4; i++) acc[mt][nt][i] = 0.0f;

    auto groupbar = [&]() {
        asm volatile("bar.sync %0, 128;" :: "r"(1 + wn) : "memory");
    };
    auto prefetchB = [&](int t, int buf) {
        const char* wsrc = (const char*)wt + (size_t)(tb + t) * 32768;
        uint32_t dbase = sb + BBUF + buf * 40960;
#pragma unroll
        for (int it = 0; it < 4; it++) {
            int id = gtid + it * 128;
            int hl = id >> 8;
            int rest = id & 255;
            int nl = rest >> 2, seg = rest & 3;
            int n = c0 + nl;
            cp_async16(dbase + hl * 20480 + (uint32_t)n * 80 + seg * 16,
                       wsrc + hl * 16384 + (size_t)n * 64 + seg * 16);
        }
    };
    auto loadACT = [&]() {
#pragma unroll
        for (int it = 0; it < 16; it++) {
            int id = tid + it * 512;
            int seg = id & 31;
            int hl = (id >> 5) & 1;
            int row = id >> 6;
            int e = e0 + row;
            if (e >= rows) e = rows - 1;
            const char* sp = (const char*)(hl ? Al : Ah) + (size_t)e * 512 + seg * 16;
            cp_async16(sb + (hl ? ACT_LO : ACT_HI) + (uint32_t)row * 528 + seg * 16, sp);
        }
    };
    auto compute = [&](uint32_t abase, uint32_t bbase) {
#pragma unroll
        for (int s = 0; s < 2; s++) {
            int ko2 = s * 32;
            uint32_t ah[2][4], al[2][4];
#pragma unroll
            for (int mt = 0; mt < 2; mt++) {
                uint32_t ad = abase + (uint32_t)(r0 + mt * 16 + (lane & 15)) * 528 +
                              ko2 + ((lane >> 4) << 4);
                ldsm4(ah[mt], ad);
                ldsm4(al[mt], ad + (ACT_LO - ACT_HI));
            }
#pragma unroll
            for (int q = 0; q < 4; q++) {
                int n = c0 + q * 16 + (lane & 7) + ((lane & 16) >> 1);
                uint32_t bd = bbase + (uint32_t)n * 80 + ko2 + ((lane & 8) << 1);
                uint32_t bh[4], bl[4];
                ldsm4(bh, bd);
                ldsm4(bl, bd + 20480);
#pragma unroll
                for (int mt = 0; mt < 2; mt++) {
                    mma16816(acc[mt][2 * q + 0], ah[mt], bh[0], bh[1]);
                    mma16816(acc[mt][2 * q + 1], ah[mt], bh[2], bh[3]);
                    mma16816(acc[mt][2 * q + 0], al[mt], bh[0], bh[1]);
                    mma16816(acc[mt][2 * q + 1], al[mt], bh[2], bh[3]);
                    mma16816(acc[mt][2 * q + 0], ah[mt], bl[0], bl[1]);
                    mma16816(acc[mt][2 * q + 1], ah[mt], bl[2], bl[3]);
                }
            }
        }
    };

    loadACT();
    prefetchB(0, 0);
    CP_COMMIT();
    prefetchB(1, 1);
    CP_COMMIT();

    if (zbuf && blockIdx.y == 0) {
#pragma unroll
        for (int it = 0; it < 16; it++) {
            int id = tid + it * 512;
            int row = id >> 6;
            int e = e0 + row;
            if (e < rows) {
                float4 z = {0.0f, 0.0f, 0.0f, 0.0f};
                *(float4*)(zbuf + (size_t)e * 256 + (id & 63) * 4) = z;
            }
        }
    }

    for (int g = 0; g < 8; g++) {
        if (g < 7) { CP_WAIT1(); } else { CP_WAIT0(); }
        if (g == 0) __syncthreads();
        else groupbar();
        compute(sb + ACT_HI + (uint32_t)g * 64, sb + BBUF + (g & 1) * 40960);
        if (g + 2 < 8) {
            groupbar();
            prefetchB(g + 2, g & 1);
            CP_COMMIT();
        }
    }

#pragma unroll
    for (int mt = 0; mt < 2; mt++) {
#pragma unroll
        for (int nt = 0; nt < 8; nt++) {
            int ra = r0 + mt * 16 + (lane >> 2);
            int ca = c0 + nt * 8 + 2 * (lane & 3);
            float bv0 = bias ? __ldg(bias + ca) : 0.0f;
            float bv1 = bias ? __ldg(bias + ca + 1) : 0.0f;
#pragma unroll
            for (int half = 0; half < 2; half++) {
                int r = e0 + ra + half * 8;
                if (r < rows) {
                    float v0 = acc[mt][nt][half * 2 + 0] + bv0;
                    float v1 = acc[mt][nt][half * 2 + 1] + bv1;
                    if (act == 1) { v0 = gelu_f(v0); v1 = gelu_f(v1); }
                    if (res) {
                        float2 rv = *(const float2*)(res + (size_t)r * 256 + ca);
                        v0 += rv.x; v1 += rv.y;
                    }
                    if (C) {
                        float2 o; o.x = v0; o.y = v1;
                        *(float2*)(C + (size_t)r * 256 + ca) = o;
                    }
                    if (Ch) {
                        __nv_bfloat16 h0 = __float2bfloat16(v0);
                        __nv_bfloat16 h1 = __float2bfloat16(v1);
                        __nv_bfloat162 hp; hp.x = h0; hp.y = h1;
                        __nv_bfloat162 lp;
                        lp.x = __float2bfloat16(v0 - __bfloat162float(h0));
                        lp.y = __float2bfloat16(v1 - __bfloat162float(h1));
                        *(__nv_bfloat162*)(Ch + (size_t)r * 256 + ca) = hp;
                        *(__nv_bfloat162*)(Cl + (size_t)r * 256 + ca) = lp;
                    }
                }
            }
        }
    }
}

// ---------------------------------------------------------------------------
extern "C" void kernel_launch(void* const* d_in, const int* in_sizes, int n_in,
                              void* d_out, int out_size) {
    const int* atom_types = (const int*)d_in[0];
    const float* x_extra = (const float*)d_in[1];
    const int* edge_index = (const int*)d_in[2];
    const float* dists = (const float*)d_in[3];
    const float* freq = (const float*)d_in[4];
    const float* emb_table = (const float*)d_in[5];
    const float* w_emb = (const float*)d_in[6];
    const float* b_emb = (const float*)d_in[7];
    const float* w_n2m = (const float*)d_in[8];
    const float* b_n2m = (const float*)d_in[9];
    const float* w_r2m = (const float*)d_in[10];
    const float* b_r2m = (const float*)d_in[11];
    const float* w_m2n = (const float*)d_in[12];
    const float* mw1 = (const float*)d_in[13];
    const float* mb1 = (const float*)d_in[14];
    const float* mw2 = (const float*)d_in[15];
    const float* mb2 = (const float*)d_in[16];
    const float* mw3 = (const float*)d_in[17];
    const float* mb3 = (const float*)d_in[18];
    const float* mw4 = (const float*)d_in[19];
    const float* mb4 = (const float*)d_in[20];
    const float* fw1 = (const float*)d_in[21];
    const float* fb1 = (const float*)d_in[22];
    const float* fw2 = (const float*)d_in[23];
    const float* fb2 = (const float*)d_in[24];
    float* out = (float*)d_out;

    int N = in_sizes[0];
    int E = in_sizes[2] / 2;

    float *p_h, *p_p, *p_q, *p_agg, *p_t, *p_wr2, *p_cz;
    __nv_bfloat16 *p_hh, *p_hl, *p_aggh, *p_aggl, *p_th, *p_tl, *p_uh, *p_ul, *p_wt;
    __half *p_a1h, *p_a1l, *p_wte;
    cudaGetSymbolAddress((void**)&p_h, g_h);
    cudaGetSymbolAddress((void**)&p_p, g_p);
    cudaGetSymbolAddress((void**)&p_q, g_q);
    cudaGetSymbolAddress((void**)&p_agg, g_agg);
    cudaGetSymbolAddress((void**)&p_t, g_t);
    cudaGetSymbolAddress((void**)&p_wr2, g_wr2);
    cudaGetSymbolAddress((void**)&p_cz, g_cz);
    cudaGetSymbolAddress((void**)&p_hh, g_hh);
    cudaGetSymbolAddress((void**)&p_hl, g_hl);
    cudaGetSymbolAddress((void**)&p_aggh, g_aggh);
    cudaGetSymbolAddress((void**)&p_aggl, g_aggl);
    cudaGetSymbolAddress((void**)&p_th, g_th);
    cudaGetSymbolAddress((void**)&p_tl, g_tl);
    cudaGetSymbolAddress((void**)&p_uh, g_uh);
    cudaGetSymbolAddress((void**)&p_ul, g_ul);
    cudaGetSymbolAddress((void**)&p_a1h, g_a1h);
    cudaGetSymbolAddress((void**)&p_a1l, g_a1l);
    cudaGetSymbolAddress((void**)&p_wt, g_wt);
    cudaGetSymbolAddress((void**)&p_wte, g_wte);

    cudaFuncSetAttribute(edge_mlp_hmma, cudaFuncAttributeMaxDynamicSharedMemorySize, DSMEM_E);
    cudaFuncSetAttribute(node_hmma, cudaFuncAttributeMaxDynamicSharedMemorySize, DSMEM_N);

    dim3 gMega((N + 63) / 64, 2, 5);
    int gE64 = (E + 63) / 64;
    int gE128 = (E + 127) / 128;
    int gNode = (N + 127) / 128;
    dim3 gPQ(gNode, 2);
    dim3 gN1(gNode, 1);

    k0_mega<<<gMega, 256>>>(atom_types, x_extra, emb_table, w_emb, b_emb,
                            w_n2m, b_n2m, w_r2m, b_r2m, mw1, mb1, mw2, mw3, mw4,
                            w_m2n, fw1, fw2, p_h, p_hh, p_hl, p_wr2, p_cz,
                            p_wt, p_wte, N);
    node_hmma<<<gPQ, 512, DSMEM_N>>>(p_hh, p_hl, p_wt, 48, 56, nullptr, nullptr,
                                     p_p, p_q, nullptr, nullptr, p_agg, N, 0);
    edge_combine<<<gE64, 256>>>(dists, freq, p_wr2, p_p, p_q, p_cz, edge_index,
                                p_a1h, p_a1l, E);
    edge_mlp_hmma<<<gE128, 512, DSMEM_E>>>(p_a1h, p_a1l, edge_index, p_wte,
                                           mb2, mb3, mb4, p_agg, E);
    conv_hilo<<<(N * 256 + 255) / 256, 256>>>(p_agg, p_aggh, p_aggl, N * 256);
    node_hmma<<<gN1, 512, DSMEM_N>>>(p_aggh, p_aggl, p_wt, 24, 24, nullptr, p_h,
                                     p_t, nullptr, p_th, p_tl, nullptr, N, 0);
    node_hmma<<<gN1, 512, DSMEM_N>>>(p_th, p_tl, p_wt, 32, 32, fb1, nullptr,
                                     nullptr, nullptr, p_uh, p_ul, nullptr, N, 1);
    node_hmma<<<gN1, 512, DSMEM_N>>>(p_uh, p_ul, p_wt, 40, 40, fb2, p_t,
                                     out, nullptr, nullptr, nullptr, nullptr, N, 0);
}

// round 15
// speedup vs baseline: 1.7845x; 1.0190x over previous
#include <cuda_runtime.h>
#include <cuda_bf16.h>
#include <cuda_fp16.h>
#include <math.h>
#include <stdint.h>

#define NN 10000
#define EE 160000
#define HH 256

// ---------------------------------------------------------------------------
// Scratch (no runtime allocation allowed)
// ---------------------------------------------------------------------------
__device__ float g_h[NN * HH];
__device__ float g_p[NN * HH];
__device__ float g_q[NN * HH];
__device__ float g_agg[NN * HH];
__device__ float g_t[NN * HH];
__device__ float g_wr2[32 * 256];
__device__ float g_cz[256];
__device__ __nv_bfloat16 g_hh[NN * HH], g_hl[NN * HH];
__device__ __nv_bfloat16 g_aggh[NN * HH], g_aggl[NN * HH];
__device__ __nv_bfloat16 g_th[NN * HH], g_tl[NN * HH];
__device__ __nv_bfloat16 g_uh[NN * HH], g_ul[NN * HH];
// act1 hi/lo fp16, [E, 256]
__device__ __half g_a1h[(size_t)EE * HH];
__device__ __half g_a1l[(size_t)EE * HH];
// Node-path W^T tiles, bf16 hi/lo:
// 24..31 w_m2n | 32..39 fw1 | 40..47 fw2 | 48..55 wpa | 56..63 wqb
__device__ __align__(16) __nv_bfloat16 g_wt[64 * 16384];
// Edge-path W^T tiles, fp16 SINGLE: 0..7 W2 | 8..15 W3 | 16..23 W4
__device__ __align__(16) __half g_wte[24 * 8192];

__device__ __forceinline__ float gelu_f(float x) {
    float x3 = x * x * x;
    return 0.5f * x * (1.0f + tanhf(0.7978845608028654f * (x + 0.044715f * x3)));
}
__device__ __forceinline__ float lrelu_f(float x) { return x > 0.0f ? x : 0.01f * x; }

// ---------------------------------------------------------------------------
// PTX helpers (sm_80/sm_90 base ISA: valid at .target sm_100)
// ---------------------------------------------------------------------------
__device__ __forceinline__ uint32_t smem_u32(const void* p) {
    uint32_t a;
    asm("{ .reg .u64 t; cvta.to.shared.u64 t, %1; cvt.u32.u64 %0, t; }" : "=r"(a) : "l"(p));
    return a;
}
__device__ __forceinline__ void cp_async16(uint32_t smem_addr, const void* gptr) {
    asm volatile("cp.async.cg.shared.global [%0], [%1], 16;\n" :: "r"(smem_addr), "l"(gptr));
}
#define CP_COMMIT() asm volatile("cp.async.commit_group;\n" ::: "memory")
#define CP_WAIT0()  asm volatile("cp.async.wait_group 0;\n" ::: "memory")
#define CP_WAIT1()  asm volatile("cp.async.wait_group 1;\n" ::: "memory")

__device__ __forceinline__ void bulk_reduce_add_f32(void* gdst, uint32_t ssrc, uint32_t bytes) {
    asm volatile("cp.reduce.async.bulk.global.shared::cta.bulk_group.add.f32 [%0], [%1], %2;\n"
                 :: "l"(gdst), "r"(ssrc), "r"(bytes) : "memory");
}
#define BULK_COMMIT() asm volatile("cp.async.bulk.commit_group;" ::: "memory")
#define BULK_WAIT0()  asm volatile("cp.async.bulk.wait_group 0;" ::: "memory")
#define FENCE_ASYNC() asm volatile("fence.proxy.async.shared::cta;" ::: "memory")

__device__ __forceinline__ void ldsm4(uint32_t* f, uint32_t a) {
    asm volatile("ldmatrix.sync.aligned.m8n8.x4.shared.b16 {%0,%1,%2,%3}, [%4];\n"
                 : "=r"(f[0]), "=r"(f[1]), "=r"(f[2]), "=r"(f[3]) : "r"(a));
}
// bf16 MMA (node path)
__device__ __forceinline__ void mma16816(float* d, const uint32_t* a, uint32_t b0, uint32_t b1) {
    asm volatile(
        "mma.sync.aligned.m16n8k16.row.col.f32.bf16.bf16.f32 "
        "{%0,%1,%2,%3}, {%4,%5,%6,%7}, {%8,%9}, {%0,%1,%2,%3};\n"
        : "+f"(d[0]), "+f"(d[1]), "+f"(d[2]), "+f"(d[3])
        : "r"(a[0]), "r"(a[1]), "r"(a[2]), "r"(a[3]), "r"(b0), "r"(b1));
}
// fp16 MMA (edge path)
__device__ __forceinline__ void mma16816h(float* d, const uint32_t* a, uint32_t b0, uint32_t b1) {
    asm volatile(
        "mma.sync.aligned.m16n8k16.row.col.f32.f16.f16.f32 "
        "{%0,%1,%2,%3}, {%4,%5,%6,%7}, {%8,%9}, {%0,%1,%2,%3};\n"
        : "+f"(d[0]), "+f"(d[1]), "+f"(d[2]), "+f"(d[3])
        : "r"(a[0]), "r"(a[1]), "r"(a[2]), "r"(a[3]), "r"(b0), "r"(b1));
}

// SMEM layout
#define ACT_HI 0
#define ACT_LO 67584
#define BBUF   135168
#define DSMEM_N 217088            // node kernel (bf16 hi/lo B: 2 x 40960)
#define DSMEM_E (135168 + 40960)  // edge kernel (fp16 single B: 2 x 20480)

// ---------------------------------------------------------------------------
// Mega kernel 0 (unchanged from R14)
// ---------------------------------------------------------------------------
__global__ __launch_bounds__(256, 2) void k0_mega(
    const int* __restrict__ atom_types, const float* __restrict__ x_extra,
    const float* __restrict__ emb_table,
    const float* __restrict__ w_emb, const float* __restrict__ b_emb,
    const float* __restrict__ w_n2m, const float* __restrict__ b_n2m,
    const float* __restrict__ w_r2m, const float* __restrict__ b_r2m,
    const float* __restrict__ mw1, const float* __restrict__ mb1,
    const float* __restrict__ mw2, const float* __restrict__ mw3,
    const float* __restrict__ mw4, const float* __restrict__ w_m2n,
    const float* __restrict__ fw1, const float* __restrict__ fw2,
    float* __restrict__ h, __nv_bfloat16* __restrict__ hh, __nv_bfloat16* __restrict__ hl,
    float* __restrict__ wr2, float* __restrict__ cz,
    __nv_bfloat16* __restrict__ wt, __half* __restrict__ wte, int N) {
    int z = blockIdx.z;
    if (z == 4) {
        int bid = blockIdx.x * 2 + blockIdx.y;
        int flat = bid * 256 + (int)threadIdx.x;
        for (int item = flat; item < 393472; item += 80384) {
            if (item < 196608) {
                int kg = item >> 8, n = item & 255;
                const float* w; int kl, t;
                if (kg < 256)      { w = mw2; kl = kg;       t = (kl >> 5); }
                else if (kg < 512) { w = mw3; kl = kg - 256; t = 8 + (kl >> 5); }
                else               { w = mw4; kl = kg - 512; t = 16 + (kl >> 5); }
                int kk = kl & 31;
                wte[(size_t)t * 8192 + n * 32 + kk] = __float2half(w[(long)kl * 256 + n]);
            } else if (item < 393216) {
                int it2 = item - 196608;
                int kg = it2 >> 8, n = it2 & 255;
                const float* w; int kl, t;
                if (kg < 256)      { w = w_m2n; kl = kg;       t = 24 + (kl >> 5); }
                else if (kg < 512) { w = fw1;   kl = kg - 256; t = 32 + (kl >> 5); }
                else               { w = fw2;   kl = kg - 512; t = 40 + (kl >> 5); }
                int kk = kl & 31;
                float v = w[(long)kl * 256 + n];
                __nv_bfloat16 vh = __float2bfloat16(v);
                __nv_bfloat16 vl = __float2bfloat16(v - __bfloat162float(vh));
                size_t base = (size_t)t * 16384 + n * 32 + kk;
                wt[base] = vh;
                wt[base + 8192] = vl;
            } else {
                int n = item - 393216;
                float s = mb1[n];
                for (int k = 0; k < 256; k++) {
                    s += b_n2m[k] * (mw1[(long)k * 256 + n] + mw1[(long)(256 + k) * 256 + n]);
                    s += b_r2m[k] * mw1[(long)(512 + k) * 256 + n];
                }
                cz[n] = s;
            }
        }
        return;
    }

    __shared__ float As[64 * 33];
    __shared__ float Bs[32 * 132];
    const float* A = nullptr;
    const float* W;
    const float* bias = nullptr;
    int K, rows, act = 0, foldt = -1;
    bool gather = false;
    if (z == 0)      { gather = true; K = 48; W = w_emb; bias = b_emb; rows = N; act = 1; }
    else if (z == 1) { A = w_n2m; K = 256; W = mw1;          rows = 256; foldt = 48; }
    else if (z == 2) { A = w_n2m; K = 256; W = mw1 + 65536;  rows = 256; foldt = 56; }
    else             { A = w_r2m; K = 256; W = mw1 + 131072; rows = 32; }

    int tid = threadIdx.x, tx = tid & 15, ty = tid >> 4;
    int row0 = blockIdx.x * 64;
    int col0 = blockIdx.y * 128;
    if (row0 >= rows) return;

    float acc[4][8];
#pragma unroll
    for (int i = 0; i < 4; i++)
#pragma unroll
        for (int j = 0; j < 8; j++) acc[i][j] = 0.0f;
    for (int k0 = 0; k0 < K; k0 += 32) {
#pragma unroll
        for (int i = 0; i < 8; i++) {
            int idx = tid + i * 256, r = idx >> 5, c = idx & 31;
            int gr = row0 + r, gk = k0 + c;
            float v = 0.0f;
            if (gr < rows && gk < K) {
                if (gather)
                    v = (gk < 32) ? emb_table[atom_types[gr] * 32 + gk]
                                  : x_extra[gr * 16 + gk - 32];
                else
                    v = A[(long)gr * K + gk];
            }
            As[r * 33 + c] = v;
        }
#pragma unroll
        for (int i = 0; i < 16; i++) {
            int idx = tid + i * 256, r = idx >> 7, c = idx & 127;
            int gk = k0 + r;
            Bs[r * 132 + c] = (gk < K) ? W[(long)gk * 256 + col0 + c] : 0.0f;
        }
        __syncthreads();
#pragma unroll
        for (int kk = 0; kk < 32; kk++) {
            float a[4];
#pragma unroll
            for (int i = 0; i < 4; i++) a[i] = As[(ty * 4 + i) * 33 + kk];
#pragma unroll
            for (int j = 0; j < 8; j++) {
                float b = Bs[kk * 132 + tx + 16 * j];
#pragma unroll
                for (int i = 0; i < 4; i++) acc[i][j] = fmaf(a[i], b, acc[i][j]);
            }
        }
        __syncthreads();
    }
#pragma unroll
    for (int i = 0; i < 4; i++) {
        int r = row0 + ty * 4 + i;
        if (r < rows) {
#pragma unroll
            for (int j = 0; j < 8; j++) {
                int col = col0 + tx + 16 * j;
                float v = acc[i][j];
                if (bias) v += bias[col];
                if (act == 1) v = gelu_f(v);
                if (foldt >= 0) {
                    int t = foldt + (r >> 5);
                    size_t base = (size_t)t * 16384 + (size_t)col * 32 + (r & 31);
                    __nv_bfloat16 vh = __float2bfloat16(v);
                    wt[base] = vh;
                    wt[base + 8192] = __float2bfloat16(v - __bfloat162float(vh));
                } else if (z == 0) {
                    h[(long)r * 256 + col] = v;
                    __nv_bfloat16 vh = __float2bfloat16(v);
                    hh[(long)r * 256 + col] = vh;
                    hl[(long)r * 256 + col] = __float2bfloat16(v - __bfloat162float(vh));
                } else {
                    wr2[(long)r * 256 + col] = v;
                }
            }
        }
    }
}

// fp32 -> hi/lo bf16
__global__ void conv_hilo(const float* __restrict__ x, __nv_bfloat16* __restrict__ xh,
                          __nv_bfloat16* __restrict__ xl, int total) {
    int i = blockIdx.x * blockDim.x + threadIdx.x;
    if (i < total) {
        float v = x[i];
        __nv_bfloat16 h = __float2bfloat16(v);
        xh[i] = h;
        xl[i] = __float2bfloat16(v - __bfloat162float(h));
    }
}

// ---------------------------------------------------------------------------
// edge combine: act1 = lrelu( rbf@Wr2 + p[src] + q[dst] + cz ) -> fp16 hi/lo
// Vectorized: thread owns col pairs {2*tx + 32*j}, float2 loads, half2 stores.
// ---------------------------------------------------------------------------
__global__ __launch_bounds__(256, 2) void edge_combine(
    const float* __restrict__ dists, const float* __restrict__ freq,
    const float* __restrict__ wr2, const float* __restrict__ p,
    const float* __restrict__ q, const float* __restrict__ cz,
    const int* __restrict__ edge_index,
    __half* __restrict__ a1h, __half* __restrict__ a1l, int E) {
    __shared__ float Rs[64 * 33];
    __shared__ float Bs[32 * 256];
    __shared__ float s_freq[32];
    __shared__ float s_cz[256];
    __shared__ int s_src[64], s_dst[64];
    int tid = threadIdx.x, tx = tid & 15, ty = tid >> 4;
    int e0 = blockIdx.x * 64;
    if (tid < 32) s_freq[tid] = freq[tid];
    s_cz[tid] = cz[tid];
    if (tid < 64) {
        int e = e0 + tid;
        s_src[tid] = (e < E) ? edge_index[e] : 0;
        s_dst[tid] = (e < E) ? edge_index[E + e] : 0;
    }
#pragma unroll
    for (int i = 0; i < 32; i++) Bs[i * 256 + tid] = wr2[i * 256 + tid];
    __syncthreads();
#pragma unroll
    for (int i = 0; i < 8; i++) {
        int idx = tid + i * 256, el = idx >> 5, r = idx & 31;
        int e = e0 + el;
        float d = (e < E) ? dists[e] * 0.2f : 1.0f;
        float d2 = d * d, d5 = d2 * d2 * d;
        float env = 1.0f / d + d5 * (-28.0f + d * (48.0f + d * (-21.0f)));
        Rs[el * 33 + r] = env * sinf(s_freq[r] * d);
    }
    __syncthreads();
    float2 acc[4][8];
#pragma unroll
    for (int i = 0; i < 4; i++)
#pragma unroll
        for (int j = 0; j < 8; j++) { acc[i][j].x = 0.0f; acc[i][j].y = 0.0f; }
#pragma unroll
    for (int kk = 0; kk < 32; kk++) {
        float a[4];
#pragma unroll
        for (int i = 0; i < 4; i++) a[i] = Rs[(ty * 4 + i) * 33 + kk];
#pragma unroll
        for (int j = 0; j < 8; j++) {
            float2 b = *(const float2*)&Bs[kk * 256 + tx * 2 + 32 * j];
#pragma unroll
            for (int i = 0; i < 4; i++) {
                acc[i][j].x = fmaf(a[i], b.x, acc[i][j].x);
                acc[i][j].y = fmaf(a[i], b.y, acc[i][j].y);
            }
        }
    }
#pragma unroll
    for (int i = 0; i < 4; i++) {
        int r = ty * 4 + i;
        int e = e0 + r;
        if (e < E) {
            const float* prow = p + (size_t)s_src[r] * 256;
            const float* qrow = q + (size_t)s_dst[r] * 256;
#pragma unroll
            for (int j = 0; j < 8; j++) {
                int col = tx * 2 + 32 * j;
                float2 pv = *(const float2*)(prow + col);
                float2 qv = *(const float2*)(qrow + col);
                float v0 = lrelu_f(acc[i][j].x + pv.x + qv.x + s_cz[col]);
                float v1 = lrelu_f(acc[i][j].y + pv.y + qv.y + s_cz[col + 1]);
                __half h0 = __float2half(v0);
                __half h1 = __float2half(v1);
                __half2 hp; hp.x = h0; hp.y = h1;
                __half2 lp;
                lp.x = __float2half(v0 - __half2float(h0));
                lp.y = __float2half(v1 - __half2float(h1));
                *(__half2*)(a1h + (size_t)e * 256 + col) = hp;
                *(__half2*)(a1l + (size_t)e * 256 + col) = lp;
            }
        }
    }
}

// ---------------------------------------------------------------------------
// fp16 HMMA fused edge MLP (layers 2..4). Batched B ldsm per k16-step.
// ---------------------------------------------------------------------------
__global__ __launch_bounds__(512, 1) void edge_mlp_hmma(
    const __half* __restrict__ a1h, const __half* __restrict__ a1l,
    const int* __restrict__ edge_index, const __half* __restrict__ wte,
    const float* __restrict__ b2, const float* __restrict__ b3,
    const float* __restrict__ b4, float* __restrict__ agg, int E) {
    extern __shared__ __align__(16) char dsm[];
    __shared__ int s_dst[128];
    __shared__ float s_bias[768];

    const int tid = threadIdx.x;
    const int wid = tid >> 5, lane = tid & 31;
    const int wm = wid >> 2, wn = wid & 3;
    const int r0 = wm * 32;
    const int c0 = wn * 64;
    const int gtid = lane + wm * 32;
    const int e0 = blockIdx.x * 128;
    const uint32_t sb = smem_u32(dsm);

    for (int i = tid; i < 768; i += 512) {
        const float* b = (i < 256) ? b2 : (i < 512) ? b3 : b4;
        s_bias[i] = b[i & 255];
    }
    if (tid < 128) {
        int e = e0 + tid;
        s_dst[tid] = (e < E) ? edge_index[E + e] : 0;
    }

    float acc[2][8][4];
#pragma unroll
    for (int mt = 0; mt < 2; mt++)
#pragma unroll
        for (int nt = 0; nt < 8; nt++)
#pragma unroll
            for (int i = 0; i < 4; i++) acc[mt][nt][i] = 0.0f;

    auto groupbar = [&]() {
        asm volatile("bar.sync %0, 128;" :: "r"(1 + wn) : "memory");
    };
    auto prefetchB = [&](int t, int buf) {
        const char* wsrc = (const char*)wte + (size_t)t * 16384;
        uint32_t dbase = sb + BBUF + buf * 20480;
#pragma unroll
        for (int it = 0; it < 2; it++) {
            int id = gtid + it * 128;
            int nl = id >> 2, seg = id & 3;
            int n = c0 + nl;
            cp_async16(dbase + (uint32_t)n * 80 + seg * 16,
                       wsrc + (size_t)n * 64 + seg * 16);
        }
    };
    auto loadACT = [&]() {
#pragma unroll
        for (int it = 0; it < 16; it++) {
            int id = tid + it * 512;
            int seg = id & 31;
            int hl = (id >> 5) & 1;
            int row = id >> 6;
            int e = e0 + row;
            if (e >= E) e = E - 1;
            const char* sp = (const char*)(hl ? a1l : a1h) + (size_t)e * 512 + seg * 16;
            cp_async16(sb + (hl ? ACT_LO : ACT_HI) + (uint32_t)row * 528 + seg * 16, sp);
        }
    };
    auto compute = [&](uint32_t abase, uint32_t bbase) {
#pragma unroll
        for (int s = 0; s < 2; s++) {
            int ko2 = s * 32;
            uint32_t ah[2][4], al[2][4];
#pragma unroll
            for (int mt = 0; mt < 2; mt++) {
                uint32_t ad = abase + (uint32_t)(r0 + mt * 16 + (lane & 15)) * 528 +
                              ko2 + ((lane >> 4) << 4);
                ldsm4(ah[mt], ad);
                ldsm4(al[mt], ad + (ACT_LO - ACT_HI));
            }
            uint32_t bb[4][4];
#pragma unroll
            for (int q = 0; q < 4; q++) {
                int n = c0 + q * 16 + (lane & 7) + ((lane & 16) >> 1);
                uint32_t bd = bbase + (uint32_t)n * 80 + ko2 + ((lane & 8) << 1);
                ldsm4(bb[q], bd);
            }
#pragma unroll
            for (int q = 0; q < 4; q++) {
#pragma unroll
                for (int mt = 0; mt < 2; mt++) {
                    mma16816h(acc[mt][2 * q + 0], ah[mt], bb[q][0], bb[q][1]);
                    mma16816h(acc[mt][2 * q + 1], ah[mt], bb[q][2], bb[q][3]);
                    mma16816h(acc[mt][2 * q + 0], al[mt], bb[q][0], bb[q][1]);
                    mma16816h(acc[mt][2 * q + 1], al[mt], bb[q][2], bb[q][3]);
                }
            }
        }
    };
    auto epilogue_act = [&](int bidx) {
#pragma unroll
        for (int mt = 0; mt < 2; mt++) {
#pragma unroll
            for (int nt = 0; nt < 8; nt++) {
                int ra = r0 + mt * 16 + (lane >> 2);
                int ca = c0 + nt * 8 + 2 * (lane & 3);
                float bv0 = s_bias[bidx * 256 + ca], bv1 = s_bias[bidx * 256 + ca + 1];
#pragma unroll
                for (int half = 0; half < 2; half++) {
                    int r = ra + half * 8;
                    float v0 = lrelu_f(acc[mt][nt][half * 2 + 0] + bv0);
                    float v1 = lrelu_f(acc[mt][nt][half * 2 + 1] + bv1);
                    __half h0 = __float2half(v0);
                    __half h1 = __float2half(v1);
                    __half2 hp; hp.x = h0; hp.y = h1;
                    __half2 lp;
                    lp.x = __float2half(v0 - __half2float(h0));
                    lp.y = __float2half(v1 - __half2float(h1));
                    uint32_t off = (uint32_t)r * 528 + (uint32_t)ca * 2;
                    *(__half2*)(dsm + ACT_HI + off) = hp;
                    *(__half2*)(dsm + ACT_LO + off) = lp;
                    acc[mt][nt][half * 2 + 0] = 0.0f;
                    acc[mt][nt][half * 2 + 1] = 0.0f;
                }
            }
        }
    };

    loadACT();
    prefetchB(0, 0);
    CP_COMMIT();
    prefetchB(1, 1);
    CP_COMMIT();

    for (int g = 0; g < 24; g++) {
        if (g < 23) { CP_WAIT1(); } else { CP_WAIT0(); }
        if (g == 0 || g == 8 || g == 16) __syncthreads();
        else groupbar();
        compute(sb + ACT_HI + (uint32_t)(g & 7) * 64, sb + BBUF + (g & 1) * 20480);
        if (g + 2 < 24) {
            groupbar();
            prefetchB(g + 2, g & 1);
            CP_COMMIT();
        }
        if (g == 7 || g == 15) {
            __syncthreads();
            epilogue_act(g >> 3);
        } else if (g == 23) {
            __syncthreads();
#pragma unroll
            for (int mt = 0; mt < 2; mt++) {
#pragma unroll
                for (int nt = 0; nt < 8; nt++) {
                    int ra = r0 + mt * 16 + (lane >> 2);
                    int ca = c0 + nt * 8 + 2 * (lane & 3);
                    float bv0 = s_bias[512 + ca], bv1 = s_bias[512 + ca + 1];
#pragma unroll
                    for (int half = 0; half < 2; half++) {
                        int r = ra + half * 8;
                        float2 v;
                        v.x = acc[mt][nt][half * 2 + 0] + bv0;
                        v.y = acc[mt][nt][half * 2 + 1] + bv1;
                        *(float2*)(dsm + (uint32_t)r * 1024 + (uint32_t)ca * 4) = v;
                    }
                }
            }
            FENCE_ASYNC();
            __syncthreads();
            if (tid < 128 && (e0 + tid) < E) {
                bulk_reduce_add_f32(agg + (size_t)s_dst[tid] * 256,
                                    sb + (uint32_t)tid * 1024, 1024);
            }
            BULK_COMMIT();
            BULK_WAIT0();
        }
    }
}

// ---------------------------------------------------------------------------
// Node HMMA GEMM (bf16 3-product, unchanged — validated).
// ---------------------------------------------------------------------------
__global__ __launch_bounds__(512, 1) void node_hmma(
    const __nv_bfloat16* __restrict__ Ah, const __nv_bfloat16* __restrict__ Al,
    const __nv_bfloat16* __restrict__ wt, int tb0, int tb1,
    const float* __restrict__ bias, const float* __restrict__ res,
    float* __restrict__ C0, float* __restrict__ C1,
    __nv_bfloat16* __restrict__ Ch, __nv_bfloat16* __restrict__ Cl,
    float* __restrict__ zbuf, int rows, int act) {
    extern __shared__ __align__(16) char dsm[];
    const int tid = threadIdx.x;
    const int wid = tid >> 5, lane = tid & 31;
    const int wm = wid >> 2, wn = wid & 3;
    const int r0 = wm * 32;
    const int c0 = wn * 64;
    const int gtid = lane + wm * 32;
    const int e0 = blockIdx.x * 128;
    const uint32_t sb = smem_u32(dsm);
    const int tb = blockIdx.y ? tb1 : tb0;
    float* C = blockIdx.y ? C1 : C0;
    if (e0 >= rows) return;

    float acc[2][8][4];
#pragma unroll
    for (int mt = 0; mt < 2; mt++)
#pragma unroll
        for (int nt = 0; nt < 8; nt++)
#pragma unroll
            for (int i = 0; i < 4; i++) acc[mt][nt][i] = 0.0f;

    auto groupbar = [&]() {
        asm volatile("bar.sync %0, 128;" :: "r"(1 + wn) : "memory");
    };
    auto prefetchB = [&](int t, int buf) {
        const char* wsrc = (const char*)wt + (size_t)(tb + t) * 32768;
        uint32_t dbase = sb + BBUF + buf * 40960;
#pragma unroll
        for (int it = 0; it < 4; it++) {
            int id = gtid + it * 128;
            int hl = id >> 8;
            int rest = id & 255;
            int nl = rest >> 2, seg = rest & 3;
            int n = c0 + nl;
            cp_async16(dbase + hl * 20480 + (uint32_t)n * 80 + seg * 16,
                       wsrc + hl * 16384 + (size_t)n * 64 + seg * 16);
        }
    };
    auto loadACT = [&]() {
#pragma unroll
        for (int it = 0; it < 16; it++) {
            int id = tid + it * 512;
            int seg = id & 31;
            int hl = (id >> 5) & 1;
            int row = id >> 6;
            int e = e0 + row;
            if (e >= rows) e = rows - 1;
            const char* sp = (const char*)(hl ? Al : Ah) + (size_t)e * 512 + seg * 16;
            cp_async16(sb + (hl ? ACT_LO : ACT_HI) + (uint32_t)row * 528 + seg * 16, sp);
        }
    };
    auto compute = [&](uint32_t abase, uint32_t bbase) {
#pragma unroll
        for (int s = 0; s < 2; s++) {
            int ko2 = s * 32;
            uint32_t ah[2][4], al[2][4];
#pragma unroll
            for (int mt = 0; mt < 2; mt++) {
                uint32_t ad = abase + (uint32_t)(r0 + mt * 16 + (lane & 15)) * 528 +
                              ko2 + ((lane >> 4) << 4);
                ldsm4(ah[mt], ad);
                ldsm4(al[mt], ad + (ACT_LO - ACT_HI));
            }
#pragma unroll
            for (int q = 0; q < 4; q++) {
                int n = c0 + q * 16 + (lane & 7) + ((lane & 16) >> 1);
                uint32_t bd = bbase + (uint32_t)n * 80 + ko2 + ((lane & 8) << 1);
                uint32_t bh[4], bl[4];
                ldsm4(bh, bd);
                ldsm4(bl, bd + 20480);
#pragma unroll
                for (int mt = 0; mt < 2; mt++) {
                    mma16816(acc[mt][2 * q + 0], ah[mt], bh[0], bh[1]);
                    mma16816(acc[mt][2 * q + 1], ah[mt], bh[2], bh[3]);
                    mma16816(acc[mt][2 * q + 0], al[mt], bh[0], bh[1]);
                    mma16816(acc[mt][2 * q + 1], al[mt], bh[2], bh[3]);
                    mma16816(acc[mt][2 * q + 0], ah[mt], bl[0], bl[1]);
                    mma16816(acc[mt][2 * q + 1], ah[mt], bl[2], bl[3]);
                }
            }
        }
    };

    loadACT();
    prefetchB(0, 0);
    CP_COMMIT();
    prefetchB(1, 1);
    CP_COMMIT();

    if (zbuf && blockIdx.y == 0) {
#pragma unroll
        for (int it = 0; it < 16; it++) {
            int id = tid + it * 512;
            int row = id >> 6;
            int e = e0 + row;
            if (e < rows) {
                float4 z = {0.0f, 0.0f, 0.0f, 0.0f};
                *(float4*)(zbuf + (size_t)e * 256 + (id & 63) * 4) = z;
            }
        }
    }

    for (int g = 0; g < 8; g++) {
        if (g < 7) { CP_WAIT1(); } else { CP_WAIT0(); }
        if (g == 0) __syncthreads();
        else groupbar();
        compute(sb + ACT_HI + (uint32_t)g * 64, sb + BBUF + (g & 1) * 40960);
        if (g + 2 < 8) {
            groupbar();
            prefetchB(g + 2, g & 1);
            CP_COMMIT();
        }
    }

#pragma unroll
    for (int mt = 0; mt < 2; mt++) {
#pragma unroll
        for (int nt = 0; nt < 8; nt++) {
            int ra = r0 + mt * 16 + (lane >> 2);
            int ca = c0 + nt * 8 + 2 * (lane & 3);
            float bv0 = bias ? __ldg(bias + ca) : 0.0f;
            float bv1 = bias ? __ldg(bias + ca + 1) : 0.0f;
#pragma unroll
            for (int half = 0; half < 2; half++) {
                int r = e0 + ra + half * 8;
                if (r < rows) {
                    float v0 = acc[mt][nt][half * 2 + 0] + bv0;
                    float v1 = acc[mt][nt][half * 2 + 1] + bv1;
                    if (act == 1) { v0 = gelu_f(v0); v1 = gelu_f(v1); }
                    if (res) {
                        float2 rv = *(const float2*)(res + (size_t)r * 256 + ca);
                        v0 += rv.x; v1 += rv.y;
                    }
                    if (C) {
                        float2 o; o.x = v0; o.y = v1;
                        *(float2*)(C + (size_t)r * 256 + ca) = o;
                    }
                    if (Ch) {
                        __nv_bfloat16 h0 = __float2bfloat16(v0);
                        __nv_bfloat16 h1 = __float2bfloat16(v1);
                        __nv_bfloat162 hp; hp.x = h0; hp.y = h1;
                        __nv_bfloat162 lp;
                        lp.x = __float2bfloat16(v0 - __bfloat162float(h0));
                        lp.y = __float2bfloat16(v1 - __bfloat162float(h1));
                        *(__nv_bfloat162*)(Ch + (size_t)r * 256 + ca) = hp;
                        *(__nv_bfloat162*)(Cl + (size_t)r * 256 + ca) = lp;
                    }
                }
            }
        }
    }
}

// ---------------------------------------------------------------------------
extern "C" void kernel_launch(void* const* d_in, const int* in_sizes, int n_in,
                              void* d_out, int out_size) {
    const int* atom_types = (const int*)d_in[0];
    const float* x_extra = (const float*)d_in[1];
    const int* edge_index = (const int*)d_in[2];
    const float* dists = (const float*)d_in[3];
    const float* freq = (const float*)d_in[4];
    const float* emb_table = (const float*)d_in[5];
    const float* w_emb = (const float*)d_in[6];
    const float* b_emb = (const float*)d_in[7];
    const float* w_n2m = (const float*)d_in[8];
    const float* b_n2m = (const float*)d_in[9];
    const float* w_r2m = (const float*)d_in[10];
    const float* b_r2m = (const float*)d_in[11];
    const float* w_m2n = (const float*)d_in[12];
    const float* mw1 = (const float*)d_in[13];
    const float* mb1 = (const float*)d_in[14];
    const float* mw2 = (const float*)d_in[15];
    const float* mb2 = (const float*)d_in[16];
    const float* mw3 = (const float*)d_in[17];
    const float* mb3 = (const float*)d_in[18];
    const float* mw4 = (const float*)d_in[19];
    const float* mb4 = (const float*)d_in[20];
    const float* fw1 = (const float*)d_in[21];
    const float* fb1 = (const float*)d_in[22];
    const float* fw2 = (const float*)d_in[23];
    const float* fb2 = (const float*)d_in[24];
    float* out = (float*)d_out;

    int N = in_sizes[0];
    int E = in_sizes[2] / 2;

    float *p_h, *p_p, *p_q, *p_agg, *p_t, *p_wr2, *p_cz;
    __nv_bfloat16 *p_hh, *p_hl, *p_aggh, *p_aggl, *p_th, *p_tl, *p_uh, *p_ul, *p_wt;
    __half *p_a1h, *p_a1l, *p_wte;
    cudaGetSymbolAddress((void**)&p_h, g_h);
    cudaGetSymbolAddress((void**)&p_p, g_p);
    cudaGetSymbolAddress((void**)&p_q, g_q);
    cudaGetSymbolAddress((void**)&p_agg, g_agg);
    cudaGetSymbolAddress((void**)&p_t, g_t);
    cudaGetSymbolAddress((void**)&p_wr2, g_wr2);
    cudaGetSymbolAddress((void**)&p_cz, g_cz);
    cudaGetSymbolAddress((void**)&p_hh, g_hh);
    cudaGetSymbolAddress((void**)&p_hl, g_hl);
    cudaGetSymbolAddress((void**)&p_aggh, g_aggh);
    cudaGetSymbolAddress((void**)&p_aggl, g_aggl);
    cudaGetSymbolAddress((void**)&p_th, g_th);
    cudaGetSymbolAddress((void**)&p_tl, g_tl);
    cudaGetSymbolAddress((void**)&p_uh, g_uh);
    cudaGetSymbolAddress((void**)&p_ul, g_ul);
    cudaGetSymbolAddress((void**)&p_a1h, g_a1h);
    cudaGetSymbolAddress((void**)&p_a1l, g_a1l);
    cudaGetSymbolAddress((void**)&p_wt, g_wt);
    cudaGetSymbolAddress((void**)&p_wte, g_wte);

    cudaFuncSetAttribute(edge_mlp_hmma, cudaFuncAttributeMaxDynamicSharedMemorySize, DSMEM_E);
    cudaFuncSetAttribute(node_hmma, cudaFuncAttributeMaxDynamicSharedMemorySize, DSMEM_N);

    dim3 gMega((N + 63) / 64, 2, 5);
    int gE64 = (E + 63) / 64;
    int gE128 = (E + 127) / 128;
    int gNode = (N + 127) / 128;
    dim3 gPQ(gNode, 2);
    dim3 gN1(gNode, 1);

    k0_mega<<<gMega, 256>>>(atom_types, x_extra, emb_table, w_emb, b_emb,
                            w_n2m, b_n2m, w_r2m, b_r2m, mw1, mb1, mw2, mw3, mw4,
                            w_m2n, fw1, fw2, p_h, p_hh, p_hl, p_wr2, p_cz,
                            p_wt, p_wte, N);
    node_hmma<<<gPQ, 512, DSMEM_N>>>(p_hh, p_hl, p_wt, 48, 56, nullptr, nullptr,
                                     p_p, p_q, nullptr, nullptr, p_agg, N, 0);
    edge_combine<<<gE64, 256>>>(dists, freq, p_wr2, p_p, p_q, p_cz, edge_index,
                                p_a1h, p_a1l, E);
    edge_mlp_hmma<<<gE128, 512, DSMEM_E>>>(p_a1h, p_a1l, edge_index, p_wte,
                                           mb2, mb3, mb4, p_agg, E);
    conv_hilo<<<(N * 256 + 255) / 256, 256>>>(p_agg, p_aggh, p_aggl, N * 256);
    node_hmma<<<gN1, 512, DSMEM_N>>>(p_aggh, p_aggl, p_wt, 24, 24, nullptr, p_h,
                                     p_t, nullptr, p_th, p_tl, nullptr, N, 0);
    node_hmma<<<gN1, 512, DSMEM_N>>>(p_th, p_tl, p_wt, 32, 32, fb1, nullptr,
                                     nullptr, nullptr, p_uh, p_ul, nullptr, N, 1);
    node_hmma<<<gN1, 512, DSMEM_N>>>(p_uh, p_ul, p_wt, 40, 40, fb2, p_t,
                                     out, nullptr, nullptr, nullptr, nullptr, N, 0);
}

// round 16
// speedup vs baseline: 1.9802x; 1.1096x over previous
#include <cuda_runtime.h>
#include <cuda_bf16.h>
#include <cuda_fp16.h>
#include <math.h>
#include <stdint.h>

#define NN 10000
#define EE 160000
#define HH 256

// ---------------------------------------------------------------------------
// Scratch (no runtime allocation allowed)
// ---------------------------------------------------------------------------
__device__ float g_h[NN * HH];
__device__ float g_p[NN * HH];
__device__ float g_q[NN * HH];
__device__ float g_agg[NN * HH];
__device__ float g_t[NN * HH];
__device__ float g_wr2[32 * 256];
__device__ float g_cz[256];
__device__ __nv_bfloat16 g_hh[NN * HH], g_hl[NN * HH];
__device__ __nv_bfloat16 g_aggh[NN * HH], g_aggl[NN * HH];
__device__ __nv_bfloat16 g_th[NN * HH], g_tl[NN * HH];
__device__ __nv_bfloat16 g_uh[NN * HH], g_ul[NN * HH];
// act1 hi/lo fp16, [E, 256]
__device__ __half g_a1h[(size_t)EE * HH];
__device__ __half g_a1l[(size_t)EE * HH];
// Node-path W^T tiles, bf16 hi/lo:
// 24..31 w_m2n | 32..39 fw1 | 40..47 fw2 | 48..55 wpa | 56..63 wqb
__device__ __align__(16) __nv_bfloat16 g_wt[64 * 16384];
// Edge-path W^T tiles, fp16 SINGLE: 0..7 W2 | 8..15 W3 | 16..23 W4
__device__ __align__(16) __half g_wte[24 * 8192];

__device__ __forceinline__ float gelu_f(float x) {
    float x3 = x * x * x;
    return 0.5f * x * (1.0f + tanhf(0.7978845608028654f * (x + 0.044715f * x3)));
}
__device__ __forceinline__ float lrelu_f(float x) { return x > 0.0f ? x : 0.01f * x; }

// ---------------------------------------------------------------------------
// PTX helpers (sm_80/sm_90 base ISA: valid at .target sm_100)
// ---------------------------------------------------------------------------
__device__ __forceinline__ uint32_t smem_u32(const void* p) {
    uint32_t a;
    asm("{ .reg .u64 t; cvta.to.shared.u64 t, %1; cvt.u32.u64 %0, t; }" : "=r"(a) : "l"(p));
    return a;
}
__device__ __forceinline__ void cp_async16(uint32_t smem_addr, const void* gptr) {
    asm volatile("cp.async.cg.shared.global [%0], [%1], 16;\n" :: "r"(smem_addr), "l"(gptr));
}
#define CP_COMMIT() asm volatile("cp.async.commit_group;\n" ::: "memory")
#define CP_WAIT0()  asm volatile("cp.async.wait_group 0;\n" ::: "memory")
#define CP_WAIT1()  asm volatile("cp.async.wait_group 1;\n" ::: "memory")

__device__ __forceinline__ void bulk_reduce_add_f32(void* gdst, uint32_t ssrc, uint32_t bytes) {
    asm volatile("cp.reduce.async.bulk.global.shared::cta.bulk_group.add.f32 [%0], [%1], %2;\n"
                 :: "l"(gdst), "r"(ssrc), "r"(bytes) : "memory");
}
#define BULK_COMMIT() asm volatile("cp.async.bulk.commit_group;" ::: "memory")
#define BULK_WAIT0()  asm volatile("cp.async.bulk.wait_group 0;" ::: "memory")
#define FENCE_ASYNC() asm volatile("fence.proxy.async.shared::cta;" ::: "memory")

__device__ __forceinline__ void ldsm4(uint32_t* f, uint32_t a) {
    asm volatile("ldmatrix.sync.aligned.m8n8.x4.shared.b16 {%0,%1,%2,%3}, [%4];\n"
                 : "=r"(f[0]), "=r"(f[1]), "=r"(f[2]), "=r"(f[3]) : "r"(a));
}
// bf16 MMA (node path)
__device__ __forceinline__ void mma16816(float* d, const uint32_t* a, uint32_t b0, uint32_t b1) {
    asm volatile(
        "mma.sync.aligned.m16n8k16.row.col.f32.bf16.bf16.f32 "
        "{%0,%1,%2,%3}, {%4,%5,%6,%7}, {%8,%9}, {%0,%1,%2,%3};\n"
        : "+f"(d[0]), "+f"(d[1]), "+f"(d[2]), "+f"(d[3])
        : "r"(a[0]), "r"(a[1]), "r"(a[2]), "r"(a[3]), "r"(b0), "r"(b1));
}
// fp16 MMA (edge path)
__device__ __forceinline__ void mma16816h(float* d, const uint32_t* a, uint32_t b0, uint32_t b1) {
    asm volatile(
        "mma.sync.aligned.m16n8k16.row.col.f32.f16.f16.f32 "
        "{%0,%1,%2,%3}, {%4,%5,%6,%7}, {%8,%9}, {%0,%1,%2,%3};\n"
        : "+f"(d[0]), "+f"(d[1]), "+f"(d[2]), "+f"(d[3])
        : "r"(a[0]), "r"(a[1]), "r"(a[2]), "r"(a[3]), "r"(b0), "r"(b1));
}

// SMEM layout — node kernel (128 rows)
#define ACT_HI 0
#define ACT_LO 67584
#define BBUF   135168
#define DSMEM_N 217088            // bf16 hi/lo B: 2 x 40960
// SMEM layout — edge kernel (64 rows, 2 CTAs/SM)
#define E_ACT_LO 33792
#define E_BBUF   67584
#define DSMEM_E  108544           // 67584 + 2 x 20480

// ---------------------------------------------------------------------------
// Mega kernel 0 (unchanged)
// ---------------------------------------------------------------------------
__global__ __launch_bounds__(256, 2) void k0_mega(
    const int* __restrict__ atom_types, const float* __restrict__ x_extra,
    const float* __restrict__ emb_table,
    const float* __restrict__ w_emb, const float* __restrict__ b_emb,
    const float* __restrict__ w_n2m, const float* __restrict__ b_n2m,
    const float* __restrict__ w_r2m, const float* __restrict__ b_r2m,
    const float* __restrict__ mw1, const float* __restrict__ mb1,
    const float* __restrict__ mw2, const float* __restrict__ mw3,
    const float* __restrict__ mw4, const float* __restrict__ w_m2n,
    const float* __restrict__ fw1, const float* __restrict__ fw2,
    float* __restrict__ h, __nv_bfloat16* __restrict__ hh, __nv_bfloat16* __restrict__ hl,
    float* __restrict__ wr2, float* __restrict__ cz,
    __nv_bfloat16* __restrict__ wt, __half* __restrict__ wte, int N) {
    int z = blockIdx.z;
    if (z == 4) {
        int bid = blockIdx.x * 2 + blockIdx.y;
        int flat = bid * 256 + (int)threadIdx.x;
        for (int item = flat; item < 393472; item += 80384) {
            if (item < 196608) {
                int kg = item >> 8, n = item & 255;
                const float* w; int kl, t;
                if (kg < 256)      { w = mw2; kl = kg;       t = (kl >> 5); }
                else if (kg < 512) { w = mw3; kl = kg - 256; t = 8 + (kl >> 5); }
                else               { w = mw4; kl = kg - 512; t = 16 + (kl >> 5); }
                int kk = kl & 31;
                wte[(size_t)t * 8192 + n * 32 + kk] = __float2half(w[(long)kl * 256 + n]);
            } else if (item < 393216) {
                int it2 = item - 196608;
                int kg = it2 >> 8, n = it2 & 255;
                const float* w; int kl, t;
                if (kg < 256)      { w = w_m2n; kl = kg;       t = 24 + (kl >> 5); }
                else if (kg < 512) { w = fw1;   kl = kg - 256; t = 32 + (kl >> 5); }
                else               { w = fw2;   kl = kg - 512; t = 40 + (kl >> 5); }
                int kk = kl & 31;
                float v = w[(long)kl * 256 + n];
                __nv_bfloat16 vh = __float2bfloat16(v);
                __nv_bfloat16 vl = __float2bfloat16(v - __bfloat162float(vh));
                size_t base = (size_t)t * 16384 + n * 32 + kk;
                wt[base] = vh;
                wt[base + 8192] = vl;
            } else {
                int n = item - 393216;
                float s = mb1[n];
                for (int k = 0; k < 256; k++) {
                    s += b_n2m[k] * (mw1[(long)k * 256 + n] + mw1[(long)(256 + k) * 256 + n]);
                    s += b_r2m[k] * mw1[(long)(512 + k) * 256 + n];
                }
                cz[n] = s;
            }
        }
        return;
    }

    __shared__ float As[64 * 33];
    __shared__ float Bs[32 * 132];
    const float* A = nullptr;
    const float* W;
    const float* bias = nullptr;
    int K, rows, act = 0, foldt = -1;
    bool gather = false;
    if (z == 0)      { gather = true; K = 48; W = w_emb; bias = b_emb; rows = N; act = 1; }
    else if (z == 1) { A = w_n2m; K = 256; W = mw1;          rows = 256; foldt = 48; }
    else if (z == 2) { A = w_n2m; K = 256; W = mw1 + 65536;  rows = 256; foldt = 56; }
    else             { A = w_r2m; K = 256; W = mw1 + 131072; rows = 32; }

    int tid = threadIdx.x, tx = tid & 15, ty = tid >> 4;
    int row0 = blockIdx.x * 64;
    int col0 = blockIdx.y * 128;
    if (row0 >= rows) return;

    float acc[4][8];
#pragma unroll
    for (int i = 0; i < 4; i++)
#pragma unroll
        for (int j = 0; j < 8; j++) acc[i][j] = 0.0f;
    for (int k0 = 0; k0 < K; k0 += 32) {
#pragma unroll
        for (int i = 0; i < 8; i++) {
            int idx = tid + i * 256, r = idx >> 5, c = idx & 31;
            int gr = row0 + r, gk = k0 + c;
            float v = 0.0f;
            if (gr < rows && gk < K) {
                if (gather)
                    v = (gk < 32) ? emb_table[atom_types[gr] * 32 + gk]
                                  : x_extra[gr * 16 + gk - 32];
                else
                    v = A[(long)gr * K + gk];
            }
            As[r * 33 + c] = v;
        }
#pragma unroll
        for (int i = 0; i < 16; i++) {
            int idx = tid + i * 256, r = idx >> 7, c = idx & 127;
            int gk = k0 + r;
            Bs[r * 132 + c] = (gk < K) ? W[(long)gk * 256 + col0 + c] : 0.0f;
        }
        __syncthreads();
#pragma unroll
        for (int kk = 0; kk < 32; kk++) {
            float a[4];
#pragma unroll
            for (int i = 0; i < 4; i++) a[i] = As[(ty * 4 + i) * 33 + kk];
#pragma unroll
            for (int j = 0; j < 8; j++) {
                float b = Bs[kk * 132 + tx + 16 * j];
#pragma unroll
                for (int i = 0; i < 4; i++) acc[i][j] = fmaf(a[i], b, acc[i][j]);
            }
        }
        __syncthreads();
    }
#pragma unroll
    for (int i = 0; i < 4; i++) {
        int r = row0 + ty * 4 + i;
        if (r < rows) {
#pragma unroll
            for (int j = 0; j < 8; j++) {
                int col = col0 + tx + 16 * j;
                float v = acc[i][j];
                if (bias) v += bias[col];
                if (act == 1) v = gelu_f(v);
                if (foldt >= 0) {
                    int t = foldt + (r >> 5);
                    size_t base = (size_t)t * 16384 + (size_t)col * 32 + (r & 31);
                    __nv_bfloat16 vh = __float2bfloat16(v);
                    wt[base] = vh;
                    wt[base + 8192] = __float2bfloat16(v - __bfloat162float(vh));
                } else if (z == 0) {
                    h[(long)r * 256 + col] = v;
                    __nv_bfloat16 vh = __float2bfloat16(v);
                    hh[(long)r * 256 + col] = vh;
                    hl[(long)r * 256 + col] = __float2bfloat16(v - __bfloat162float(vh));
                } else {
                    wr2[(long)r * 256 + col] = v;
                }
            }
        }
    }
}

// fp32 -> hi/lo bf16
__global__ void conv_hilo(const float* __restrict__ x, __nv_bfloat16* __restrict__ xh,
                          __nv_bfloat16* __restrict__ xl, int total) {
    int i = blockIdx.x * blockDim.x + threadIdx.x;
    if (i < total) {
        float v = x[i];
        __nv_bfloat16 h = __float2bfloat16(v);
        xh[i] = h;
        xl[i] = __float2bfloat16(v - __bfloat162float(h));
    }
}

// ---------------------------------------------------------------------------
// edge combine (vectorized, from R15)
// ---------------------------------------------------------------------------
__global__ __launch_bounds__(256, 2) void edge_combine(
    const float* __restrict__ dists, const float* __restrict__ freq,
    const float* __restrict__ wr2, const float* __restrict__ p,
    const float* __restrict__ q, const float* __restrict__ cz,
    const int* __restrict__ edge_index,
    __half* __restrict__ a1h, __half* __restrict__ a1l, int E) {
    __shared__ float Rs[64 * 33];
    __shared__ float Bs[32 * 256];
    __shared__ float s_freq[32];
    __shared__ float s_cz[256];
    __shared__ int s_src[64], s_dst[64];
    int tid = threadIdx.x, tx = tid & 15, ty = tid >> 4;
    int e0 = blockIdx.x * 64;
    if (tid < 32) s_freq[tid] = freq[tid];
    s_cz[tid] = cz[tid];
    if (tid < 64) {
        int e = e0 + tid;
        s_src[tid] = (e < E) ? edge_index[e] : 0;
        s_dst[tid] = (e < E) ? edge_index[E + e] : 0;
    }
#pragma unroll
    for (int i = 0; i < 32; i++) Bs[i * 256 + tid] = wr2[i * 256 + tid];
    __syncthreads();
#pragma unroll
    for (int i = 0; i < 8; i++) {
        int idx = tid + i * 256, el = idx >> 5, r = idx & 31;
        int e = e0 + el;
        float d = (e < E) ? dists[e] * 0.2f : 1.0f;
        float d2 = d * d, d5 = d2 * d2 * d;
        float env = 1.0f / d + d5 * (-28.0f + d * (48.0f + d * (-21.0f)));
        Rs[el * 33 + r] = env * sinf(s_freq[r] * d);
    }
    __syncthreads();
    float2 acc[4][8];
#pragma unroll
    for (int i = 0; i < 4; i++)
#pragma unroll
        for (int j = 0; j < 8; j++) { acc[i][j].x = 0.0f; acc[i][j].y = 0.0f; }
#pragma unroll
    for (int kk = 0; kk < 32; kk++) {
        float a[4];
#pragma unroll
        for (int i = 0; i < 4; i++) a[i] = Rs[(ty * 4 + i) * 33 + kk];
#pragma unroll
        for (int j = 0; j < 8; j++) {
            float2 b = *(const float2*)&Bs[kk * 256 + tx * 2 + 32 * j];
#pragma unroll
            for (int i = 0; i < 4; i++) {
                acc[i][j].x = fmaf(a[i], b.x, acc[i][j].x);
                acc[i][j].y = fmaf(a[i], b.y, acc[i][j].y);
            }
        }
    }
#pragma unroll
    for (int i = 0; i < 4; i++) {
        int r = ty * 4 + i;
        int e = e0 + r;
        if (e < E) {
            const float* prow = p + (size_t)s_src[r] * 256;
            const float* qrow = q + (size_t)s_dst[r] * 256;
#pragma unroll
            for (int j = 0; j < 8; j++) {
                int col = tx * 2 + 32 * j;
                float2 pv = *(const float2*)(prow + col);
                float2 qv = *(const float2*)(qrow + col);
                float v0 = lrelu_f(acc[i][j].x + pv.x + qv.x + s_cz[col]);
                float v1 = lrelu_f(acc[i][j].y + pv.y + qv.y + s_cz[col + 1]);
                __half h0 = __float2half(v0);
                __half h1 = __float2half(v1);
                __half2 hp; hp.x = h0; hp.y = h1;
                __half2 lp;
                lp.x = __float2half(v0 - __half2float(h0));
                lp.y = __float2half(v1 - __half2float(h1));
                *(__half2*)(a1h + (size_t)e * 256 + col) = hp;
                *(__half2*)(a1l + (size_t)e * 256 + col) = lp;
            }
        }
    }
}

// ---------------------------------------------------------------------------
// fp16 HMMA fused edge MLP (layers 2..4). CTA = 64 edges, 8 warps, 2 CTAs/SM.
// Per-SMSP named-barrier groups of 2 warps (64 threads). Two co-resident CTAs
// interleave to hide barrier/epilogue stalls.
// ---------------------------------------------------------------------------
__global__ __launch_bounds__(256, 2) void edge_mlp_hmma(
    const __half* __restrict__ a1h, const __half* __restrict__ a1l,
    const int* __restrict__ edge_index, const __half* __restrict__ wte,
    const float* __restrict__ b2, const float* __restrict__ b3,
    const float* __restrict__ b4, float* __restrict__ agg, int E) {
    extern __shared__ __align__(16) char dsm[];
    __shared__ int s_dst[64];
    __shared__ float s_bias[768];

    const int tid = threadIdx.x;
    const int wid = tid >> 5, lane = tid & 31;
    const int wm = wid >> 2, wn = wid & 3;      // wm 0..1, wn 0..3
    const int r0 = wm * 32;
    const int c0 = wn * 64;
    const int gtid = lane + wm * 32;            // 0..63 within N-group wn
    const int e0 = blockIdx.x * 64;
    const uint32_t sb = smem_u32(dsm);

    for (int i = tid; i < 768; i += 256) {
        const float* b = (i < 256) ? b2 : (i < 512) ? b3 : b4;
        s_bias[i] = b[i & 255];
    }
    if (tid < 64) {
        int e = e0 + tid;
        s_dst[tid] = (e < E) ? edge_index[E + e] : 0;
    }

    float acc[2][8][4];
#pragma unroll
    for (int mt = 0; mt < 2; mt++)
#pragma unroll
        for (int nt = 0; nt < 8; nt++)
#pragma unroll
            for (int i = 0; i < 4; i++) acc[mt][nt][i] = 0.0f;

    auto groupbar = [&]() {
        asm volatile("bar.sync %0, 64;" :: "r"(1 + wn) : "memory");
    };
    // group B slice: cols [c0, c0+64), 64 B data per col @80B stride; 256 x 16B / 64 thr
    auto prefetchB = [&](int t, int buf) {
        const char* wsrc = (const char*)wte + (size_t)t * 16384;
        uint32_t dbase = sb + E_BBUF + buf * 20480;
#pragma unroll
        for (int it = 0; it < 4; it++) {
            int id = gtid + it * 64;         // 0..255
            int nl = id >> 2, seg = id & 3;
            int n = c0 + nl;
            cp_async16(dbase + (uint32_t)n * 80 + seg * 16,
                       wsrc + (size_t)n * 64 + seg * 16);
        }
    };
    auto loadACT = [&]() {
#pragma unroll
        for (int it = 0; it < 16; it++) {
            int id = tid + it * 256;         // 0..4095
            int seg = id & 31;
            int hl = (id >> 5) & 1;
            int row = id >> 6;               // 0..63
            int e = e0 + row;
            if (e >= E) e = E - 1;
            const char* sp = (const char*)(hl ? a1l : a1h) + (size_t)e * 512 + seg * 16;
            cp_async16(sb + (hl ? E_ACT_LO : ACT_HI) + (uint32_t)row * 528 + seg * 16, sp);
        }
    };
    auto compute = [&](uint32_t abase, uint32_t bbase) {
#pragma unroll
        for (int s = 0; s < 2; s++) {
            int ko2 = s * 32;
            uint32_t ah[2][4], al[2][4];
#pragma unroll
            for (int mt = 0; mt < 2; mt++) {
                uint32_t ad = abase + (uint32_t)(r0 + mt * 16 + (lane & 15)) * 528 +
                              ko2 + ((lane >> 4) << 4);
                ldsm4(ah[mt], ad);
                ldsm4(al[mt], ad + E_ACT_LO);
            }
#pragma unroll
            for (int q = 0; q < 4; q++) {
                int n = c0 + q * 16 + (lane & 7) + ((lane & 16) >> 1);
                uint32_t bd = bbase + (uint32_t)n * 80 + ko2 + ((lane & 8) << 1);
                uint32_t bb[4];
                ldsm4(bb, bd);
#pragma unroll
                for (int mt = 0; mt < 2; mt++) {
                    mma16816h(acc[mt][2 * q + 0], ah[mt], bb[0], bb[1]);
                    mma16816h(acc[mt][2 * q + 1], ah[mt], bb[2], bb[3]);
                    mma16816h(acc[mt][2 * q + 0], al[mt], bb[0], bb[1]);
                    mma16816h(acc[mt][2 * q + 1], al[mt], bb[2], bb[3]);
                }
            }
        }
    };
    auto epilogue_act = [&](int bidx) {
#pragma unroll
        for (int mt = 0; mt < 2; mt++) {
#pragma unroll
            for (int nt = 0; nt < 8; nt++) {
                int ra = r0 + mt * 16 + (lane >> 2);
                int ca = c0 + nt * 8 + 2 * (lane & 3);
                float bv0 = s_bias[bidx * 256 + ca], bv1 = s_bias[bidx * 256 + ca + 1];
#pragma unroll
                for (int half = 0; half < 2; half++) {
                    int r = ra + half * 8;
                    float v0 = lrelu_f(acc[mt][nt][half * 2 + 0] + bv0);
                    float v1 = lrelu_f(acc[mt][nt][half * 2 + 1] + bv1);
                    __half h0 = __float2half(v0);
                    __half h1 = __float2half(v1);
                    __half2 hp; hp.x = h0; hp.y = h1;
                    __half2 lp;
                    lp.x = __float2half(v0 - __half2float(h0));
                    lp.y = __float2half(v1 - __half2float(h1));
                    uint32_t off = (uint32_t)r * 528 + (uint32_t)ca * 2;
                    *(__half2*)(dsm + ACT_HI + off) = hp;
                    *(__half2*)(dsm + E_ACT_LO + off) = lp;
                    acc[mt][nt][half * 2 + 0] = 0.0f;
                    acc[mt][nt][half * 2 + 1] = 0.0f;
                }
            }
        }
    };

    loadACT();
    prefetchB(0, 0);
    CP_COMMIT();
    prefetchB(1, 1);
    CP_COMMIT();

    for (int g = 0; g < 24; g++) {
        if (g < 23) { CP_WAIT1(); } else { CP_WAIT0(); }
        if (g == 0 || g == 8 || g == 16) __syncthreads();
        else groupbar();
        compute(sb + ACT_HI + (uint32_t)(g & 7) * 64, sb + E_BBUF + (g & 1) * 20480);
        if (g + 2 < 24) {
            groupbar();
            prefetchB(g + 2, g & 1);
            CP_COMMIT();
        }
        if (g == 7 || g == 15) {
            __syncthreads();
            epilogue_act(g >> 3);
        } else if (g == 23) {
            __syncthreads();
#pragma unroll
            for (int mt = 0; mt < 2; mt++) {
#pragma unroll
                for (int nt = 0; nt < 8; nt++) {
                    int ra = r0 + mt * 16 + (lane >> 2);
                    int ca = c0 + nt * 8 + 2 * (lane & 3);
                    float bv0 = s_bias[512 + ca], bv1 = s_bias[512 + ca + 1];
#pragma unroll
                    for (int half = 0; half < 2; half++) {
                        int r = ra + half * 8;
                        float2 v;
                        v.x = acc[mt][nt][half * 2 + 0] + bv0;
                        v.y = acc[mt][nt][half * 2 + 1] + bv1;
                        *(float2*)(dsm + (uint32_t)r * 1024 + (uint32_t)ca * 4) = v;
                    }
                }
            }
            FENCE_ASYNC();
            __syncthreads();
            if (tid < 64 && (e0 + tid) < E) {
                bulk_reduce_add_f32(agg + (size_t)s_dst[tid] * 256,
                                    sb + (uint32_t)tid * 1024, 1024);
            }
            BULK_COMMIT();
            BULK_WAIT0();
        }
    }
}

// ---------------------------------------------------------------------------
// Node HMMA GEMM (bf16 3-product, unchanged — validated).
// ---------------------------------------------------------------------------
__global__ __launch_bounds__(512, 1) void node_hmma(
    const __nv_bfloat16* __restrict__ Ah, const __nv_bfloat16* __restrict__ Al,
    const __nv_bfloat16* __restrict__ wt, int tb0, int tb1,
    const float* __restrict__ bias, const float* __restrict__ res,
    float* __restrict__ C0, float* __restrict__ C1,
    __nv_bfloat16* __restrict__ Ch, __nv_bfloat16* __restrict__ Cl,
    float* __restrict__ zbuf, int rows, int act) {
    extern __shared__ __align__(16) char dsm[];
    const int tid = threadIdx.x;
    const int wid = tid >> 5, lane = tid & 31;
    const int wm = wid >> 2, wn = wid & 3;
    const int r0 = wm * 32;
    const int c0 = wn * 64;
    const int gtid = lane + wm * 32;
    const int e0 = blockIdx.x * 128;
    const uint32_t sb = smem_u32(dsm);
    const int tb = blockIdx.y ? tb1 : tb0;
    float* C = blockIdx.y ? C1 : C0;
    if (e0 >= rows) return;

    float acc[2][8][4];
#pragma unroll
    for (int mt = 0; mt < 2; mt++)
#pragma unroll
        for (int nt = 0; nt < 8; nt++)
#pragma unroll
            for (int i = 0; i < 4; i++) acc[mt][nt][i] = 0.0f;

    auto groupbar = [&]() {
        asm volatile("bar.sync %0, 128;" :: "r"(1 + wn) : "memory");
    };
    auto prefetchB = [&](int t, int buf) {
        const char* wsrc = (const char*)wt + (size_t)(tb + t) * 32768;
        uint32_t dbase = sb + BBUF + buf * 40960;
#pragma unroll
        for (int it = 0; it < 4; it++) {
            int id = gtid + it * 128;
            int hl = id >> 8;
            int rest = id & 255;
            int nl = rest >> 2, seg = rest & 3;
            int n = c0 + nl;
            cp_async16(dbase + hl * 20480 + (uint32_t)n * 80 + seg * 16,
                       wsrc + hl * 16384 + (size_t)n * 64 + seg * 16);
        }
    };
    auto loadACT = [&]() {
#pragma unroll
        for (int it = 0; it < 16; it++) {
            int id = tid + it * 512;
            int seg = id & 31;
            int hl = (id >> 5) & 1;
            int row = id >> 6;
            int e = e0 + row;
            if (e >= rows) e = rows - 1;
            const char* sp = (const char*)(hl ? Al : Ah) + (size_t)e * 512 + seg * 16;
            cp_async16(sb + (hl ? ACT_LO : ACT_HI) + (uint32_t)row * 528 + seg * 16, sp);
        }
    };
    auto compute = [&](uint32_t abase, uint32_t bbase) {
#pragma unroll
        for (int s = 0; s < 2; s++) {
            int ko2 = s * 32;
            uint32_t ah[2][4], al[2][4];
#pragma unroll
            for (int mt = 0; mt < 2; mt++) {
                uint32_t ad = abase + (uint32_t)(r0 + mt * 16 + (lane & 15)) * 528 +
                              ko2 + ((lane >> 4) << 4);
                ldsm4(ah[mt], ad);
                ldsm4(al[mt], ad + (ACT_LO - ACT_HI));
            }
#pragma unroll
            for (int q = 0; q < 4; q++) {
                int n = c0 + q * 16 + (lane & 7) + ((lane & 16) >> 1);
                uint32_t bd = bbase + (uint32_t)n * 80 + ko2 + ((lane & 8) << 1);
                uint32_t bh[4], bl[4];
                ldsm4(bh, bd);
                ldsm4(bl, bd + 20480);
#pragma unroll
                for (int mt = 0; mt < 2; mt++) {
                    mma16816(acc[mt][2 * q + 0], ah[mt], bh[0], bh[1]);
                    mma16816(acc[mt][2 * q + 1], ah[mt], bh[2], bh[3]);
                    mma16816(acc[mt][2 * q + 0], al[mt], bh[0], bh[1]);
                    mma16816(acc[mt][2 * q + 1], al[mt], bh[2], bh[3]);
                    mma16816(acc[mt][2 * q + 0], ah[mt], bl[0], bl[1]);
                    mma16816(acc[mt][2 * q + 1], ah[mt], bl[2], bl[3]);
                }
            }
        }
    };

    loadACT();
    prefetchB(0, 0);
    CP_COMMIT();
    prefetchB(1, 1);
    CP_COMMIT();

    if (zbuf && blockIdx.y == 0) {
#pragma unroll
        for (int it = 0; it < 16; it++) {
            int id = tid + it * 512;
            int row = id >> 6;
            int e = e0 + row;
            if (e < rows) {
                float4 z = {0.0f, 0.0f, 0.0f, 0.0f};
                *(float4*)(zbuf + (size_t)e * 256 + (id & 63) * 4) = z;
            }
        }
    }

    for (int g = 0; g < 8; g++) {
        if (g < 7) { CP_WAIT1(); } else { CP_WAIT0(); }
        if (g == 0) __syncthreads();
        else groupbar();
        compute(sb + ACT_HI + (uint32_t)g * 64, sb + BBUF + (g & 1) * 40960);
        if (g + 2 < 8) {
            groupbar();
            prefetchB(g + 2, g & 1);
            CP_COMMIT();
        }
    }

#pragma unroll
    for (int mt = 0; mt < 2; mt++) {
#pragma unroll
        for (int nt = 0; nt < 8; nt++) {
            int ra = r0 + mt * 16 + (lane >> 2);
            int ca = c0 + nt * 8 + 2 * (lane & 3);
            float bv0 = bias ? __ldg(bias + ca) : 0.0f;
            float bv1 = bias ? __ldg(bias + ca + 1) : 0.0f;
#pragma unroll
            for (int half = 0; half < 2; half++) {
                int r = e0 + ra + half * 8;
                if (r < rows) {
                    float v0 = acc[mt][nt][half * 2 + 0] + bv0;
                    float v1 = acc[mt][nt][half * 2 + 1] + bv1;
                    if (act == 1) { v0 = gelu_f(v0); v1 = gelu_f(v1); }
                    if (res) {
                        float2 rv = *(const float2*)(res + (size_t)r * 256 + ca);
                        v0 += rv.x; v1 += rv.y;
                    }
                    if (C) {
                        float2 o; o.x = v0; o.y = v1;
                        *(float2*)(C + (size_t)r * 256 + ca) = o;
                    }
                    if (Ch) {
                        __nv_bfloat16 h0 = __float2bfloat16(v0);
                        __nv_bfloat16 h1 = __float2bfloat16(v1);
                        __nv_bfloat162 hp; hp.x = h0; hp.y = h1;
                        __nv_bfloat162 lp;
                        lp.x = __float2bfloat16(v0 - __bfloat162float(h0));
                        lp.y = __float2bfloat16(v1 - __bfloat162float(h1));
                        *(__nv_bfloat162*)(Ch + (size_t)r * 256 + ca) = hp;
                        *(__nv_bfloat162*)(Cl + (size_t)r * 256 + ca) = lp;
                    }
                }
            }
        }
    }
}

// ---------------------------------------------------------------------------
extern "C" void kernel_launch(void* const* d_in, const int* in_sizes, int n_in,
                              void* d_out, int out_size) {
    const int* atom_types = (const int*)d_in[0];
    const float* x_extra = (const float*)d_in[1];
    const int* edge_index = (const int*)d_in[2];
    const float* dists = (const float*)d_in[3];
    const float* freq = (const float*)d_in[4];
    const float* emb_table = (const float*)d_in[5];
    const float* w_emb = (const float*)d_in[6];
    const float* b_emb = (const float*)d_in[7];
    const float* w_n2m = (const float*)d_in[8];
    const float* b_n2m = (const float*)d_in[9];
    const float* w_r2m = (const float*)d_in[10];
    const float* b_r2m = (const float*)d_in[11];
    const float* w_m2n = (const float*)d_in[12];
    const float* mw1 = (const float*)d_in[13];
    const float* mb1 = (const float*)d_in[14];
    const float* mw2 = (const float*)d_in[15];
    const float* mb2 = (const float*)d_in[16];
    const float* mw3 = (const float*)d_in[17];
    const float* mb3 = (const float*)d_in[18];
    const float* mw4 = (const float*)d_in[19];
    const float* mb4 = (const float*)d_in[20];
    const float* fw1 = (const float*)d_in[21];
    const float* fb1 = (const float*)d_in[22];
    const float* fw2 = (const float*)d_in[23];
    const float* fb2 = (const float*)d_in[24];
    float* out = (float*)d_out;

    int N = in_sizes[0];
    int E = in_sizes[2] / 2;

    float *p_h, *p_p, *p_q, *p_agg, *p_t, *p_wr2, *p_cz;
    __nv_bfloat16 *p_hh, *p_hl, *p_aggh, *p_aggl, *p_th, *p_tl, *p_uh, *p_ul, *p_wt;
    __half *p_a1h, *p_a1l, *p_wte;
    cudaGetSymbolAddress((void**)&p_h, g_h);
    cudaGetSymbolAddress((void**)&p_p, g_p);
    cudaGetSymbolAddress((void**)&p_q, g_q);
    cudaGetSymbolAddress((void**)&p_agg, g_agg);
    cudaGetSymbolAddress((void**)&p_t, g_t);
    cudaGetSymbolAddress((void**)&p_wr2, g_wr2);
    cudaGetSymbolAddress((void**)&p_cz, g_cz);
    cudaGetSymbolAddress((void**)&p_hh, g_hh);
    cudaGetSymbolAddress((void**)&p_hl, g_hl);
    cudaGetSymbolAddress((void**)&p_aggh, g_aggh);
    cudaGetSymbolAddress((void**)&p_aggl, g_aggl);
    cudaGetSymbolAddress((void**)&p_th, g_th);
    cudaGetSymbolAddress((void**)&p_tl, g_tl);
    cudaGetSymbolAddress((void**)&p_uh, g_uh);
    cudaGetSymbolAddress((void**)&p_ul, g_ul);
    cudaGetSymbolAddress((void**)&p_a1h, g_a1h);
    cudaGetSymbolAddress((void**)&p_a1l, g_a1l);
    cudaGetSymbolAddress((void**)&p_wt, g_wt);
    cudaGetSymbolAddress((void**)&p_wte, g_wte);

    cudaFuncSetAttribute(edge_mlp_hmma, cudaFuncAttributeMaxDynamicSharedMemorySize, DSMEM_E);
    cudaFuncSetAttribute(node_hmma, cudaFuncAttributeMaxDynamicSharedMemorySize, DSMEM_N);

    dim3 gMega((N + 63) / 64, 2, 5);
    int gE64 = (E + 63) / 64;
    int gNode = (N + 127) / 128;
    dim3 gPQ(gNode, 2);
    dim3 gN1(gNode, 1);

    k0_mega<<<gMega, 256>>>(atom_types, x_extra, emb_table, w_emb, b_emb,
                            w_n2m, b_n2m, w_r2m, b_r2m, mw1, mb1, mw2, mw3, mw4,
                            w_m2n, fw1, fw2, p_h, p_hh, p_hl, p_wr2, p_cz,
                            p_wt, p_wte, N);
    node_hmma<<<gPQ, 512, DSMEM_N>>>(p_hh, p_hl, p_wt, 48, 56, nullptr, nullptr,
                                     p_p, p_q, nullptr, nullptr, p_agg, N, 0);
    edge_combine<<<gE64, 256>>>(dists, freq, p_wr2, p_p, p_q, p_cz, edge_index,
                                p_a1h, p_a1l, E);
    edge_mlp_hmma<<<gE64, 256, DSMEM_E>>>(p_a1h, p_a1l, edge_index, p_wte,
                                          mb2, mb3, mb4, p_agg, E);
    conv_hilo<<<(N * 256 + 255) / 256, 256>>>(p_agg, p_aggh, p_aggl, N * 256);
    node_hmma<<<gN1, 512, DSMEM_N>>>(p_aggh, p_aggl, p_wt, 24, 24, nullptr, p_h,
                                     p_t, nullptr, p_th, p_tl, nullptr, N, 0);
    node_hmma<<<gN1, 512, DSMEM_N>>>(p_th, p_tl, p_wt, 32, 32, fb1, nullptr,
                                     nullptr, nullptr, p_uh, p_ul, nullptr, N, 1);
    node_hmma<<<gN1, 512, DSMEM_N>>>(p_uh, p_ul, p_wt, 40, 40, fb2, p_t,
                                     out, nullptr, nullptr, nullptr, nullptr, N, 0);
}

// round 17
// speedup vs baseline: 2.1120x; 1.0666x over previous
#include <cuda_runtime.h>
#include <cuda_bf16.h>
#include <cuda_fp16.h>
#include <math.h>
#include <stdint.h>

#define NN 10000
#define EE 160000
#define HH 256

// ---------------------------------------------------------------------------
// Scratch (no runtime allocation allowed)
// ---------------------------------------------------------------------------
__device__ float g_h[NN * HH];
__device__ float g_p[NN * HH];
__device__ float g_q[NN * HH];
__device__ float g_agg[NN * HH];
__device__ float g_t[NN * HH];
__device__ float g_wr2[32 * 256];
__device__ float g_cz[256];
__device__ __half g_hh[NN * HH], g_hl[NN * HH];
__device__ __half g_aggh[NN * HH], g_aggl[NN * HH];
__device__ __half g_th[NN * HH], g_tl[NN * HH];
__device__ __half g_uh[NN * HH], g_ul[NN * HH];
// act1 hi/lo fp16, [E, 256]
__device__ __half g_a1h[(size_t)EE * HH];
__device__ __half g_a1l[(size_t)EE * HH];
// All W^T tiles fp16 SINGLE (8192 half = 16KB each):
// 0..7 W2 | 8..15 W3 | 16..23 W4 | 24..31 w_m2n | 32..39 fw1 | 40..47 fw2
// 48..55 wpa (runtime fold) | 56..63 wqb (runtime fold)
__device__ __align__(16) __half g_wte[64 * 8192];

__device__ __forceinline__ float gelu_f(float x) {
    float x3 = x * x * x;
    return 0.5f * x * (1.0f + tanhf(0.7978845608028654f * (x + 0.044715f * x3)));
}
__device__ __forceinline__ float lrelu_f(float x) { return x > 0.0f ? x : 0.01f * x; }

// ---------------------------------------------------------------------------
// PTX helpers (sm_80/sm_90 base ISA: valid at .target sm_100)
// ---------------------------------------------------------------------------
__device__ __forceinline__ uint32_t smem_u32(const void* p) {
    uint32_t a;
    asm("{ .reg .u64 t; cvta.to.shared.u64 t, %1; cvt.u32.u64 %0, t; }" : "=r"(a) : "l"(p));
    return a;
}
__device__ __forceinline__ void cp_async16(uint32_t smem_addr, const void* gptr) {
    asm volatile("cp.async.cg.shared.global [%0], [%1], 16;\n" :: "r"(smem_addr), "l"(gptr));
}
#define CP_COMMIT() asm volatile("cp.async.commit_group;\n" ::: "memory")
#define CP_WAIT0()  asm volatile("cp.async.wait_group 0;\n" ::: "memory")
#define CP_WAIT1()  asm volatile("cp.async.wait_group 1;\n" ::: "memory")

__device__ __forceinline__ void bulk_reduce_add_f32(void* gdst, uint32_t ssrc, uint32_t bytes) {
    asm volatile("cp.reduce.async.bulk.global.shared::cta.bulk_group.add.f32 [%0], [%1], %2;\n"
                 :: "l"(gdst), "r"(ssrc), "r"(bytes) : "memory");
}
#define BULK_COMMIT() asm volatile("cp.async.bulk.commit_group;" ::: "memory")
#define BULK_WAIT0()  asm volatile("cp.async.bulk.wait_group 0;" ::: "memory")
#define FENCE_ASYNC() asm volatile("fence.proxy.async.shared::cta;" ::: "memory")

__device__ __forceinline__ void ldsm4(uint32_t* f, uint32_t a) {
    asm volatile("ldmatrix.sync.aligned.m8n8.x4.shared.b16 {%0,%1,%2,%3}, [%4];\n"
                 : "=r"(f[0]), "=r"(f[1]), "=r"(f[2]), "=r"(f[3]) : "r"(a));
}
__device__ __forceinline__ void mma16816h(float* d, const uint32_t* a, uint32_t b0, uint32_t b1) {
    asm volatile(
        "mma.sync.aligned.m16n8k16.row.col.f32.f16.f16.f32 "
        "{%0,%1,%2,%3}, {%4,%5,%6,%7}, {%8,%9}, {%0,%1,%2,%3};\n"
        : "+f"(d[0]), "+f"(d[1]), "+f"(d[2]), "+f"(d[3])
        : "r"(a[0]), "r"(a[1]), "r"(a[2]), "r"(a[3]), "r"(b0), "r"(b1));
}

// SMEM layout — 64-row fp16 kernels (edge + node), 2 CTAs/SM
#define ACT_HI   0
#define E_ACT_LO 33792
#define E_BBUF   67584
#define DSMEM_E  108544           // 67584 + 2 x 20480

// ---------------------------------------------------------------------------
// Mega kernel 0:
//   z=0 -> h = gelu(xcat@w_emb+b) (gathered) + h hi/lo fp16
//   z=1 -> wpa fold -> wte tiles 48..55 ; z=2 -> wqb fold -> 56..63
//   z=3 -> wr2 = w_r2m @ mw1c (rows=32, fp32)
//   z=4 -> flat prep: wte fp16 tiles (W2/3/4/m2n/fw1/fw2) + cz
// ---------------------------------------------------------------------------
__global__ __launch_bounds__(256, 2) void k0_mega(
    const int* __restrict__ atom_types, const float* __restrict__ x_extra,
    const float* __restrict__ emb_table,
    const float* __restrict__ w_emb, const float* __restrict__ b_emb,
    const float* __restrict__ w_n2m, const float* __restrict__ b_n2m,
    const float* __restrict__ w_r2m, const float* __restrict__ b_r2m,
    const float* __restrict__ mw1, const float* __restrict__ mb1,
    const float* __restrict__ mw2, const float* __restrict__ mw3,
    const float* __restrict__ mw4, const float* __restrict__ w_m2n,
    const float* __restrict__ fw1, const float* __restrict__ fw2,
    float* __restrict__ h, __half* __restrict__ hh, __half* __restrict__ hl,
    float* __restrict__ wr2, float* __restrict__ cz,
    __half* __restrict__ wte, int N) {
    int z = blockIdx.z;
    if (z == 4) {
        int bid = blockIdx.x * 2 + blockIdx.y;
        int flat = bid * 256 + (int)threadIdx.x;
        for (int item = flat; item < 393472; item += 80384) {
            if (item < 393216) {
                int kg = item >> 8, n = item & 255;
                const float* w; int kl, t;
                if (kg < 256)       { w = mw2;   kl = kg;        t = (kl >> 5); }
                else if (kg < 512)  { w = mw3;   kl = kg - 256;  t = 8 + (kl >> 5); }
                else if (kg < 768)  { w = mw4;   kl = kg - 512;  t = 16 + (kl >> 5); }
                else if (kg < 1024) { w = w_m2n; kl = kg - 768;  t = 24 + (kl >> 5); }
                else if (kg < 1280) { w = fw1;   kl = kg - 1024; t = 32 + (kl >> 5); }
                else                { w = fw2;   kl = kg - 1280; t = 40 + (kl >> 5); }
                int kk = kl & 31;
                wte[(size_t)t * 8192 + n * 32 + kk] = __float2half(w[(long)kl * 256 + n]);
            } else {
                int n = item - 393216;
                float s = mb1[n];
                for (int k = 0; k < 256; k++) {
                    s += b_n2m[k] * (mw1[(long)k * 256 + n] + mw1[(long)(256 + k) * 256 + n]);
                    s += b_r2m[k] * mw1[(long)(512 + k) * 256 + n];
                }
                cz[n] = s;
            }
        }
        return;
    }

    __shared__ float As[64 * 33];
    __shared__ float Bs[32 * 132];
    const float* A = nullptr;
    const float* W;
    const float* bias = nullptr;
    int K, rows, act = 0, foldt = -1;
    bool gather = false;
    if (z == 0)      { gather = true; K = 48; W = w_emb; bias = b_emb; rows = N; act = 1; }
    else if (z == 1) { A = w_n2m; K = 256; W = mw1;          rows = 256; foldt = 48; }
    else if (z == 2) { A = w_n2m; K = 256; W = mw1 + 65536;  rows = 256; foldt = 56; }
    else             { A = w_r2m; K = 256; W = mw1 + 131072; rows = 32; }

    int tid = threadIdx.x, tx = tid & 15, ty = tid >> 4;
    int row0 = blockIdx.x * 64;
    int col0 = blockIdx.y * 128;
    if (row0 >= rows) return;

    float acc[4][8];
#pragma unroll
    for (int i = 0; i < 4; i++)
#pragma unroll
        for (int j = 0; j < 8; j++) acc[i][j] = 0.0f;
    for (int k0 = 0; k0 < K; k0 += 32) {
#pragma unroll
        for (int i = 0; i < 8; i++) {
            int idx = tid + i * 256, r = idx >> 5, c = idx & 31;
            int gr = row0 + r, gk = k0 + c;
            float v = 0.0f;
            if (gr < rows && gk < K) {
                if (gather)
                    v = (gk < 32) ? emb_table[atom_types[gr] * 32 + gk]
                                  : x_extra[gr * 16 + gk - 32];
                else
                    v = A[(long)gr * K + gk];
            }
            As[r * 33 + c] = v;
        }
#pragma unroll
        for (int i = 0; i < 16; i++) {
            int idx = tid + i * 256, r = idx >> 7, c = idx & 127;
            int gk = k0 + r;
            Bs[r * 132 + c] = (gk < K) ? W[(long)gk * 256 + col0 + c] : 0.0f;
        }
        __syncthreads();
#pragma unroll
        for (int kk = 0; kk < 32; kk++) {
            float a[4];
#pragma unroll
            for (int i = 0; i < 4; i++) a[i] = As[(ty * 4 + i) * 33 + kk];
#pragma unroll
            for (int j = 0; j < 8; j++) {
                float b = Bs[kk * 132 + tx + 16 * j];
#pragma unroll
                for (int i = 0; i < 4; i++) acc[i][j] = fmaf(a[i], b, acc[i][j]);
            }
        }
        __syncthreads();
    }
#pragma unroll
    for (int i = 0; i < 4; i++) {
        int r = row0 + ty * 4 + i;
        if (r < rows) {
#pragma unroll
            for (int j = 0; j < 8; j++) {
                int col = col0 + tx + 16 * j;
                float v = acc[i][j];
                if (bias) v += bias[col];
                if (act == 1) v = gelu_f(v);
                if (foldt >= 0) {
                    int t = foldt + (r >> 5);
                    wte[(size_t)t * 8192 + (size_t)col * 32 + (r & 31)] = __float2half(v);
                } else if (z == 0) {
                    h[(long)r * 256 + col] = v;
                    __half vh = __float2half(v);
                    hh[(long)r * 256 + col] = vh;
                    hl[(long)r * 256 + col] = __float2half(v - __half2float(vh));
                } else {
                    wr2[(long)r * 256 + col] = v;
                }
            }
        }
    }
}

// fp32 -> hi/lo fp16
__global__ void conv_hilo(const float* __restrict__ x, __half* __restrict__ xh,
                          __half* __restrict__ xl, int total) {
    int i = blockIdx.x * blockDim.x + threadIdx.x;
    if (i < total) {
        float v = x[i];
        __half h = __float2half(v);
        xh[i] = h;
        xl[i] = __float2half(v - __half2float(h));
    }
}

// ---------------------------------------------------------------------------
// edge combine (vectorized, from R15 — validated)
// ---------------------------------------------------------------------------
__global__ __launch_bounds__(256, 2) void edge_combine(
    const float* __restrict__ dists, const float* __restrict__ freq,
    const float* __restrict__ wr2, const float* __restrict__ p,
    const float* __restrict__ q, const float* __restrict__ cz,
    const int* __restrict__ edge_index,
    __half* __restrict__ a1h, __half* __restrict__ a1l, int E) {
    __shared__ float Rs[64 * 33];
    __shared__ float Bs[32 * 256];
    __shared__ float s_freq[32];
    __shared__ float s_cz[256];
    __shared__ int s_src[64], s_dst[64];
    int tid = threadIdx.x, tx = tid & 15, ty = tid >> 4;
    int e0 = blockIdx.x * 64;
    if (tid < 32) s_freq[tid] = freq[tid];
    s_cz[tid] = cz[tid];
    if (tid < 64) {
        int e = e0 + tid;
        s_src[tid] = (e < E) ? edge_index[e] : 0;
        s_dst[tid] = (e < E) ? edge_index[E + e] : 0;
    }
#pragma unroll
    for (int i = 0; i < 32; i++) Bs[i * 256 + tid] = wr2[i * 256 + tid];
    __syncthreads();
#pragma unroll
    for (int i = 0; i < 8; i++) {
        int idx = tid + i * 256, el = idx >> 5, r = idx & 31;
        int e = e0 + el;
        float d = (e < E) ? dists[e] * 0.2f : 1.0f;
        float d2 = d * d, d5 = d2 * d2 * d;
        float env = 1.0f / d + d5 * (-28.0f + d * (48.0f + d * (-21.0f)));
        Rs[el * 33 + r] = env * sinf(s_freq[r] * d);
    }
    __syncthreads();
    float2 acc[4][8];
#pragma unroll
    for (int i = 0; i < 4; i++)
#pragma unroll
        for (int j = 0; j < 8; j++) { acc[i][j].x = 0.0f; acc[i][j].y = 0.0f; }
#pragma unroll
    for (int kk = 0; kk < 32; kk++) {
        float a[4];
#pragma unroll
        for (int i = 0; i < 4; i++) a[i] = Rs[(ty * 4 + i) * 33 + kk];
#pragma unroll
        for (int j = 0; j < 8; j++) {
            float2 b = *(const float2*)&Bs[kk * 256 + tx * 2 + 32 * j];
#pragma unroll
            for (int i = 0; i < 4; i++) {
                acc[i][j].x = fmaf(a[i], b.x, acc[i][j].x);
                acc[i][j].y = fmaf(a[i], b.y, acc[i][j].y);
            }
        }
    }
#pragma unroll
    for (int i = 0; i < 4; i++) {
        int r = ty * 4 + i;
        int e = e0 + r;
        if (e < E) {
            const float* prow = p + (size_t)s_src[r] * 256;
            const float* qrow = q + (size_t)s_dst[r] * 256;
#pragma unroll
            for (int j = 0; j < 8; j++) {
                int col = tx * 2 + 32 * j;
                float2 pv = *(const float2*)(prow + col);
                float2 qv = *(const float2*)(qrow + col);
                float v0 = lrelu_f(acc[i][j].x + pv.x + qv.x + s_cz[col]);
                float v1 = lrelu_f(acc[i][j].y + pv.y + qv.y + s_cz[col + 1]);
                __half h0 = __float2half(v0);
                __half h1 = __float2half(v1);
                __half2 hp; hp.x = h0; hp.y = h1;
                __half2 lp;
                lp.x = __float2half(v0 - __half2float(h0));
                lp.y = __float2half(v1 - __half2float(h1));
                *(__half2*)(a1h + (size_t)e * 256 + col) = hp;
                *(__half2*)(a1l + (size_t)e * 256 + col) = lp;
            }
        }
    }
}

// ---------------------------------------------------------------------------
// fp16 HMMA fused edge MLP (layers 2..4) — unchanged from R16 (validated).
// CTA = 64 edges, 8 warps, 2 CTAs/SM, per-SMSP 64-thread named barriers.
// ---------------------------------------------------------------------------
__global__ __launch_bounds__(256, 2) void edge_mlp_hmma(
    const __half* __restrict__ a1h, const __half* __restrict__ a1l,
    const int* __restrict__ edge_index, const __half* __restrict__ wte,
    const float* __restrict__ b2, const float* __restrict__ b3,
    const float* __restrict__ b4, float* __restrict__ agg, int E) {
    extern __shared__ __align__(16) char dsm[];
    __shared__ int s_dst[64];
    __shared__ float s_bias[768];

    const int tid = threadIdx.x;
    const int wid = tid >> 5, lane = tid & 31;
    const int wm = wid >> 2, wn = wid & 3;
    const int r0 = wm * 32;
    const int c0 = wn * 64;
    const int gtid = lane + wm * 32;
    const int e0 = blockIdx.x * 64;
    const uint32_t sb = smem_u32(dsm);

    for (int i = tid; i < 768; i += 256) {
        const float* b = (i < 256) ? b2 : (i < 512) ? b3 : b4;
        s_bias[i] = b[i & 255];
    }
    if (tid < 64) {
        int e = e0 + tid;
        s_dst[tid] = (e < E) ? edge_index[E + e] : 0;
    }

    float acc[2][8][4];
#pragma unroll
    for (int mt = 0; mt < 2; mt++)
#pragma unroll
        for (int nt = 0; nt < 8; nt++)
#pragma unroll
            for (int i = 0; i < 4; i++) acc[mt][nt][i] = 0.0f;

    auto groupbar = [&]() {
        asm volatile("bar.sync %0, 64;" :: "r"(1 + wn) : "memory");
    };
    auto prefetchB = [&](int t, int buf) {
        const char* wsrc = (const char*)wte + (size_t)t * 16384;
        uint32_t dbase = sb + E_BBUF + buf * 20480;
#pragma unroll
        for (int it = 0; it < 4; it++) {
            int id = gtid + it * 64;
            int nl = id >> 2, seg = id & 3;
            int n = c0 + nl;
            cp_async16(dbase + (uint32_t)n * 80 + seg * 16,
                       wsrc + (size_t)n * 64 + seg * 16);
        }
    };
    auto loadACT = [&]() {
#pragma unroll
        for (int it = 0; it < 16; it++) {
            int id = tid + it * 256;
            int seg = id & 31;
            int hl = (id >> 5) & 1;
            int row = id >> 6;
            int e = e0 + row;
            if (e >= E) e = E - 1;
            const char* sp = (const char*)(hl ? a1l : a1h) + (size_t)e * 512 + seg * 16;
            cp_async16(sb + (hl ? E_ACT_LO : ACT_HI) + (uint32_t)row * 528 + seg * 16, sp);
        }
    };
    auto compute = [&](uint32_t abase, uint32_t bbase) {
#pragma unroll
        for (int s = 0; s < 2; s++) {
            int ko2 = s * 32;
            uint32_t ah[2][4], al[2][4];
#pragma unroll
            for (int mt = 0; mt < 2; mt++) {
                uint32_t ad = abase + (uint32_t)(r0 + mt * 16 + (lane & 15)) * 528 +
                              ko2 + ((lane >> 4) << 4);
                ldsm4(ah[mt], ad);
                ldsm4(al[mt], ad + E_ACT_LO);
            }
#pragma unroll
            for (int q = 0; q < 4; q++) {
                int n = c0 + q * 16 + (lane & 7) + ((lane & 16) >> 1);
                uint32_t bd = bbase + (uint32_t)n * 80 + ko2 + ((lane & 8) << 1);
                uint32_t bb[4];
                ldsm4(bb, bd);
#pragma unroll
                for (int mt = 0; mt < 2; mt++) {
                    mma16816h(acc[mt][2 * q + 0], ah[mt], bb[0], bb[1]);
                    mma16816h(acc[mt][2 * q + 1], ah[mt], bb[2], bb[3]);
                    mma16816h(acc[mt][2 * q + 0], al[mt], bb[0], bb[1]);
                    mma16816h(acc[mt][2 * q + 1], al[mt], bb[2], bb[3]);
                }
            }
        }
    };
    auto epilogue_act = [&](int bidx) {
#pragma unroll
        for (int mt = 0; mt < 2; mt++) {
#pragma unroll
            for (int nt = 0; nt < 8; nt++) {
                int ra = r0 + mt * 16 + (lane >> 2);
                int ca = c0 + nt * 8 + 2 * (lane & 3);
                float bv0 = s_bias[bidx * 256 + ca], bv1 = s_bias[bidx * 256 + ca + 1];
#pragma unroll
                for (int half = 0; half < 2; half++) {
                    int r = ra + half * 8;
                    float v0 = lrelu_f(acc[mt][nt][half * 2 + 0] + bv0);
                    float v1 = lrelu_f(acc[mt][nt][half * 2 + 1] + bv1);
                    __half h0 = __float2half(v0);
                    __half h1 = __float2half(v1);
                    __half2 hp; hp.x = h0; hp.y = h1;
                    __half2 lp;
                    lp.x = __float2half(v0 - __half2float(h0));
                    lp.y = __float2half(v1 - __half2float(h1));
                    uint32_t off = (uint32_t)r * 528 + (uint32_t)ca * 2;
                    *(__half2*)(dsm + ACT_HI + off) = hp;
                    *(__half2*)(dsm + E_ACT_LO + off) = lp;
                    acc[mt][nt][half * 2 + 0] = 0.0f;
                    acc[mt][nt][half * 2 + 1] = 0.0f;
                }
            }
        }
    };

    loadACT();
    prefetchB(0, 0);
    CP_COMMIT();
    prefetchB(1, 1);
    CP_COMMIT();

    for (int g = 0; g < 24; g++) {
        if (g < 23) { CP_WAIT1(); } else { CP_WAIT0(); }
        if (g == 0 || g == 8 || g == 16) __syncthreads();
        else groupbar();
        compute(sb + ACT_HI + (uint32_t)(g & 7) * 64, sb + E_BBUF + (g & 1) * 20480);
        if (g + 2 < 24) {
            groupbar();
            prefetchB(g + 2, g & 1);
            CP_COMMIT();
        }
        if (g == 7 || g == 15) {
            __syncthreads();
            epilogue_act(g >> 3);
        } else if (g == 23) {
            __syncthreads();
#pragma unroll
            for (int mt = 0; mt < 2; mt++) {
#pragma unroll
                for (int nt = 0; nt < 8; nt++) {
                    int ra = r0 + mt * 16 + (lane >> 2);
                    int ca = c0 + nt * 8 + 2 * (lane & 3);
                    float bv0 = s_bias[512 + ca], bv1 = s_bias[512 + ca + 1];
#pragma unroll
                    for (int half = 0; half < 2; half++) {
                        int r = ra + half * 8;
                        float2 v;
                        v.x = acc[mt][nt][half * 2 + 0] + bv0;
                        v.y = acc[mt][nt][half * 2 + 1] + bv1;
                        *(float2*)(dsm + (uint32_t)r * 1024 + (uint32_t)ca * 4) = v;
                    }
                }
            }
            FENCE_ASYNC();
            __syncthreads();
            if (tid < 64 && (e0 + tid) < E) {
                bulk_reduce_add_f32(agg + (size_t)s_dst[tid] * 256,
                                    sb + (uint32_t)tid * 1024, 1024);
            }
            BULK_COMMIT();
            BULK_WAIT0();
        }
    }
}

// ---------------------------------------------------------------------------
// Unified node fp16 HMMA GEMM: C[rows,256] = act(A@W + bias) + res.
// CTA = 64 rows, 8 warps, 2 CTAs/SM (same engine as edge kernel, K=256).
// blockIdx.y selects (tb1, C1). Optional fp32 C, fp16 hi/lo C out, zbuf zeroing.
// ---------------------------------------------------------------------------
__global__ __launch_bounds__(256, 2) void node_hmma(
    const __half* __restrict__ Ah, const __half* __restrict__ Al,
    const __half* __restrict__ wte, int tb0, int tb1,
    const float* __restrict__ bias, const float* __restrict__ res,
    float* __restrict__ C0, float* __restrict__ C1,
    __half* __restrict__ Ch, __half* __restrict__ Cl,
    float* __restrict__ zbuf, int rows, int act) {
    extern __shared__ __align__(16) char dsm[];
    const int tid = threadIdx.x;
    const int wid = tid >> 5, lane = tid & 31;
    const int wm = wid >> 2, wn = wid & 3;
    const int r0 = wm * 32;
    const int c0 = wn * 64;
    const int gtid = lane + wm * 32;
    const int e0 = blockIdx.x * 64;
    const uint32_t sb = smem_u32(dsm);
    const int tb = blockIdx.y ? tb1 : tb0;
    float* C = blockIdx.y ? C1 : C0;
    if (e0 >= rows) return;

    float acc[2][8][4];
#pragma unroll
    for (int mt = 0; mt < 2; mt++)
#pragma unroll
        for (int nt = 0; nt < 8; nt++)
#pragma unroll
            for (int i = 0; i < 4; i++) acc[mt][nt][i] = 0.0f;

    auto groupbar = [&]() {
        asm volatile("bar.sync %0, 64;" :: "r"(1 + wn) : "memory");
    };
    auto prefetchB = [&](int t, int buf) {
        const char* wsrc = (const char*)wte + (size_t)(tb + t) * 16384;
        uint32_t dbase = sb + E_BBUF + buf * 20480;
#pragma unroll
        for (int it = 0; it < 4; it++) {
            int id = gtid + it * 64;
            int nl = id >> 2, seg = id & 3;
            int n = c0 + nl;
            cp_async16(dbase + (uint32_t)n * 80 + seg * 16,
                       wsrc + (size_t)n * 64 + seg * 16);
        }
    };
    auto loadACT = [&]() {
#pragma unroll
        for (int it = 0; it < 16; it++) {
            int id = tid + it * 256;
            int seg = id & 31;
            int hl = (id >> 5) & 1;
            int row = id >> 6;
            int e = e0 + row;
            if (e >= rows) e = rows - 1;
            const char* sp = (const char*)(hl ? Al : Ah) + (size_t)e * 512 + seg * 16;
            cp_async16(sb + (hl ? E_ACT_LO : ACT_HI) + (uint32_t)row * 528 + seg * 16, sp);
        }
    };
    auto compute = [&](uint32_t abase, uint32_t bbase) {
#pragma unroll
        for (int s = 0; s < 2; s++) {
            int ko2 = s * 32;
            uint32_t ah[2][4], al[2][4];
#pragma unroll
            for (int mt = 0; mt < 2; mt++) {
                uint32_t ad = abase + (uint32_t)(r0 + mt * 16 + (lane & 15)) * 528 +
                              ko2 + ((lane >> 4) << 4);
                ldsm4(ah[mt], ad);
                ldsm4(al[mt], ad + E_ACT_LO);
            }
#pragma unroll
            for (int q = 0; q < 4; q++) {
                int n = c0 + q * 16 + (lane & 7) + ((lane & 16) >> 1);
                uint32_t bd = bbase + (uint32_t)n * 80 + ko2 + ((lane & 8) << 1);
                uint32_t bb[4];
                ldsm4(bb, bd);
#pragma unroll
                for (int mt = 0; mt < 2; mt++) {
                    mma16816h(acc[mt][2 * q + 0], ah[mt], bb[0], bb[1]);
                    mma16816h(acc[mt][2 * q + 1], ah[mt], bb[2], bb[3]);
                    mma16816h(acc[mt][2 * q + 0], al[mt], bb[0], bb[1]);
                    mma16816h(acc[mt][2 * q + 1], al[mt], bb[2], bb[3]);
                }
            }
        }
    };

    loadACT();
    prefetchB(0, 0);
    CP_COMMIT();
    prefetchB(1, 1);
    CP_COMMIT();

    if (zbuf && blockIdx.y == 0) {
#pragma unroll
        for (int it = 0; it < 16; it++) {
            int id = tid + it * 256;        // 0..4095 float4 slots
            int row = id >> 6;
            int e = e0 + row;
            if (e < rows) {
                float4 z = {0.0f, 0.0f, 0.0f, 0.0f};
                *(float4*)(zbuf + (size_t)e * 256 + (id & 63) * 4) = z;
            }
        }
    }

    for (int g = 0; g < 8; g++) {
        if (g < 7) { CP_WAIT1(); } else { CP_WAIT0(); }
        if (g == 0) __syncthreads();
        else groupbar();
        compute(sb + ACT_HI + (uint32_t)g * 64, sb + E_BBUF + (g & 1) * 20480);
        if (g + 2 < 8) {
            groupbar();
            prefetchB(g + 2, g & 1);
            CP_COMMIT();
        }
    }

#pragma unroll
    for (int mt = 0; mt < 2; mt++) {
#pragma unroll
        for (int nt = 0; nt < 8; nt++) {
            int ra = r0 + mt * 16 + (lane >> 2);
            int ca = c0 + nt * 8 + 2 * (lane & 3);
            float bv0 = bias ? __ldg(bias + ca) : 0.0f;
            float bv1 = bias ? __ldg(bias + ca + 1) : 0.0f;
#pragma unroll
            for (int half = 0; half < 2; half++) {
                int r = e0 + ra + half * 8;
                if (r < rows) {
                    float v0 = acc[mt][nt][half * 2 + 0] + bv0;
                    float v1 = acc[mt][nt][half * 2 + 1] + bv1;
                    if (act == 1) { v0 = gelu_f(v0); v1 = gelu_f(v1); }
                    if (res) {
                        float2 rv = *(const float2*)(res + (size_t)r * 256 + ca);
                        v0 += rv.x; v1 += rv.y;
                    }
                    if (C) {
                        float2 o; o.x = v0; o.y = v1;
                        *(float2*)(C + (size_t)r * 256 + ca) = o;
                    }
                    if (Ch) {
                        __half h0 = __float2half(v0);
                        __half h1 = __float2half(v1);
                        __half2 hp; hp.x = h0; hp.y = h1;
                        __half2 lp;
                        lp.x = __float2half(v0 - __half2float(h0));
                        lp.y = __float2half(v1 - __half2float(h1));
                        *(__half2*)(Ch + (size_t)r * 256 + ca) = hp;
                        *(__half2*)(Cl + (size_t)r * 256 + ca) = lp;
                    }
                }
            }
        }
    }
}

// ---------------------------------------------------------------------------
extern "C" void kernel_launch(void* const* d_in, const int* in_sizes, int n_in,
                              void* d_out, int out_size) {
    const int* atom_types = (const int*)d_in[0];
    const float* x_extra = (const float*)d_in[1];
    const int* edge_index = (const int*)d_in[2];
    const float* dists = (const float*)d_in[3];
    const float* freq = (const float*)d_in[4];
    const float* emb_table = (const float*)d_in[5];
    const float* w_emb = (const float*)d_in[6];
    const float* b_emb = (const float*)d_in[7];
    const float* w_n2m = (const float*)d_in[8];
    const float* b_n2m = (const float*)d_in[9];
    const float* w_r2m = (const float*)d_in[10];
    const float* b_r2m = (const float*)d_in[11];
    const float* w_m2n = (const float*)d_in[12];
    const float* mw1 = (const float*)d_in[13];
    const float* mb1 = (const float*)d_in[14];
    const float* mw2 = (const float*)d_in[15];
    const float* mb2 = (const float*)d_in[16];
    const float* mw3 = (const float*)d_in[17];
    const float* mb3 = (const float*)d_in[18];
    const float* mw4 = (const float*)d_in[19];
    const float* mb4 = (const float*)d_in[20];
    const float* fw1 = (const float*)d_in[21];
    const float* fb1 = (const float*)d_in[22];
    const float* fw2 = (const float*)d_in[23];
    const float* fb2 = (const float*)d_in[24];
    float* out = (float*)d_out;

    int N = in_sizes[0];
    int E = in_sizes[2] / 2;

    float *p_h, *p_p, *p_q, *p_agg, *p_t, *p_wr2, *p_cz;
    __half *p_hh, *p_hl, *p_aggh, *p_aggl, *p_th, *p_tl, *p_uh, *p_ul;
    __half *p_a1h, *p_a1l, *p_wte;
    cudaGetSymbolAddress((void**)&p_h, g_h);
    cudaGetSymbolAddress((void**)&p_p, g_p);
    cudaGetSymbolAddress((void**)&p_q, g_q);
    cudaGetSymbolAddress((void**)&p_agg, g_agg);
    cudaGetSymbolAddress((void**)&p_t, g_t);
    cudaGetSymbolAddress((void**)&p_wr2, g_wr2);
    cudaGetSymbolAddress((void**)&p_cz, g_cz);
    cudaGetSymbolAddress((void**)&p_hh, g_hh);
    cudaGetSymbolAddress((void**)&p_hl, g_hl);
    cudaGetSymbolAddress((void**)&p_aggh, g_aggh);
    cudaGetSymbolAddress((void**)&p_aggl, g_aggl);
    cudaGetSymbolAddress((void**)&p_th, g_th);
    cudaGetSymbolAddress((void**)&p_tl, g_tl);
    cudaGetSymbolAddress((void**)&p_uh, g_uh);
    cudaGetSymbolAddress((void**)&p_ul, g_ul);
    cudaGetSymbolAddress((void**)&p_a1h, g_a1h);
    cudaGetSymbolAddress((void**)&p_a1l, g_a1l);
    cudaGetSymbolAddress((void**)&p_wte, g_wte);

    cudaFuncSetAttribute(edge_mlp_hmma, cudaFuncAttributeMaxDynamicSharedMemorySize, DSMEM_E);
    cudaFuncSetAttribute(node_hmma, cudaFuncAttributeMaxDynamicSharedMemorySize, DSMEM_E);

    dim3 gMega((N + 63) / 64, 2, 5);
    int gE64 = (E + 63) / 64;
    int gNode = (N + 63) / 64;
    dim3 gPQ(gNode, 2);
    dim3 gN1(gNode, 1);

    k0_mega<<<gMega, 256>>>(atom_types, x_extra, emb_table, w_emb, b_emb,
                            w_n2m, b_n2m, w_r2m, b_r2m, mw1, mb1, mw2, mw3, mw4,
                            w_m2n, fw1, fw2, p_h, p_hh, p_hl, p_wr2, p_cz,
                            p_wte, N);
    node_hmma<<<gPQ, 256, DSMEM_E>>>(p_hh, p_hl, p_wte, 48, 56, nullptr, nullptr,
                                     p_p, p_q, nullptr, nullptr, p_agg, N, 0);
    edge_combine<<<gE64, 256>>>(dists, freq, p_wr2, p_p, p_q, p_cz, edge_index,
                                p_a1h, p_a1l, E);
    edge_mlp_hmma<<<gE64, 256, DSMEM_E>>>(p_a1h, p_a1l, edge_index, p_wte,
                                          mb2, mb3, mb4, p_agg, E);
    conv_hilo<<<(N * 256 + 255) / 256, 256>>>(p_agg, p_aggh, p_aggl, N * 256);
    node_hmma<<<gN1, 256, DSMEM_E>>>(p_aggh, p_aggl, p_wte, 24, 24, nullptr, p_h,
                                     p_t, nullptr, p_th, p_tl, nullptr, N, 0);
    node_hmma<<<gN1, 256, DSMEM_E>>>(p_th, p_tl, p_wte, 32, 32, fb1, nullptr,
                                     nullptr, nullptr, p_uh, p_ul, nullptr, N, 1);
    node_hmma<<<gN1, 256, DSMEM_E>>>(p_uh, p_ul, p_wte, 40, 40, fb2, p_t,
                                     out, nullptr, nullptr, nullptr, nullptr, N, 0);
}